// round 2
// baseline (speedup 1.0000x reference)
#include <cuda_runtime.h>

namespace {
constexpr int B_  = 4;
constexpr int C_  = 64;
constexpr int IC_ = 16;
constexpr int D_  = 8;
constexpr int H_  = 128;
constexpr int W_  = 128;
constexpr int MID_ = 4;
constexpr int HP_ = 64;   // (128+2-3)/2+1
constexpr int L_  = 4096; // HP*WP
constexpr int F_  = 144;  // IC*3*3
constexpr float SCALE_ = 10.0f;

// flash kernel shared memory layout (floats)
constexpr int QST_STRIDE = 132;  // [f][128 rows + pad]
constexpr int KST_STRIDE = 68;   // [f][64 cols + pad]
constexpr int VS_STRIDE  = 148;  // [col][144 f + pad]
constexpr int PS_STRIDE  = 68;   // [row][64 cols + pad]  (row-major P)
constexpr int QST_OFF = 0;                           // 144*132 = 19008
constexpr int KST_OFF = QST_OFF + 144 * QST_STRIDE;  // +9792
constexpr int VS_OFF  = KST_OFF + 144 * KST_STRIDE;  // +9472
constexpr int PS_OFF  = VS_OFF  + 64  * VS_STRIDE;   // +8704
constexpr int SMEM_FLOATS = PS_OFF + 128 * PS_STRIDE;
constexpr int SMEM_BYTES  = SMEM_FLOATS * 4;         // ~187 KB
}

typedef unsigned long long ull;

// ---- packed f32x2 helpers (sm_103a FFMA2 path) ----
__device__ __forceinline__ ull dup2(float a) {
    ull r; asm("mov.b64 %0, {%1, %1};" : "=l"(r) : "f"(a)); return r;
}
__device__ __forceinline__ void fma2(ull& d, ull a, ull b) {
    asm("fma.rn.f32x2 %0, %1, %2, %0;" : "+l"(d) : "l"(a), "l"(b));
}
__device__ __forceinline__ void mul2(ull& d, ull a) {
    asm("mul.rn.f32x2 %0, %0, %1;" : "+l"(d) : "l"(a));
}
__device__ __forceinline__ float2 unpack2(ull v) {
    float2 f; asm("mov.b64 {%0, %1}, %2;" : "=f"(f.x), "=f"(f.y) : "l"(v)); return f;
}

// ---- scratch (device globals; no runtime allocation allowed) ----
__device__ float d_conv[3][B_][IC_][H_][W_];   // 0:q-map, 1:v-map, 2:k-map
__device__ float d_qkv[3][B_][L_][F_];         // 0:q 1:v 2:k
__device__ float d_zi[B_][L_][F_];             // attention output rows
__device__ float d_yvec[B_][C_][H_][W_];       // W_w @ z + bias

// ============================================================
// Kernel 1: 1x1 convs at the mid depth slice only.
// ============================================================
__global__ void k_conv(const float* __restrict__ s, const float* __restrict__ g,
                       const float* __restrict__ gw, const float* __restrict__ gb,
                       const float* __restrict__ tw, const float* __restrict__ tb,
                       const float* __restrict__ pw, const float* __restrict__ pb) {
    __shared__ float wq[IC_ * C_], wv[IC_ * C_], wk[IC_ * C_];
    __shared__ float bq[IC_], bv[IC_], bk[IC_];
    const int tid = threadIdx.x;
    for (int i = tid; i < IC_ * C_; i += 128) { wq[i] = gw[i]; wv[i] = tw[i]; wk[i] = pw[i]; }
    if (tid < IC_) { bq[tid] = gb[tid]; bv[tid] = tb[tid]; bk[tid] = pb[tid]; }
    __syncthreads();

    const int y = blockIdx.x, b = blockIdx.y, x = tid;
    float aq[IC_], av[IC_], ak[IC_];
#pragma unroll
    for (int ic = 0; ic < IC_; ic++) { aq[ic] = bq[ic]; av[ic] = bv[ic]; ak[ic] = bk[ic]; }

    const size_t base = ((size_t)b * C_ * D_ + MID_) * (H_ * W_) + (size_t)y * W_ + x;
    const size_t cstride = (size_t)D_ * H_ * W_;
#pragma unroll 4
    for (int c = 0; c < C_; c++) {
        const float sv = s[base + c * cstride];
        const float gv = g[base + c * cstride];
#pragma unroll
        for (int ic = 0; ic < IC_; ic++) {
            aq[ic] += wq[ic * C_ + c] * sv;
            av[ic] += wv[ic * C_ + c] * gv;
            ak[ic] += wk[ic * C_ + c] * gv;
        }
    }
#pragma unroll
    for (int ic = 0; ic < IC_; ic++) {
        const int o = ((b * IC_ + ic) * H_ + y) * W_ + x;
        (&d_conv[0][0][0][0][0])[o] = aq[ic];
        (&d_conv[1][0][0][0][0])[o] = av[ic];
        (&d_conv[2][0][0][0][0])[o] = ak[ic];
    }
}

// ============================================================
// Kernel 2: patch extraction -> q/v/k matrices [b][l][144]
// ============================================================
__global__ void k_patch() {
    const int idx = blockIdx.x * 256 + threadIdx.x;
    if (idx >= B_ * L_ * F_) return;
    const int f = idx % F_;
    const int t = idx / F_;
    const int l = t & (L_ - 1);
    const int b = t >> 12;
    const int c  = f / 9;
    const int r  = f - c * 9;
    const int ki = r / 3;
    const int kj = r - ki * 3;
    const int hp = l >> 6, wp = l & 63;
    const int y = hp * 2 - 1 + ki;
    const int x = wp * 2 - 1 + kj;
    const bool in = ((unsigned)y < (unsigned)H_) && ((unsigned)x < (unsigned)W_);
#pragma unroll
    for (int m = 0; m < 3; m++) {
        float val = in ? d_conv[m][b][c][y][x] : 0.0f;
        d_qkv[m][b][l][f] = val;
    }
}

// ============================================================
// Kernel 3: flash attention, fp32 with packed FFMA2 (f32x2).
// grid (L/128, B), 256 threads: tx = tid&7 (8 col-groups of 8),
// ty = tid>>3 (32 row-groups of 4). Per thread: 4x8 S micro-tile
// (packed along j as 4x4 f32x2), O accum 4 rows x 18 f (packed as 4x9).
// ============================================================
__global__ __launch_bounds__(256, 1) void k_flash() {
    extern __shared__ float sm[];
    float* Qst = sm + QST_OFF;   // [f][row]   (pre-scaled by SCALE)
    float* Kst = sm + KST_OFF;   // [f][col]
    float* Vs  = sm + VS_OFF;    // [col][f]
    float* Ps  = sm + PS_OFF;    // [row][col]

    const int tid = threadIdx.x;
    const int tx = tid & 7;      // 0..7  (cols tx*8..tx*8+7; f-chunk tx*18..)
    const int ty = tid >> 3;     // 0..31 (rows ty*4..ty*4+3)
    const int b = blockIdx.y;
    const int row0 = blockIdx.x * 128;

    const float* __restrict__ qg = &d_qkv[0][b][0][0];
    const float* __restrict__ vg = &d_qkv[1][b][0][0];
    const float* __restrict__ kg = &d_qkv[2][b][0][0];

    // fill Q tile transposed, pre-scaled
#pragma unroll
    for (int it = 0; it < (128 * F_) / 256; it++) {
        const int e = tid + it * 256;
        const int r = e / F_, f = e - r * F_;
        Qst[f * QST_STRIDE + r] = qg[(row0 + r) * F_ + f] * SCALE_;
    }

    float m_i[4], l_i[4];
    ull O2[4][9];
#pragma unroll
    for (int i = 0; i < 4; i++) {
        m_i[i] = -1e30f; l_i[i] = 0.f;
#pragma unroll
        for (int u = 0; u < 9; u++) O2[i][u] = 0ull;
    }

    const float* qp = Qst + ty * 4;
    const float* kp = Kst + tx * 8;
    const float* vp = Vs + tx * 18;

    for (int ct = 0; ct < 64; ct++) {
        const int col0 = ct * 64;
#pragma unroll
        for (int it = 0; it < (64 * F_) / 256; it++) {
            const int e = tid + it * 256;
            const int c = e / F_, f = e - c * F_;
            Kst[f * KST_STRIDE + c] = kg[(col0 + c) * F_ + f];
            Vs[c * VS_STRIDE + f]   = vg[(col0 + c) * F_ + f];
        }
        __syncthreads();

        // ---- S = Q K^T (128x64 tile), packed along j ----
        ull acc2[4][4];
#pragma unroll
        for (int i = 0; i < 4; i++)
#pragma unroll
            for (int jp = 0; jp < 4; jp++) acc2[i][jp] = 0ull;

#pragma unroll 4
        for (int f = 0; f < F_; f++) {
            const float4 qv = *reinterpret_cast<const float4*>(qp + f * QST_STRIDE);
            const ulonglong2 ka = *reinterpret_cast<const ulonglong2*>(kp + f * KST_STRIDE);
            const ulonglong2 kb = *reinterpret_cast<const ulonglong2*>(kp + f * KST_STRIDE + 4);
            const ull q0 = dup2(qv.x), q1 = dup2(qv.y), q2 = dup2(qv.z), q3 = dup2(qv.w);
            fma2(acc2[0][0], q0, ka.x); fma2(acc2[0][1], q0, ka.y);
            fma2(acc2[0][2], q0, kb.x); fma2(acc2[0][3], q0, kb.y);
            fma2(acc2[1][0], q1, ka.x); fma2(acc2[1][1], q1, ka.y);
            fma2(acc2[1][2], q1, kb.x); fma2(acc2[1][3], q1, kb.y);
            fma2(acc2[2][0], q2, ka.x); fma2(acc2[2][1], q2, ka.y);
            fma2(acc2[2][2], q2, kb.x); fma2(acc2[2][3], q2, kb.y);
            fma2(acc2[3][0], q3, ka.x); fma2(acc2[3][1], q3, ka.y);
            fma2(acc2[3][2], q3, kb.x); fma2(acc2[3][3], q3, kb.y);
        }

        // unpack to scalars for softmax
        float sc[4][8];
#pragma unroll
        for (int i = 0; i < 4; i++)
#pragma unroll
            for (int jp = 0; jp < 4; jp++) {
                const float2 t = unpack2(acc2[i][jp]);
                sc[i][2 * jp] = t.x; sc[i][2 * jp + 1] = t.y;
            }

        // ---- online softmax (row groups = 8 lanes sharing ty) ----
        float mloc[4], rs[4], alpha[4];
#pragma unroll
        for (int i = 0; i < 4; i++) {
            float m = sc[i][0];
#pragma unroll
            for (int j = 1; j < 8; j++) m = fmaxf(m, sc[i][j]);
            mloc[i] = m;
        }
#pragma unroll
        for (int off = 4; off >= 1; off >>= 1)
#pragma unroll
            for (int i = 0; i < 4; i++)
                mloc[i] = fmaxf(mloc[i], __shfl_xor_sync(0xffffffffu, mloc[i], off, 8));

#pragma unroll
        for (int i = 0; i < 4; i++) {
            const float mn = fmaxf(m_i[i], mloc[i]);
            alpha[i] = __expf(m_i[i] - mn);
            m_i[i] = mn;
            float r = 0.f;
#pragma unroll
            for (int j = 0; j < 8; j++) { sc[i][j] = __expf(sc[i][j] - mn); r += sc[i][j]; }
            rs[i] = r;
        }
#pragma unroll
        for (int off = 4; off >= 1; off >>= 1)
#pragma unroll
            for (int i = 0; i < 4; i++)
                rs[i] += __shfl_xor_sync(0xffffffffu, rs[i], off, 8);
#pragma unroll
        for (int i = 0; i < 4; i++) l_i[i] = l_i[i] * alpha[i] + rs[i];

        // store P row-major; rescale O
#pragma unroll
        for (int i = 0; i < 4; i++) {
            float* pr = Ps + (ty * 4 + i) * PS_STRIDE + tx * 8;
            *reinterpret_cast<float4*>(pr)     = make_float4(sc[i][0], sc[i][1], sc[i][2], sc[i][3]);
            *reinterpret_cast<float4*>(pr + 4) = make_float4(sc[i][4], sc[i][5], sc[i][6], sc[i][7]);
        }
#pragma unroll
        for (int i = 0; i < 4; i++) {
            const ull al = dup2(alpha[i]);
#pragma unroll
            for (int u = 0; u < 9; u++) mul2(O2[i][u], al);
        }
        __syncthreads();

        // ---- O += P V, packed along f ----
#pragma unroll 2
        for (int c = 0; c < 64; c++) {
            const float* prow = Ps + ty * 4 * PS_STRIDE + c;
            const ull p0 = dup2(prow[0]);
            const ull p1 = dup2(prow[PS_STRIDE]);
            const ull p2 = dup2(prow[2 * PS_STRIDE]);
            const ull p3 = dup2(prow[3 * PS_STRIDE]);
            const float* vr = vp + c * VS_STRIDE;
#pragma unroll
            for (int u = 0; u < 9; u++) {
                const ull vv = *reinterpret_cast<const ull*>(vr + 2 * u);
                fma2(O2[0][u], p0, vv);
                fma2(O2[1][u], p1, vv);
                fma2(O2[2][u], p2, vv);
                fma2(O2[3][u], p3, vv);
            }
        }
        __syncthreads();
    }

    // normalize + write zi
#pragma unroll
    for (int i = 0; i < 4; i++) {
        const float inv = 1.0f / l_i[i];
        const int row = row0 + ty * 4 + i;
        float* zr = &d_zi[b][row][tx * 18];
#pragma unroll
        for (int u = 0; u < 9; u++) {
            const float2 t = unpack2(O2[i][u]);
            *reinterpret_cast<float2*>(zr + 2 * u) = make_float2(t.x * inv, t.y * inv);
        }
    }
}

// ============================================================
// Kernel 4: fold (overlap-add + count normalize) + W_w conv -> yvec
// ============================================================
__global__ void k_fold(const float* __restrict__ Wmat, const float* __restrict__ Wb) {
    __shared__ float zs[IC_][W_];
    __shared__ float wsm[C_ * IC_];
    __shared__ float bsm[C_];
    const int x = threadIdx.x;
    const int y = blockIdx.x, b = blockIdx.y;
    for (int i = x; i < C_ * IC_; i += 128) wsm[i] = Wmat[i];
    if (x < C_) bsm[x] = Wb[x];

    float v[IC_];
#pragma unroll
    for (int ic = 0; ic < IC_; ic++) v[ic] = 0.f;
    int cnt = 0;
#pragma unroll
    for (int i = 0; i < 3; i++) {
        const int tY = y + 1 - i;
        if (tY < 0 || (tY & 1) || (tY >> 1) >= HP_) continue;
        const int hp = tY >> 1;
#pragma unroll
        for (int j = 0; j < 3; j++) {
            const int tX = x + 1 - j;
            if (tX < 0 || (tX & 1) || (tX >> 1) >= HP_) continue;
            const int wp = tX >> 1;
            const float* zrow = &d_zi[b][hp * 64 + wp][0];
            cnt++;
#pragma unroll
            for (int ic = 0; ic < IC_; ic++) v[ic] += zrow[ic * 9 + i * 3 + j];
        }
    }
    const float invc = 1.0f / (float)cnt;
#pragma unroll
    for (int ic = 0; ic < IC_; ic++) zs[ic][x] = v[ic] * invc;
    __syncthreads();

    for (int o = 0; o < C_; o++) {
        float a = bsm[o];
#pragma unroll
        for (int ic = 0; ic < IC_; ic++) a += wsm[o * IC_ + ic] * zs[ic][x];
        d_yvec[b][o][y][x] = a;
    }
}

// ============================================================
// Kernel 5: out = s + yvec (broadcast over D)
// ============================================================
__global__ void k_out(const float* __restrict__ s, float* __restrict__ out) {
    const int idx = blockIdx.x * 256 + threadIdx.x;
    const int pix = idx & (H_ * W_ - 1);
    const int bo = (idx >> 14) >> 3;  // b*64 + o
    out[idx] = s[idx] + (&d_yvec[0][0][0][0])[bo * (H_ * W_) + pix];
}

// ============================================================
extern "C" void kernel_launch(void* const* d_in, const int* /*in_sizes*/, int /*n_in*/,
                              void* d_out, int /*out_size*/) {
    const float* s   = (const float*)d_in[0];
    const float* g   = (const float*)d_in[1];
    const float* g_w = (const float*)d_in[2];
    const float* g_b = (const float*)d_in[3];
    const float* t_w = (const float*)d_in[4];
    const float* t_b = (const float*)d_in[5];
    const float* p_w = (const float*)d_in[6];
    const float* p_b = (const float*)d_in[7];
    const float* W_w = (const float*)d_in[8];
    const float* W_b = (const float*)d_in[9];
    float* out = (float*)d_out;

    k_conv<<<dim3(H_, B_), 128>>>(s, g, g_w, g_b, t_w, t_b, p_w, p_b);
    k_patch<<<(B_ * L_ * F_) / 256, 256>>>();

    cudaFuncSetAttribute(k_flash, cudaFuncAttributeMaxDynamicSharedMemorySize, SMEM_BYTES);
    k_flash<<<dim3(L_ / 128, B_), 256, SMEM_BYTES>>>();

    k_fold<<<dim3(H_, B_), 128>>>(W_w, W_b);

    const int total = B_ * C_ * D_ * H_ * W_;
    k_out<<<total / 256, 256>>>(s, out);
}

// round 4
// speedup vs baseline: 1.6803x; 1.6803x over previous
#include <cuda_runtime.h>
#include <cuda_fp16.h>
#include <cstdint>

namespace {
constexpr int B_  = 4;
constexpr int C_  = 64;
constexpr int IC_ = 16;
constexpr int D_  = 8;
constexpr int H_  = 128;
constexpr int W_  = 128;
constexpr int MID_ = 4;
constexpr int HP_ = 64;
constexpr int L_  = 4096;
constexpr int F_  = 144;   // IC*3*3, = 9 * 16 exactly
constexpr float SCALE_ = 10.0f;

// S-GEMM smem strides (in halfs)
constexpr int SQ_STR = 152;               // 144 + 8 pad
constexpr int SQH_OFF = 0;
constexpr int SQL_OFF = 128 * SQ_STR;     // 19456
constexpr int SKH_OFF = 2 * 128 * SQ_STR; // 38912
constexpr int SKL_OFF = 3 * 128 * SQ_STR; // 58368
constexpr int SGEMM_SMEM_BYTES = 4 * 128 * SQ_STR * 2;  // 155648

// PV-GEMM smem strides (in halfs)
constexpr int PV_STR = 72;                // 64 + 8 pad
constexpr int SP_OFF  = 0;                // P chunk [128][72]
constexpr int SVH_OFF = 128 * PV_STR;     // 9216
constexpr int SVL_OFF = SVH_OFF + 144 * PV_STR;  // 19584
constexpr int PV_SMEM_BYTES = (SVL_OFF + 144 * PV_STR) * 2;  // 59904
}

// ============================================================
// mma.sync m16n8k16 f16 -> f32 (base PTX, valid on compute_103)
// ============================================================
__device__ __forceinline__ void mma16816(float* c, const uint32_t* a,
                                         uint32_t b0, uint32_t b1) {
    asm volatile(
        "mma.sync.aligned.m16n8k16.row.col.f32.f16.f16.f32 "
        "{%0,%1,%2,%3}, {%4,%5,%6,%7}, {%8,%9}, {%0,%1,%2,%3};"
        : "+f"(c[0]), "+f"(c[1]), "+f"(c[2]), "+f"(c[3])
        : "r"(a[0]), "r"(a[1]), "r"(a[2]), "r"(a[3]), "r"(b0), "r"(b1));
}

__device__ __forceinline__ void split16(float x, __half& h, __half& l) {
    h = __float2half_rn(x);
    l = __float2half_rn(x - __half2float(h));
}

// ============================================================
// scratch (device globals)
// ============================================================
__device__ float d_conv[3][B_][IC_][H_][W_];   // 0:q-map 1:v-map 2:k-map
__device__ __align__(16) __half d_qh[B_][L_][F_];
__device__ __align__(16) __half d_ql[B_][L_][F_];
__device__ __align__(16) __half d_kh[B_][L_][F_];
__device__ __align__(16) __half d_kl[B_][L_][F_];
__device__ __align__(16) __half d_vth[B_][F_][L_];
__device__ __align__(16) __half d_vtl[B_][F_][L_];
__device__ float d_S[B_][L_][L_];              // 256 MiB logits
__device__ __half d_Pv[B_][L_][L_];            // 128 MiB unnormalized exp
__device__ float d_linv[B_][L_];
__device__ float d_zi[B_][L_][F_];
__device__ float d_yvec[B_][C_][H_][W_];

// ============================================================
// Kernel 1: 1x1 convs at the mid depth slice only.
// ============================================================
__global__ void k_conv(const float* __restrict__ s, const float* __restrict__ g,
                       const float* __restrict__ gw, const float* __restrict__ gb,
                       const float* __restrict__ tw, const float* __restrict__ tb,
                       const float* __restrict__ pw, const float* __restrict__ pb) {
    __shared__ float wq[IC_ * C_], wv[IC_ * C_], wk[IC_ * C_];
    __shared__ float bq[IC_], bv[IC_], bk[IC_];
    const int tid = threadIdx.x;
    for (int i = tid; i < IC_ * C_; i += 128) { wq[i] = gw[i]; wv[i] = tw[i]; wk[i] = pw[i]; }
    if (tid < IC_) { bq[tid] = gb[tid]; bv[tid] = tb[tid]; bk[tid] = pb[tid]; }
    __syncthreads();

    const int y = blockIdx.x, b = blockIdx.y, x = tid;
    float aq[IC_], av[IC_], ak[IC_];
#pragma unroll
    for (int ic = 0; ic < IC_; ic++) { aq[ic] = bq[ic]; av[ic] = bv[ic]; ak[ic] = bk[ic]; }

    const size_t base = ((size_t)b * C_ * D_ + MID_) * (H_ * W_) + (size_t)y * W_ + x;
    const size_t cstride = (size_t)D_ * H_ * W_;
#pragma unroll 4
    for (int c = 0; c < C_; c++) {
        const float sv = s[base + c * cstride];
        const float gv = g[base + c * cstride];
#pragma unroll
        for (int ic = 0; ic < IC_; ic++) {
            aq[ic] += wq[ic * C_ + c] * sv;
            av[ic] += wv[ic * C_ + c] * gv;
            ak[ic] += wk[ic * C_ + c] * gv;
        }
    }
#pragma unroll
    for (int ic = 0; ic < IC_; ic++) {
        const int o = ((b * IC_ + ic) * H_ + y) * W_ + x;
        (&d_conv[0][0][0][0][0])[o] = aq[ic];
        (&d_conv[1][0][0][0][0])[o] = av[ic];
        (&d_conv[2][0][0][0][0])[o] = ak[ic];
    }
}

// ============================================================
// Kernel 2a: patches -> q (pre-scaled by 10) and k, fp16 hi/lo split.
// ============================================================
__global__ void k_patch_qk() {
    const int idx = blockIdx.x * 256 + threadIdx.x;
    const int f = idx % F_;
    const int t = idx / F_;
    const int l = t & (L_ - 1);
    const int b = t >> 12;
    const int c = f / 9;
    const int r = f - c * 9;
    const int ki = r / 3, kj = r - (r / 3) * 3;
    const int hp = l >> 6, wp = l & 63;
    const int y = hp * 2 - 1 + ki;
    const int x = wp * 2 - 1 + kj;
    const bool in = ((unsigned)y < (unsigned)H_) && ((unsigned)x < (unsigned)W_);
    float q = in ? d_conv[0][b][c][y][x] : 0.0f;
    float k = in ? d_conv[2][b][c][y][x] : 0.0f;
    q *= SCALE_;
    __half qh, ql, kh, kl;
    split16(q, qh, ql);
    split16(k, kh, kl);
    d_qh[b][l][f] = qh; d_ql[b][l][f] = ql;
    d_kh[b][l][f] = kh; d_kl[b][l][f] = kl;
}

// ============================================================
// Kernel 2b: patches -> V transposed [b][f][l], fp16 hi/lo split.
// ============================================================
__global__ void k_patch_v() {
    const int idx = blockIdx.x * 256 + threadIdx.x;
    const int b = idx / (F_ * L_);
    const int rem = idx - b * (F_ * L_);
    const int f = rem / L_;
    const int l = rem - f * L_;
    const int c = f / 9;
    const int r = f - c * 9;
    const int ki = r / 3, kj = r - (r / 3) * 3;
    const int hp = l >> 6, wp = l & 63;
    const int y = hp * 2 - 1 + ki;
    const int x = wp * 2 - 1 + kj;
    const bool in = ((unsigned)y < (unsigned)H_) && ((unsigned)x < (unsigned)W_);
    const float v = in ? d_conv[1][b][c][y][x] : 0.0f;
    __half vh, vl;
    split16(v, vh, vl);
    d_vth[b][f][l] = vh;
    d_vtl[b][f][l] = vl;
}

// ============================================================
// Kernel 3: S = (10 Q) K^T, fp16 split (hh + hl + lh), HMMA.
// grid (32 col-tiles, 32 row-tiles, B), 256 threads = 8 warps (4 row x 2 col).
// CTA tile 128x128; warp tile 32x64; K = 144 (9 x k16).
// ============================================================
__global__ __launch_bounds__(256, 1) void k_gemmS() {
    extern __shared__ __half smh[];
    const int tid = threadIdx.x;
    const int lane = tid & 31;
    const int warp = tid >> 5;
    const int wr = warp >> 1;           // 0..3
    const int wc = warp & 1;            // 0..1
    const int g = lane >> 2;            // 0..7
    const int t = lane & 3;             // 0..3
    const int b = blockIdx.z;
    const int row0 = blockIdx.y * 128;
    const int col0 = blockIdx.x * 128;

    // load Q and K tiles hi/lo: 128 rows x 144 halfs each (18 uint4/row)
    for (int e = tid; e < 128 * 18; e += 256) {
        const int r = e / 18, u = e - (e / 18) * 18;
        const int so = r * SQ_STR + u * 8;
        *(uint4*)&smh[SQH_OFF + so] = *(const uint4*)&d_qh[b][row0 + r][u * 8];
        *(uint4*)&smh[SQL_OFF + so] = *(const uint4*)&d_ql[b][row0 + r][u * 8];
        *(uint4*)&smh[SKH_OFF + so] = *(const uint4*)&d_kh[b][col0 + r][u * 8];
        *(uint4*)&smh[SKL_OFF + so] = *(const uint4*)&d_kl[b][col0 + r][u * 8];
    }
    __syncthreads();

    float acc[2][8][4];
#pragma unroll
    for (int m = 0; m < 2; m++)
#pragma unroll
        for (int n = 0; n < 8; n++)
#pragma unroll
            for (int j = 0; j < 4; j++) acc[m][n][j] = 0.f;

#pragma unroll
    for (int sp = 0; sp < 3; sp++) {
        const __half* A  = smh + ((sp == 2) ? SQL_OFF : SQH_OFF);
        const __half* Bm = smh + ((sp == 1) ? SKL_OFF : SKH_OFF);
#pragma unroll
        for (int k16 = 0; k16 < 9; k16++) {
            const int kc = k16 * 16 + t * 2;
            uint32_t a[2][4];
#pragma unroll
            for (int m = 0; m < 2; m++) {
                const int r0 = wr * 32 + m * 16 + g;
                a[m][0] = *(const uint32_t*)&A[r0 * SQ_STR + kc];
                a[m][1] = *(const uint32_t*)&A[(r0 + 8) * SQ_STR + kc];
                a[m][2] = *(const uint32_t*)&A[r0 * SQ_STR + kc + 8];
                a[m][3] = *(const uint32_t*)&A[(r0 + 8) * SQ_STR + kc + 8];
            }
#pragma unroll
            for (int n = 0; n < 8; n++) {
                const int cn = wc * 64 + n * 8 + g;
                const uint32_t b0 = *(const uint32_t*)&Bm[cn * SQ_STR + kc];
                const uint32_t b1 = *(const uint32_t*)&Bm[cn * SQ_STR + kc + 8];
                mma16816(acc[0][n], a[0], b0, b1);
                mma16816(acc[1][n], a[1], b0, b1);
            }
        }
    }

    // store S
#pragma unroll
    for (int m = 0; m < 2; m++) {
        const int row = row0 + wr * 32 + m * 16 + g;
#pragma unroll
        for (int n = 0; n < 8; n++) {
            const int col = col0 + wc * 64 + n * 8 + t * 2;
            *(float2*)&d_S[b][row][col]     = make_float2(acc[m][n][0], acc[m][n][1]);
            *(float2*)&d_S[b][row + 8][col] = make_float2(acc[m][n][2], acc[m][n][3]);
        }
    }
}

// ============================================================
// Kernel 4: row softmax; store unnormalized exp as fp16, 1/sum.
// one block (256 thr) per row.
// ============================================================
__global__ __launch_bounds__(256) void k_softmax() {
    const int bid = blockIdx.x;
    const int b = bid >> 12, r = bid & 4095;
    const int tid = threadIdx.x;
    const int lane = tid & 31, warp = tid >> 5;
    const float4* Srow = (const float4*)&d_S[b][r][0];   // 1024 float4

    float4 v[4];
    float m = -1e30f;
#pragma unroll
    for (int j = 0; j < 4; j++) {
        v[j] = Srow[tid + j * 256];
        m = fmaxf(m, fmaxf(fmaxf(v[j].x, v[j].y), fmaxf(v[j].z, v[j].w)));
    }
    __shared__ float redm[8], reds[8];
#pragma unroll
    for (int off = 16; off >= 1; off >>= 1)
        m = fmaxf(m, __shfl_xor_sync(0xffffffffu, m, off));
    if (lane == 0) redm[warp] = m;
    __syncthreads();
    m = redm[0];
#pragma unroll
    for (int w = 1; w < 8; w++) m = fmaxf(m, redm[w]);

    float s = 0.f;
    uint2* Prow = (uint2*)&d_Pv[b][r][0];
#pragma unroll
    for (int j = 0; j < 4; j++) {
        const float ex = __expf(v[j].x - m);
        const float ey = __expf(v[j].y - m);
        const float ez = __expf(v[j].z - m);
        const float ew = __expf(v[j].w - m);
        s += (ex + ey) + (ez + ew);
        const __half2 p0 = __floats2half2_rn(ex, ey);
        const __half2 p1 = __floats2half2_rn(ez, ew);
        uint2 u;
        u.x = *(const uint32_t*)&p0;
        u.y = *(const uint32_t*)&p1;
        Prow[tid + j * 256] = u;
    }
#pragma unroll
    for (int off = 16; off >= 1; off >>= 1)
        s += __shfl_xor_sync(0xffffffffu, s, off);
    if (lane == 0) reds[warp] = s;
    __syncthreads();
    if (tid == 0) {
        float st = 0.f;
#pragma unroll
        for (int w = 0; w < 8; w++) st += reds[w];
        d_linv[b][r] = 1.0f / st;
    }
}

// ============================================================
// Kernel 5: zi = (P / l) V, fp16 HMMA, V split hi+lo.
// grid (32 row-tiles, B), 256 threads = 8 warps (4 row x 2 col).
// CTA tile 128 x 144; warp tile 32 x 72; K = 4096 in chunks of 64.
// ============================================================
__global__ __launch_bounds__(256, 1) void k_gemmPV() {
    extern __shared__ __half smh[];
    const int tid = threadIdx.x;
    const int lane = tid & 31;
    const int warp = tid >> 5;
    const int wr = warp >> 1;
    const int wc = warp & 1;
    const int g = lane >> 2;
    const int t = lane & 3;
    const int b = blockIdx.y;
    const int row0 = blockIdx.x * 128;

    float acc[2][9][4];
#pragma unroll
    for (int m = 0; m < 2; m++)
#pragma unroll
        for (int n = 0; n < 9; n++)
#pragma unroll
            for (int j = 0; j < 4; j++) acc[m][n][j] = 0.f;

    for (int ct = 0; ct < 64; ct++) {
        const int k0 = ct * 64;
        // P chunk [128 rows][64]
        for (int e = tid; e < 128 * 8; e += 256) {
            const int r = e >> 3, u = e & 7;
            *(uint4*)&smh[SP_OFF + r * PV_STR + u * 8] = *(const uint4*)&d_Pv[b][row0 + r][k0 + u * 8];
        }
        // V chunks [144 f][64] hi/lo
        for (int e = tid; e < 144 * 8; e += 256) {
            const int f = e >> 3, u = e & 7;
            *(uint4*)&smh[SVH_OFF + f * PV_STR + u * 8] = *(const uint4*)&d_vth[b][f][k0 + u * 8];
            *(uint4*)&smh[SVL_OFF + f * PV_STR + u * 8] = *(const uint4*)&d_vtl[b][f][k0 + u * 8];
        }
        __syncthreads();

#pragma unroll
        for (int sp = 0; sp < 2; sp++) {
            const __half* Bm = smh + (sp ? SVL_OFF : SVH_OFF);
#pragma unroll
            for (int k16 = 0; k16 < 4; k16++) {
                const int kc = k16 * 16 + t * 2;
                uint32_t a[2][4];
#pragma unroll
                for (int m = 0; m < 2; m++) {
                    const int r0 = wr * 32 + m * 16 + g;
                    a[m][0] = *(const uint32_t*)&smh[SP_OFF + r0 * PV_STR + kc];
                    a[m][1] = *(const uint32_t*)&smh[SP_OFF + (r0 + 8) * PV_STR + kc];
                    a[m][2] = *(const uint32_t*)&smh[SP_OFF + r0 * PV_STR + kc + 8];
                    a[m][3] = *(const uint32_t*)&smh[SP_OFF + (r0 + 8) * PV_STR + kc + 8];
                }
#pragma unroll
                for (int n = 0; n < 9; n++) {
                    const int cn = wc * 72 + n * 8 + g;
                    const uint32_t b0 = *(const uint32_t*)&Bm[cn * PV_STR + kc];
                    const uint32_t b1 = *(const uint32_t*)&Bm[cn * PV_STR + kc + 8];
                    mma16816(acc[0][n], a[0], b0, b1);
                    mma16816(acc[1][n], a[1], b0, b1);
                }
            }
        }
        __syncthreads();
    }

    // normalize + store zi
#pragma unroll
    for (int m = 0; m < 2; m++) {
        const int row = row0 + wr * 32 + m * 16 + g;
        const float li0 = d_linv[b][row];
        const float li1 = d_linv[b][row + 8];
#pragma unroll
        for (int n = 0; n < 9; n++) {
            const int col = wc * 72 + n * 8 + t * 2;
            *(float2*)&d_zi[b][row][col]     = make_float2(acc[m][n][0] * li0, acc[m][n][1] * li0);
            *(float2*)&d_zi[b][row + 8][col] = make_float2(acc[m][n][2] * li1, acc[m][n][3] * li1);
        }
    }
}

// ============================================================
// Kernel 6: fold (overlap-add + count normalize) + W_w conv -> yvec
// ============================================================
__global__ void k_fold(const float* __restrict__ Wmat, const float* __restrict__ Wb) {
    __shared__ float zs[IC_][W_];
    __shared__ float wsm[C_ * IC_];
    __shared__ float bsm[C_];
    const int x = threadIdx.x;
    const int y = blockIdx.x, b = blockIdx.y;
    for (int i = x; i < C_ * IC_; i += 128) wsm[i] = Wmat[i];
    if (x < C_) bsm[x] = Wb[x];

    float v[IC_];
#pragma unroll
    for (int ic = 0; ic < IC_; ic++) v[ic] = 0.f;
    int cnt = 0;
#pragma unroll
    for (int i = 0; i < 3; i++) {
        const int tY = y + 1 - i;
        if (tY < 0 || (tY & 1) || (tY >> 1) >= HP_) continue;
        const int hp = tY >> 1;
#pragma unroll
        for (int j = 0; j < 3; j++) {
            const int tX = x + 1 - j;
            if (tX < 0 || (tX & 1) || (tX >> 1) >= HP_) continue;
            const int wp = tX >> 1;
            const float* zrow = &d_zi[b][hp * 64 + wp][0];
            cnt++;
#pragma unroll
            for (int ic = 0; ic < IC_; ic++) v[ic] += zrow[ic * 9 + i * 3 + j];
        }
    }
    const float invc = 1.0f / (float)cnt;
#pragma unroll
    for (int ic = 0; ic < IC_; ic++) zs[ic][x] = v[ic] * invc;
    __syncthreads();

    for (int o = 0; o < C_; o++) {
        float a = bsm[o];
#pragma unroll
        for (int ic = 0; ic < IC_; ic++) a += wsm[o * IC_ + ic] * zs[ic][x];
        d_yvec[b][o][y][x] = a;
    }
}

// ============================================================
// Kernel 7: out = s + yvec (broadcast over D)
// ============================================================
__global__ void k_out(const float* __restrict__ s, float* __restrict__ out) {
    const int idx = blockIdx.x * 256 + threadIdx.x;
    const int pix = idx & (H_ * W_ - 1);
    const int bo = (idx >> 14) >> 3;  // b*64 + o
    out[idx] = s[idx] + (&d_yvec[0][0][0][0])[bo * (H_ * W_) + pix];
}

// ============================================================
extern "C" void kernel_launch(void* const* d_in, const int* /*in_sizes*/, int /*n_in*/,
                              void* d_out, int /*out_size*/) {
    const float* s   = (const float*)d_in[0];
    const float* g   = (const float*)d_in[1];
    const float* g_w = (const float*)d_in[2];
    const float* g_b = (const float*)d_in[3];
    const float* t_w = (const float*)d_in[4];
    const float* t_b = (const float*)d_in[5];
    const float* p_w = (const float*)d_in[6];
    const float* p_b = (const float*)d_in[7];
    const float* W_w = (const float*)d_in[8];
    const float* W_b = (const float*)d_in[9];
    float* out = (float*)d_out;

    cudaFuncSetAttribute(k_gemmS,  cudaFuncAttributeMaxDynamicSharedMemorySize, SGEMM_SMEM_BYTES);
    cudaFuncSetAttribute(k_gemmPV, cudaFuncAttributeMaxDynamicSharedMemorySize, PV_SMEM_BYTES);

    k_conv<<<dim3(H_, B_), 128>>>(s, g, g_w, g_b, t_w, t_b, p_w, p_b);
    k_patch_qk<<<(B_ * L_ * F_) / 256, 256>>>();
    k_patch_v<<<(B_ * F_ * L_) / 256, 256>>>();

    k_gemmS<<<dim3(32, 32, B_), 256, SGEMM_SMEM_BYTES>>>();
    k_softmax<<<B_ * L_, 256>>>();
    k_gemmPV<<<dim3(32, B_), 256, PV_SMEM_BYTES>>>();

    k_fold<<<dim3(H_, B_), 128>>>(W_w, W_b);
    k_out<<<(B_ * C_ * D_ * H_ * W_) / 256, 256>>>(s, out);
}

// round 5
// speedup vs baseline: 2.6923x; 1.6023x over previous
#include <cuda_runtime.h>
#include <cuda_fp16.h>
#include <cstdint>

namespace {
constexpr int B_  = 4;
constexpr int C_  = 64;
constexpr int IC_ = 16;
constexpr int D_  = 8;
constexpr int H_  = 128;
constexpr int W_  = 128;
constexpr int MID_ = 4;
constexpr int HP_ = 64;
constexpr int L_  = 4096;
constexpr int F_  = 144;   // IC*3*3 = 9 * 16
constexpr int NCB_ = 32;   // number of 128-col chunks
constexpr float SCALE_ = 10.0f;

// S-GEMM smem (halfs)
constexpr int SQ_STR = 152;               // 144 + 8 pad (12g mod 32 distinct)
constexpr int SQH_OFF = 0;
constexpr int SQL_OFF = 128 * SQ_STR;
constexpr int SKH_OFF = 2 * 128 * SQ_STR;
constexpr int SKL_OFF = 3 * 128 * SQ_STR;
constexpr int SGEMM_SMEM_BYTES = 4 * 128 * SQ_STR * 2;  // 155648

// PV-GEMM smem layout (bytes):
// [scs: 32*128 floats][P0][P1][V0][V1], halfs stride 72
constexpr int PV_STR = 72;
constexpr int PV_SCS_BYTES = 32 * 128 * 4;                 // 16384
constexpr int PV_P_HALFS = 128 * PV_STR;                   // 9216
constexpr int PV_V_HALFS = 144 * PV_STR;                   // 10368
constexpr int PV_P_OFF = PV_SCS_BYTES;                     // byte offsets
constexpr int PV_V_OFF = PV_P_OFF + 2 * PV_P_HALFS * 2;
constexpr int PV_SMEM_BYTES = PV_V_OFF + 2 * PV_V_HALFS * 2;  // 94720
}

// ============================================================
// helpers
// ============================================================
__device__ __forceinline__ void mma16816(float* c, const uint32_t* a,
                                         uint32_t b0, uint32_t b1) {
    asm volatile(
        "mma.sync.aligned.m16n8k16.row.col.f32.f16.f16.f32 "
        "{%0,%1,%2,%3}, {%4,%5,%6,%7}, {%8,%9}, {%0,%1,%2,%3};"
        : "+f"(c[0]), "+f"(c[1]), "+f"(c[2]), "+f"(c[3])
        : "r"(a[0]), "r"(a[1]), "r"(a[2]), "r"(a[3]), "r"(b0), "r"(b1));
}

__device__ __forceinline__ void cp_async16(uint32_t smaddr, const void* gptr) {
    asm volatile("cp.async.cg.shared.global [%0], [%1], 16;"
                 :: "r"(smaddr), "l"(gptr) : "memory");
}
#define CP_COMMIT() asm volatile("cp.async.commit_group;" ::: "memory")
#define CP_WAIT(n)  asm volatile("cp.async.wait_group %0;" :: "n"(n) : "memory")

__device__ __forceinline__ uint32_t smem_u32(const void* p) {
    uint32_t a;
    asm("{ .reg .u64 t; cvta.to.shared.u64 t, %1; cvt.u32.u64 %0, t; }" : "=r"(a) : "l"(p));
    return a;
}

__device__ __forceinline__ void split16(float x, __half& h, __half& l) {
    h = __float2half_rn(x);
    l = __float2half_rn(x - __half2float(h));
}

// ============================================================
// scratch (device globals)
// ============================================================
__device__ float d_conv[3][B_][IC_][H_][W_];
__device__ __align__(16) __half d_qh[B_][L_][F_];
__device__ __align__(16) __half d_ql[B_][L_][F_];
__device__ __align__(16) __half d_kh[B_][L_][F_];
__device__ __align__(16) __half d_kl[B_][L_][F_];
__device__ __align__(16) __half d_vth[B_][F_][L_];
__device__ __align__(16) __half d_Pv[B_][L_][L_];     // exp(S - m_chunk), fp16
__device__ float d_mc[B_][NCB_][L_];
__device__ float d_lc[B_][NCB_][L_];
__device__ float d_scale[B_][NCB_][L_];
__device__ float d_linv[B_][L_];
__device__ float d_zi[B_][L_][F_];
__device__ float d_yvec[B_][C_][H_][W_];

// ============================================================
// Kernel 1: 1x1 convs at the mid depth slice only.
// ============================================================
__global__ void k_conv(const float* __restrict__ s, const float* __restrict__ g,
                       const float* __restrict__ gw, const float* __restrict__ gb,
                       const float* __restrict__ tw, const float* __restrict__ tb,
                       const float* __restrict__ pw, const float* __restrict__ pb) {
    __shared__ float wq[IC_ * C_], wv[IC_ * C_], wk[IC_ * C_];
    __shared__ float bq[IC_], bv[IC_], bk[IC_];
    const int tid = threadIdx.x;
    for (int i = tid; i < IC_ * C_; i += 128) { wq[i] = gw[i]; wv[i] = tw[i]; wk[i] = pw[i]; }
    if (tid < IC_) { bq[tid] = gb[tid]; bv[tid] = tb[tid]; bk[tid] = pb[tid]; }
    __syncthreads();

    const int y = blockIdx.x, b = blockIdx.y, x = tid;
    float aq[IC_], av[IC_], ak[IC_];
#pragma unroll
    for (int ic = 0; ic < IC_; ic++) { aq[ic] = bq[ic]; av[ic] = bv[ic]; ak[ic] = bk[ic]; }

    const size_t base = ((size_t)b * C_ * D_ + MID_) * (H_ * W_) + (size_t)y * W_ + x;
    const size_t cstride = (size_t)D_ * H_ * W_;
#pragma unroll 4
    for (int c = 0; c < C_; c++) {
        const float sv = s[base + c * cstride];
        const float gv = g[base + c * cstride];
#pragma unroll
        for (int ic = 0; ic < IC_; ic++) {
            aq[ic] += wq[ic * C_ + c] * sv;
            av[ic] += wv[ic * C_ + c] * gv;
            ak[ic] += wk[ic * C_ + c] * gv;
        }
    }
#pragma unroll
    for (int ic = 0; ic < IC_; ic++) {
        const int o = ((b * IC_ + ic) * H_ + y) * W_ + x;
        (&d_conv[0][0][0][0][0])[o] = aq[ic];
        (&d_conv[1][0][0][0][0])[o] = av[ic];
        (&d_conv[2][0][0][0][0])[o] = ak[ic];
    }
}

// ============================================================
// Kernel 2a: patches -> q (pre-scaled by 10) and k, fp16 hi/lo split.
// ============================================================
__global__ void k_patch_qk() {
    const int idx = blockIdx.x * 256 + threadIdx.x;
    const int f = idx % F_;
    const int t = idx / F_;
    const int l = t & (L_ - 1);
    const int b = t >> 12;
    const int c = f / 9;
    const int r = f - c * 9;
    const int ki = r / 3, kj = r - (r / 3) * 3;
    const int hp = l >> 6, wp = l & 63;
    const int y = hp * 2 - 1 + ki;
    const int x = wp * 2 - 1 + kj;
    const bool in = ((unsigned)y < (unsigned)H_) && ((unsigned)x < (unsigned)W_);
    float q = in ? d_conv[0][b][c][y][x] : 0.0f;
    float k = in ? d_conv[2][b][c][y][x] : 0.0f;
    q *= SCALE_;
    __half qh, ql, kh, kl;
    split16(q, qh, ql);
    split16(k, kh, kl);
    d_qh[b][l][f] = qh; d_ql[b][l][f] = ql;
    d_kh[b][l][f] = kh; d_kl[b][l][f] = kl;
}

// ============================================================
// Kernel 2b: patches -> V transposed [b][f][l], fp16 (single precision pass).
// ============================================================
__global__ void k_patch_v() {
    const int idx = blockIdx.x * 256 + threadIdx.x;
    const int b = idx / (F_ * L_);
    const int rem = idx - b * (F_ * L_);
    const int f = rem / L_;
    const int l = rem - f * L_;
    const int c = f / 9;
    const int r = f - c * 9;
    const int ki = r / 3, kj = r - (r / 3) * 3;
    const int hp = l >> 6, wp = l & 63;
    const int y = hp * 2 - 1 + ki;
    const int x = wp * 2 - 1 + kj;
    const bool in = ((unsigned)y < (unsigned)H_) && ((unsigned)x < (unsigned)W_);
    const float v = in ? d_conv[1][b][c][y][x] : 0.0f;
    d_vth[b][f][l] = __float2half_rn(v);
}

// ============================================================
// Kernel 3: S = (10 Q) K^T (3 fp16 split passes) + fused chunk softmax.
// grid (32 col-chunks, 32 row-tiles, B), 512 threads = 16 warps (4 wr x 4 wc),
// warp tile 32x32. Writes P = exp(S - m_cb) fp16 + d_mc/d_lc.
// ============================================================
__global__ __launch_bounds__(512, 1) void k_gemmS() {
    extern __shared__ __half smh[];
    __shared__ float redbuf[4][128];
    __shared__ float mfin[128];

    const int tid = threadIdx.x;
    const int lane = tid & 31;
    const int warp = tid >> 5;
    const int wr = warp >> 2;           // 0..3 (rows)
    const int wc = warp & 3;            // 0..3 (cols)
    const int g = lane >> 2;            // 0..7
    const int t = lane & 3;             // 0..3
    const int b = blockIdx.z;
    const int row0 = blockIdx.y * 128;
    const int col0 = blockIdx.x * 128;
    const int cb = blockIdx.x;

    // load Q and K tiles hi/lo: 128 rows x 144 halfs each (18 uint4/row)
    for (int e = tid; e < 128 * 18; e += 512) {
        const int r = e / 18, u = e - (e / 18) * 18;
        const int so = r * SQ_STR + u * 8;
        *(uint4*)&smh[SQH_OFF + so] = *(const uint4*)&d_qh[b][row0 + r][u * 8];
        *(uint4*)&smh[SQL_OFF + so] = *(const uint4*)&d_ql[b][row0 + r][u * 8];
        *(uint4*)&smh[SKH_OFF + so] = *(const uint4*)&d_kh[b][col0 + r][u * 8];
        *(uint4*)&smh[SKL_OFF + so] = *(const uint4*)&d_kl[b][col0 + r][u * 8];
    }
    __syncthreads();

    float acc[2][4][4];
#pragma unroll
    for (int m = 0; m < 2; m++)
#pragma unroll
        for (int n = 0; n < 4; n++)
#pragma unroll
            for (int j = 0; j < 4; j++) acc[m][n][j] = 0.f;

#pragma unroll
    for (int sp = 0; sp < 3; sp++) {
        const __half* A  = smh + ((sp == 2) ? SQL_OFF : SQH_OFF);
        const __half* Bm = smh + ((sp == 1) ? SKL_OFF : SKH_OFF);
#pragma unroll
        for (int k16 = 0; k16 < 9; k16++) {
            const int kc = k16 * 16 + t * 2;
            uint32_t a[2][4];
#pragma unroll
            for (int m = 0; m < 2; m++) {
                const int r0 = wr * 32 + m * 16 + g;
                a[m][0] = *(const uint32_t*)&A[r0 * SQ_STR + kc];
                a[m][1] = *(const uint32_t*)&A[(r0 + 8) * SQ_STR + kc];
                a[m][2] = *(const uint32_t*)&A[r0 * SQ_STR + kc + 8];
                a[m][3] = *(const uint32_t*)&A[(r0 + 8) * SQ_STR + kc + 8];
            }
#pragma unroll
            for (int n = 0; n < 4; n++) {
                const int cn = wc * 32 + n * 8 + g;
                const uint32_t b0 = *(const uint32_t*)&Bm[cn * SQ_STR + kc];
                const uint32_t b1 = *(const uint32_t*)&Bm[cn * SQ_STR + kc + 8];
                mma16816(acc[0][n], a[0], b0, b1);
                mma16816(acc[1][n], a[1], b0, b1);
            }
        }
    }

    // ---- fused chunk softmax ----
    // thread rows: R[ri] = wr*32 + (ri>>1)*16 + (ri&1)*8 + g, ri = 0..3
    // values for row ri: acc[ri>>1][n][(ri&1)*2 + {0,1}], n = 0..3
    float rmax[4];
#pragma unroll
    for (int ri = 0; ri < 4; ri++) {
        const int m = ri >> 1, jb = (ri & 1) * 2;
        float mx = acc[m][0][jb];
#pragma unroll
        for (int n = 0; n < 4; n++)
            mx = fmaxf(mx, fmaxf(acc[m][n][jb], acc[m][n][jb + 1]));
        rmax[ri] = mx;
    }
#pragma unroll
    for (int off = 1; off <= 2; off <<= 1)
#pragma unroll
        for (int ri = 0; ri < 4; ri++)
            rmax[ri] = fmaxf(rmax[ri], __shfl_xor_sync(0xffffffffu, rmax[ri], off));
    if (t == 0) {
#pragma unroll
        for (int ri = 0; ri < 4; ri++)
            redbuf[wc][wr * 32 + (ri >> 1) * 16 + (ri & 1) * 8 + g] = rmax[ri];
    }
    __syncthreads();
    if (tid < 128)
        mfin[tid] = fmaxf(fmaxf(redbuf[0][tid], redbuf[1][tid]),
                          fmaxf(redbuf[2][tid], redbuf[3][tid]));
    __syncthreads();

    float rsum[4];
#pragma unroll
    for (int ri = 0; ri < 4; ri++) {
        const int m = ri >> 1, jb = (ri & 1) * 2;
        const int row = wr * 32 + (ri >> 1) * 16 + (ri & 1) * 8 + g;
        const float mx = mfin[row];
        float sum = 0.f;
#pragma unroll
        for (int n = 0; n < 4; n++) {
            const float e0 = __expf(acc[m][n][jb] - mx);
            const float e1 = __expf(acc[m][n][jb + 1] - mx);
            sum += e0 + e1;
            *(__half2*)&d_Pv[b][row0 + row][col0 + wc * 32 + n * 8 + t * 2] =
                __floats2half2_rn(e0, e1);
        }
        rsum[ri] = sum;
    }
#pragma unroll
    for (int off = 1; off <= 2; off <<= 1)
#pragma unroll
        for (int ri = 0; ri < 4; ri++)
            rsum[ri] += __shfl_xor_sync(0xffffffffu, rsum[ri], off);
    if (t == 0) {
#pragma unroll
        for (int ri = 0; ri < 4; ri++)
            redbuf[wc][wr * 32 + (ri >> 1) * 16 + (ri & 1) * 8 + g] = rsum[ri];
    }
    __syncthreads();
    if (tid < 128) {
        d_mc[b][cb][row0 + tid] = mfin[tid];
        d_lc[b][cb][row0 + tid] = redbuf[0][tid] + redbuf[1][tid] +
                                  redbuf[2][tid] + redbuf[3][tid];
    }
}

// ============================================================
// Kernel 4: per-row reduction: final max, chunk scales, 1/l.
// ============================================================
__global__ void k_reduce() {
    const int idx = blockIdx.x * 256 + threadIdx.x;   // b*4096 + r
    const int b = idx >> 12, r = idx & 4095;
    float ms[NCB_];
    float m = -1e30f;
#pragma unroll
    for (int c = 0; c < NCB_; c++) { ms[c] = d_mc[b][c][r]; m = fmaxf(m, ms[c]); }
    float l = 0.0f;
#pragma unroll
    for (int c = 0; c < NCB_; c++) {
        const float sc = __expf(ms[c] - m);
        d_scale[b][c][r] = sc;
        l += sc * d_lc[b][c][r];
    }
    d_linv[b][r] = 1.0f / l;
}

// ============================================================
// Kernel 5: zi = (P_scaled / l) V, fp16 HMMA, single V pass,
// cp.async double-buffered V + register-prefetched P.
// grid (32 row-tiles, B), 256 threads = 8 warps (4 wr x 2 wc), warp 32x72.
// ============================================================
__global__ __launch_bounds__(256, 1) void k_gemmPV() {
    extern __shared__ char smc[];
    float* scs = (float*)smc;                      // [32 cb][128 rows]
    __half* smP = (__half*)(smc + PV_P_OFF);       // [2][128*72]
    __half* smV = (__half*)(smc + PV_V_OFF);       // [2][144*72]

    const int tid = threadIdx.x;
    const int lane = tid & 31;
    const int warp = tid >> 5;
    const int wr = warp >> 1;
    const int wc = warp & 1;
    const int g = lane >> 2;
    const int t = lane & 3;
    const int b = blockIdx.y;
    const int row0 = blockIdx.x * 128;

    // preload all 32 per-row chunk scales
    for (int e = tid; e < 32 * 128; e += 256)
        scs[e] = d_scale[b][e >> 7][row0 + (e & 127)];

    float acc[2][9][4];
#pragma unroll
    for (int m = 0; m < 2; m++)
#pragma unroll
        for (int n = 0; n < 9; n++)
#pragma unroll
            for (int j = 0; j < 4; j++) acc[m][n][j] = 0.f;

    // thread's P-staging coordinates: e = tid + i*256; r = e>>3, u = e&7
    const int pr_r[4] = { (tid) >> 3, (tid + 256) >> 3, (tid + 512) >> 3, (tid + 768) >> 3 };
    const int pr_u = tid & 7;

    // prologue: issue V chunk 0 + load P chunk 0 into regs
    {
        const uint32_t vbase = smem_u32(smV);
        for (int e = tid; e < 144 * 8; e += 256) {
            const int f = e >> 3, u = e & 7;
            cp_async16(vbase + (f * PV_STR + u * 8) * 2, &d_vth[b][f][0 + u * 8]);
        }
        CP_COMMIT();
    }
    uint4 pr[4];
#pragma unroll
    for (int i = 0; i < 4; i++)
        pr[i] = *(const uint4*)&d_Pv[b][row0 + pr_r[i]][0 + pr_u * 8];
    __syncthreads();   // scs ready

    for (int ct = 0; ct < 64; ct++) {
        const int buf = ct & 1;
        __half* P = smP + buf * PV_P_HALFS;
        __half* V = smV + buf * PV_V_HALFS;

        // stage P (scaled) into smem
        {
            const float* scrow = scs + (ct >> 1) * 128;
#pragma unroll
            for (int i = 0; i < 4; i++) {
                const __half2 hsc = __float2half2_rn(scrow[pr_r[i]]);
                uint4 p = pr[i];
                __half2* ph = (__half2*)&p;
#pragma unroll
                for (int j = 0; j < 4; j++) ph[j] = __hmul2(ph[j], hsc);
                *(uint4*)&P[pr_r[i] * PV_STR + pr_u * 8] = p;
            }
        }
        CP_WAIT(0);          // V[buf] arrived
        __syncthreads();

        if (ct < 63) {
            // issue V(ct+1) into other buffer; prefetch P(ct+1) regs
            const uint32_t vbase = smem_u32(smV + (buf ^ 1) * PV_V_HALFS);
            const int k1 = (ct + 1) * 64;
            for (int e = tid; e < 144 * 8; e += 256) {
                const int f = e >> 3, u = e & 7;
                cp_async16(vbase + (f * PV_STR + u * 8) * 2, &d_vth[b][f][k1 + u * 8]);
            }
            CP_COMMIT();
#pragma unroll
            for (int i = 0; i < 4; i++)
                pr[i] = *(const uint4*)&d_Pv[b][row0 + pr_r[i]][k1 + pr_u * 8];
        }

        // compute
#pragma unroll
        for (int k16 = 0; k16 < 4; k16++) {
            const int kc = k16 * 16 + t * 2;
            uint32_t a[2][4];
#pragma unroll
            for (int m = 0; m < 2; m++) {
                const int r0 = wr * 32 + m * 16 + g;
                a[m][0] = *(const uint32_t*)&P[r0 * PV_STR + kc];
                a[m][1] = *(const uint32_t*)&P[(r0 + 8) * PV_STR + kc];
                a[m][2] = *(const uint32_t*)&P[r0 * PV_STR + kc + 8];
                a[m][3] = *(const uint32_t*)&P[(r0 + 8) * PV_STR + kc + 8];
            }
#pragma unroll
            for (int n = 0; n < 9; n++) {
                const int cn = wc * 72 + n * 8 + g;
                const uint32_t b0 = *(const uint32_t*)&V[cn * PV_STR + kc];
                const uint32_t b1 = *(const uint32_t*)&V[cn * PV_STR + kc + 8];
                mma16816(acc[0][n], a[0], b0, b1);
                mma16816(acc[1][n], a[1], b0, b1);
            }
        }
        __syncthreads();
    }

    // normalize + store zi
#pragma unroll
    for (int m = 0; m < 2; m++) {
        const int row = row0 + wr * 32 + m * 16 + g;
        const float li0 = d_linv[b][row];
        const float li1 = d_linv[b][row + 8];
#pragma unroll
        for (int n = 0; n < 9; n++) {
            const int col = wc * 72 + n * 8 + t * 2;
            *(float2*)&d_zi[b][row][col]     = make_float2(acc[m][n][0] * li0, acc[m][n][1] * li0);
            *(float2*)&d_zi[b][row + 8][col] = make_float2(acc[m][n][2] * li1, acc[m][n][3] * li1);
        }
    }
}

// ============================================================
// Kernel 6: fold (overlap-add + count normalize) + W_w conv -> yvec
// ============================================================
__global__ void k_fold(const float* __restrict__ Wmat, const float* __restrict__ Wb) {
    __shared__ float zs[IC_][W_];
    __shared__ float wsm[C_ * IC_];
    __shared__ float bsm[C_];
    const int x = threadIdx.x;
    const int y = blockIdx.x, b = blockIdx.y;
    for (int i = x; i < C_ * IC_; i += 128) wsm[i] = Wmat[i];
    if (x < C_) bsm[x] = Wb[x];

    float v[IC_];
#pragma unroll
    for (int ic = 0; ic < IC_; ic++) v[ic] = 0.f;
    int cnt = 0;
#pragma unroll
    for (int i = 0; i < 3; i++) {
        const int tY = y + 1 - i;
        if (tY < 0 || (tY & 1) || (tY >> 1) >= HP_) continue;
        const int hp = tY >> 1;
#pragma unroll
        for (int j = 0; j < 3; j++) {
            const int tX = x + 1 - j;
            if (tX < 0 || (tX & 1) || (tX >> 1) >= HP_) continue;
            const int wp = tX >> 1;
            const float* zrow = &d_zi[b][hp * 64 + wp][0];
            cnt++;
#pragma unroll
            for (int ic = 0; ic < IC_; ic++) v[ic] += zrow[ic * 9 + i * 3 + j];
        }
    }
    const float invc = 1.0f / (float)cnt;
#pragma unroll
    for (int ic = 0; ic < IC_; ic++) zs[ic][x] = v[ic] * invc;
    __syncthreads();

    for (int o = 0; o < C_; o++) {
        float a = bsm[o];
#pragma unroll
        for (int ic = 0; ic < IC_; ic++) a += wsm[o * IC_ + ic] * zs[ic][x];
        d_yvec[b][o][y][x] = a;
    }
}

// ============================================================
// Kernel 7: out = s + yvec (broadcast over D)
// ============================================================
__global__ void k_out(const float* __restrict__ s, float* __restrict__ out) {
    const int idx = blockIdx.x * 256 + threadIdx.x;
    const int pix = idx & (H_ * W_ - 1);
    const int bo = (idx >> 14) >> 3;  // b*64 + o
    out[idx] = s[idx] + (&d_yvec[0][0][0][0])[bo * (H_ * W_) + pix];
}

// ============================================================
extern "C" void kernel_launch(void* const* d_in, const int* /*in_sizes*/, int /*n_in*/,
                              void* d_out, int /*out_size*/) {
    const float* s   = (const float*)d_in[0];
    const float* g   = (const float*)d_in[1];
    const float* g_w = (const float*)d_in[2];
    const float* g_b = (const float*)d_in[3];
    const float* t_w = (const float*)d_in[4];
    const float* t_b = (const float*)d_in[5];
    const float* p_w = (const float*)d_in[6];
    const float* p_b = (const float*)d_in[7];
    const float* W_w = (const float*)d_in[8];
    const float* W_b = (const float*)d_in[9];
    float* out = (float*)d_out;

    cudaFuncSetAttribute(k_gemmS,  cudaFuncAttributeMaxDynamicSharedMemorySize, SGEMM_SMEM_BYTES);
    cudaFuncSetAttribute(k_gemmPV, cudaFuncAttributeMaxDynamicSharedMemorySize, PV_SMEM_BYTES);

    k_conv<<<dim3(H_, B_), 128>>>(s, g, g_w, g_b, t_w, t_b, p_w, p_b);
    k_patch_qk<<<(B_ * L_ * F_) / 256, 256>>>();
    k_patch_v<<<(B_ * F_ * L_) / 256, 256>>>();

    k_gemmS<<<dim3(32, 32, B_), 512, SGEMM_SMEM_BYTES>>>();
    k_reduce<<<(B_ * L_) / 256, 256>>>();
    k_gemmPV<<<dim3(32, B_), 256, PV_SMEM_BYTES>>>();

    k_fold<<<dim3(H_, B_), 128>>>(W_w, W_b);
    k_out<<<(B_ * C_ * D_ * H_ * W_) / 256, 256>>>(s, out);
}

// round 6
// speedup vs baseline: 2.8512x; 1.0590x over previous
#include <cuda_runtime.h>
#include <cuda_fp16.h>
#include <cstdint>

namespace {
constexpr int B_  = 4;
constexpr int C_  = 64;
constexpr int IC_ = 16;
constexpr int D_  = 8;
constexpr int H_  = 128;
constexpr int W_  = 128;
constexpr int MID_ = 4;
constexpr int HP_ = 64;
constexpr int L_  = 4096;
constexpr int F_  = 144;   // IC*3*3 = 9 * 16
constexpr int NCB_ = 32;   // number of 128-col chunks
constexpr float SCALE_ = 10.0f;

// S-GEMM smem (halfs)
constexpr int SQ_STR = 152;               // 144 + 8 pad
constexpr int SQH_OFF = 0;
constexpr int SQL_OFF = 128 * SQ_STR;
constexpr int SKH_OFF = 2 * 128 * SQ_STR;
constexpr int SKL_OFF = 3 * 128 * SQ_STR;
constexpr int SGEMM_SMEM_BYTES = 4 * 128 * SQ_STR * 2;  // 155648

// PV-GEMM smem layout (bytes)
constexpr int PV_STR = 72;
constexpr int PV_SCS_BYTES = 32 * 128 * 4;                 // 16384
constexpr int PV_P_HALFS = 128 * PV_STR;                   // 9216
constexpr int PV_V_HALFS = 144 * PV_STR;                   // 10368
constexpr int PV_P_OFF = PV_SCS_BYTES;
constexpr int PV_V_OFF = PV_P_OFF + 2 * PV_P_HALFS * 2;
constexpr int PV_SMEM_BYTES = PV_V_OFF + 2 * PV_V_HALFS * 2;  // 94720
}

// ============================================================
// helpers
// ============================================================
__device__ __forceinline__ void mma16816(float* c, const uint32_t* a,
                                         uint32_t b0, uint32_t b1) {
    asm volatile(
        "mma.sync.aligned.m16n8k16.row.col.f32.f16.f16.f32 "
        "{%0,%1,%2,%3}, {%4,%5,%6,%7}, {%8,%9}, {%0,%1,%2,%3};"
        : "+f"(c[0]), "+f"(c[1]), "+f"(c[2]), "+f"(c[3])
        : "r"(a[0]), "r"(a[1]), "r"(a[2]), "r"(a[3]), "r"(b0), "r"(b1));
}

__device__ __forceinline__ void ldsm_x4(uint32_t* r, uint32_t smaddr) {
    asm volatile("ldmatrix.sync.aligned.m8n8.x4.shared.b16 {%0,%1,%2,%3}, [%4];"
                 : "=r"(r[0]), "=r"(r[1]), "=r"(r[2]), "=r"(r[3]) : "r"(smaddr));
}
__device__ __forceinline__ void ldsm_x2(uint32_t* r, uint32_t smaddr) {
    asm volatile("ldmatrix.sync.aligned.m8n8.x2.shared.b16 {%0,%1}, [%2];"
                 : "=r"(r[0]), "=r"(r[1]) : "r"(smaddr));
}

__device__ __forceinline__ void cp_async16(uint32_t smaddr, const void* gptr) {
    asm volatile("cp.async.cg.shared.global [%0], [%1], 16;"
                 :: "r"(smaddr), "l"(gptr) : "memory");
}
#define CP_COMMIT() asm volatile("cp.async.commit_group;" ::: "memory")
#define CP_WAIT(n)  asm volatile("cp.async.wait_group %0;" :: "n"(n) : "memory")

__device__ __forceinline__ uint32_t smem_u32(const void* p) {
    uint32_t a;
    asm("{ .reg .u64 t; cvta.to.shared.u64 t, %1; cvt.u32.u64 %0, t; }" : "=r"(a) : "l"(p));
    return a;
}

__device__ __forceinline__ void split16(float x, __half& h, __half& l) {
    h = __float2half_rn(x);
    l = __float2half_rn(x - __half2float(h));
}

// ============================================================
// scratch (device globals)
// ============================================================
__device__ float d_conv[3][B_][IC_][H_][W_];
__device__ __align__(16) __half d_qh[B_][L_][F_];
__device__ __align__(16) __half d_ql[B_][L_][F_];
__device__ __align__(16) __half d_kh[B_][L_][F_];
__device__ __align__(16) __half d_kl[B_][L_][F_];
__device__ __align__(16) __half d_vth[B_][F_][L_];
__device__ __align__(16) __half d_Pv[B_][L_][L_];     // exp(S - m_chunk), fp16
__device__ float d_mc[B_][NCB_][L_];
__device__ float d_lc[B_][NCB_][L_];
__device__ float d_scale[B_][NCB_][L_];
__device__ float d_linv[B_][L_];
__device__ float d_zi[B_][L_][F_];
__device__ float d_yvec[B_][C_][H_][W_];

// ============================================================
// Kernel 1: 1x1 convs at the mid depth slice only.
// ============================================================
__global__ void k_conv(const float* __restrict__ s, const float* __restrict__ g,
                       const float* __restrict__ gw, const float* __restrict__ gb,
                       const float* __restrict__ tw, const float* __restrict__ tb,
                       const float* __restrict__ pw, const float* __restrict__ pb) {
    __shared__ float wq[IC_ * C_], wv[IC_ * C_], wk[IC_ * C_];
    __shared__ float bq[IC_], bv[IC_], bk[IC_];
    const int tid = threadIdx.x;
    for (int i = tid; i < IC_ * C_; i += 128) { wq[i] = gw[i]; wv[i] = tw[i]; wk[i] = pw[i]; }
    if (tid < IC_) { bq[tid] = gb[tid]; bv[tid] = tb[tid]; bk[tid] = pb[tid]; }
    __syncthreads();

    const int y = blockIdx.x, b = blockIdx.y, x = tid;
    float aq[IC_], av[IC_], ak[IC_];
#pragma unroll
    for (int ic = 0; ic < IC_; ic++) { aq[ic] = bq[ic]; av[ic] = bv[ic]; ak[ic] = bk[ic]; }

    const size_t base = ((size_t)b * C_ * D_ + MID_) * (H_ * W_) + (size_t)y * W_ + x;
    const size_t cstride = (size_t)D_ * H_ * W_;
#pragma unroll 4
    for (int c = 0; c < C_; c++) {
        const float sv = s[base + c * cstride];
        const float gv = g[base + c * cstride];
#pragma unroll
        for (int ic = 0; ic < IC_; ic++) {
            aq[ic] += wq[ic * C_ + c] * sv;
            av[ic] += wv[ic * C_ + c] * gv;
            ak[ic] += wk[ic * C_ + c] * gv;
        }
    }
#pragma unroll
    for (int ic = 0; ic < IC_; ic++) {
        const int o = ((b * IC_ + ic) * H_ + y) * W_ + x;
        (&d_conv[0][0][0][0][0])[o] = aq[ic];
        (&d_conv[1][0][0][0][0])[o] = av[ic];
        (&d_conv[2][0][0][0][0])[o] = ak[ic];
    }
}

// ============================================================
// Kernel 2a: patches -> q (pre-scaled by 10) and k, fp16 hi/lo split.
// ============================================================
__global__ void k_patch_qk() {
    const int idx = blockIdx.x * 256 + threadIdx.x;
    const int f = idx % F_;
    const int t = idx / F_;
    const int l = t & (L_ - 1);
    const int b = t >> 12;
    const int c = f / 9;
    const int r = f - c * 9;
    const int ki = r / 3, kj = r - (r / 3) * 3;
    const int hp = l >> 6, wp = l & 63;
    const int y = hp * 2 - 1 + ki;
    const int x = wp * 2 - 1 + kj;
    const bool in = ((unsigned)y < (unsigned)H_) && ((unsigned)x < (unsigned)W_);
    float q = in ? d_conv[0][b][c][y][x] : 0.0f;
    float k = in ? d_conv[2][b][c][y][x] : 0.0f;
    q *= SCALE_;
    __half qh, ql, kh, kl;
    split16(q, qh, ql);
    split16(k, kh, kl);
    d_qh[b][l][f] = qh; d_ql[b][l][f] = ql;
    d_kh[b][l][f] = kh; d_kl[b][l][f] = kl;
}

// ============================================================
// Kernel 2b: patches -> V transposed [b][f][l], fp16.
// ============================================================
__global__ void k_patch_v() {
    const int idx = blockIdx.x * 256 + threadIdx.x;
    const int b = idx / (F_ * L_);
    const int rem = idx - b * (F_ * L_);
    const int f = rem / L_;
    const int l = rem - f * L_;
    const int c = f / 9;
    const int r = f - c * 9;
    const int ki = r / 3, kj = r - (r / 3) * 3;
    const int hp = l >> 6, wp = l & 63;
    const int y = hp * 2 - 1 + ki;
    const int x = wp * 2 - 1 + kj;
    const bool in = ((unsigned)y < (unsigned)H_) && ((unsigned)x < (unsigned)W_);
    const float v = in ? d_conv[1][b][c][y][x] : 0.0f;
    d_vth[b][f][l] = __float2half_rn(v);
}

// ============================================================
// Kernel 3: S = (10 Q) K^T (3 fp16 split passes) + fused chunk softmax.
// grid (32 col-chunks, 32 row-tiles, B), 512 threads = 16 warps (4 wr x 4 wc),
// warp tile 32x32, LDSM fragment loads.
// ============================================================
__global__ __launch_bounds__(512, 1) void k_gemmS() {
    extern __shared__ __half smh[];
    __shared__ float redbuf[4][128];
    __shared__ float mfin[128];

    const int tid = threadIdx.x;
    const int lane = tid & 31;
    const int warp = tid >> 5;
    const int wr = warp >> 2;           // 0..3 (rows)
    const int wc = warp & 3;            // 0..3 (cols)
    const int g = lane >> 2;            // 0..7
    const int t = lane & 3;             // 0..3
    const int b = blockIdx.z;
    const int row0 = blockIdx.y * 128;
    const int col0 = blockIdx.x * 128;
    const int cb = blockIdx.x;

    // load Q and K tiles hi/lo via cp.async
    {
        const uint32_t sbase = smem_u32(smh);
        for (int e = tid; e < 128 * 18; e += 512) {
            const int r = e / 18, u = e - (e / 18) * 18;
            const uint32_t so = (uint32_t)(r * SQ_STR + u * 8) * 2;
            cp_async16(sbase + SQH_OFF * 2 + so, &d_qh[b][row0 + r][u * 8]);
            cp_async16(sbase + SQL_OFF * 2 + so, &d_ql[b][row0 + r][u * 8]);
            cp_async16(sbase + SKH_OFF * 2 + so, &d_kh[b][col0 + r][u * 8]);
            cp_async16(sbase + SKL_OFF * 2 + so, &d_kl[b][col0 + r][u * 8]);
        }
        CP_COMMIT();
        CP_WAIT(0);
    }
    __syncthreads();

    // LDSM lane addressing (byte offsets within a tile)
    const uint32_t sbase = smem_u32(smh);
    const uint32_t aoff0 = (uint32_t)((wr * 32 + 0  + (lane & 15)) * SQ_STR + ((lane >> 4) << 3)) * 2;
    const uint32_t aoff1 = (uint32_t)((wr * 32 + 16 + (lane & 15)) * SQ_STR + ((lane >> 4) << 3)) * 2;
    const uint32_t boff0 = (uint32_t)((wc * 32 + 0  + (lane & 7) + ((lane >> 4) << 3)) * SQ_STR +
                                      (((lane >> 3) & 1) << 3)) * 2;
    const uint32_t boff1 = (uint32_t)((wc * 32 + 16 + (lane & 7) + ((lane >> 4) << 3)) * SQ_STR +
                                      (((lane >> 3) & 1) << 3)) * 2;

    float acc[2][4][4];
#pragma unroll
    for (int m = 0; m < 2; m++)
#pragma unroll
        for (int n = 0; n < 4; n++)
#pragma unroll
            for (int j = 0; j < 4; j++) acc[m][n][j] = 0.f;

#pragma unroll
    for (int sp = 0; sp < 3; sp++) {
        const uint32_t Ab = sbase + ((sp == 2) ? SQL_OFF : SQH_OFF) * 2;
        const uint32_t Bb = sbase + ((sp == 1) ? SKL_OFF : SKH_OFF) * 2;
#pragma unroll
        for (int k16 = 0; k16 < 9; k16++) {
            const uint32_t kb = (uint32_t)(k16 * 16) * 2;
            uint32_t a[2][4], bb[2][4];
            ldsm_x4(a[0], Ab + aoff0 + kb);
            ldsm_x4(a[1], Ab + aoff1 + kb);
            ldsm_x4(bb[0], Bb + boff0 + kb);
            ldsm_x4(bb[1], Bb + boff1 + kb);
            mma16816(acc[0][0], a[0], bb[0][0], bb[0][1]);
            mma16816(acc[1][0], a[1], bb[0][0], bb[0][1]);
            mma16816(acc[0][1], a[0], bb[0][2], bb[0][3]);
            mma16816(acc[1][1], a[1], bb[0][2], bb[0][3]);
            mma16816(acc[0][2], a[0], bb[1][0], bb[1][1]);
            mma16816(acc[1][2], a[1], bb[1][0], bb[1][1]);
            mma16816(acc[0][3], a[0], bb[1][2], bb[1][3]);
            mma16816(acc[1][3], a[1], bb[1][2], bb[1][3]);
        }
    }

    // ---- fused chunk softmax ----
    float rmax[4];
#pragma unroll
    for (int ri = 0; ri < 4; ri++) {
        const int m = ri >> 1, jb = (ri & 1) * 2;
        float mx = acc[m][0][jb];
#pragma unroll
        for (int n = 0; n < 4; n++)
            mx = fmaxf(mx, fmaxf(acc[m][n][jb], acc[m][n][jb + 1]));
        rmax[ri] = mx;
    }
#pragma unroll
    for (int off = 1; off <= 2; off <<= 1)
#pragma unroll
        for (int ri = 0; ri < 4; ri++)
            rmax[ri] = fmaxf(rmax[ri], __shfl_xor_sync(0xffffffffu, rmax[ri], off));
    if (t == 0) {
#pragma unroll
        for (int ri = 0; ri < 4; ri++)
            redbuf[wc][wr * 32 + (ri >> 1) * 16 + (ri & 1) * 8 + g] = rmax[ri];
    }
    __syncthreads();
    if (tid < 128)
        mfin[tid] = fmaxf(fmaxf(redbuf[0][tid], redbuf[1][tid]),
                          fmaxf(redbuf[2][tid], redbuf[3][tid]));
    __syncthreads();

    float rsum[4];
#pragma unroll
    for (int ri = 0; ri < 4; ri++) {
        const int m = ri >> 1, jb = (ri & 1) * 2;
        const int row = wr * 32 + (ri >> 1) * 16 + (ri & 1) * 8 + g;
        const float mx = mfin[row];
        float sum = 0.f;
#pragma unroll
        for (int n = 0; n < 4; n++) {
            const float e0 = __expf(acc[m][n][jb] - mx);
            const float e1 = __expf(acc[m][n][jb + 1] - mx);
            sum += e0 + e1;
            *(__half2*)&d_Pv[b][row0 + row][col0 + wc * 32 + n * 8 + t * 2] =
                __floats2half2_rn(e0, e1);
        }
        rsum[ri] = sum;
    }
#pragma unroll
    for (int off = 1; off <= 2; off <<= 1)
#pragma unroll
        for (int ri = 0; ri < 4; ri++)
            rsum[ri] += __shfl_xor_sync(0xffffffffu, rsum[ri], off);
    if (t == 0) {
#pragma unroll
        for (int ri = 0; ri < 4; ri++)
            redbuf[wc][wr * 32 + (ri >> 1) * 16 + (ri & 1) * 8 + g] = rsum[ri];
    }
    __syncthreads();
    if (tid < 128) {
        d_mc[b][cb][row0 + tid] = mfin[tid];
        d_lc[b][cb][row0 + tid] = redbuf[0][tid] + redbuf[1][tid] +
                                  redbuf[2][tid] + redbuf[3][tid];
    }
}

// ============================================================
// Kernel 4: per-row reduction: final max, chunk scales, 1/l.
// ============================================================
__global__ void k_reduce() {
    const int idx = blockIdx.x * 256 + threadIdx.x;   // b*4096 + r
    const int b = idx >> 12, r = idx & 4095;
    float ms[NCB_];
    float m = -1e30f;
#pragma unroll
    for (int c = 0; c < NCB_; c++) { ms[c] = d_mc[b][c][r]; m = fmaxf(m, ms[c]); }
    float l = 0.0f;
#pragma unroll
    for (int c = 0; c < NCB_; c++) {
        const float sc = __expf(ms[c] - m);
        d_scale[b][c][r] = sc;
        l += sc * d_lc[b][c][r];
    }
    d_linv[b][r] = 1.0f / l;
}

// ============================================================
// Kernel 5: zi = (P_scaled / l) V, fp16 HMMA + LDSM, double-buffered V.
// grid (32 row-tiles, B), 256 threads = 8 warps (4 wr x 2 wc), warp 32x72.
// ============================================================
__global__ __launch_bounds__(256, 1) void k_gemmPV() {
    extern __shared__ char smc[];
    float* scs = (float*)smc;                      // [32 cb][128 rows]
    __half* smP = (__half*)(smc + PV_P_OFF);       // [2][128*72]
    __half* smV = (__half*)(smc + PV_V_OFF);       // [2][144*72]

    const int tid = threadIdx.x;
    const int lane = tid & 31;
    const int warp = tid >> 5;
    const int wr = warp >> 1;
    const int wc = warp & 1;
    const int g = lane >> 2;
    const int t = lane & 3;
    const int b = blockIdx.y;
    const int row0 = blockIdx.x * 128;

    // preload all 32 per-row chunk scales
    for (int e = tid; e < 32 * 128; e += 256)
        scs[e] = d_scale[b][e >> 7][row0 + (e & 127)];

    float acc[2][9][4];
#pragma unroll
    for (int m = 0; m < 2; m++)
#pragma unroll
        for (int n = 0; n < 9; n++)
#pragma unroll
            for (int j = 0; j < 4; j++) acc[m][n][j] = 0.f;

    // LDSM lane offsets (byte offsets within buffer)
    const uint32_t pbase = smem_u32(smP);
    const uint32_t vbase0 = smem_u32(smV);
    const uint32_t aoff0 = (uint32_t)((wr * 32 + 0  + (lane & 15)) * PV_STR + ((lane >> 4) << 3)) * 2;
    const uint32_t aoff1 = (uint32_t)((wr * 32 + 16 + (lane & 15)) * PV_STR + ((lane >> 4) << 3)) * 2;
    uint32_t boffp[4];
#pragma unroll
    for (int p = 0; p < 4; p++)
        boffp[p] = (uint32_t)((wc * 72 + p * 16 + (lane & 7) + ((lane >> 4) << 3)) * PV_STR +
                              (((lane >> 3) & 1) << 3)) * 2;
    const uint32_t boffs = (uint32_t)((wc * 72 + 64 + (lane & 7)) * PV_STR +
                                      (((lane >> 3) & 1) << 3)) * 2;

    // thread's P-staging coordinates
    const int pr_r[4] = { (tid) >> 3, (tid + 256) >> 3, (tid + 512) >> 3, (tid + 768) >> 3 };
    const int pr_u = tid & 7;

    // prologue: issue V chunk 0 + load P chunk 0 into regs
    for (int e = tid; e < 144 * 8; e += 256) {
        const int f = e >> 3, u = e & 7;
        cp_async16(vbase0 + (uint32_t)(f * PV_STR + u * 8) * 2, &d_vth[b][f][0 + u * 8]);
    }
    CP_COMMIT();
    uint4 pr[4];
#pragma unroll
    for (int i = 0; i < 4; i++)
        pr[i] = *(const uint4*)&d_Pv[b][row0 + pr_r[i]][0 + pr_u * 8];
    __syncthreads();   // scs ready

    for (int ct = 0; ct < 64; ct++) {
        const int buf = ct & 1;
        __half* P = smP + buf * PV_P_HALFS;
        const uint32_t Pb = pbase + buf * PV_P_HALFS * 2;
        const uint32_t Vb = vbase0 + buf * PV_V_HALFS * 2;

        // stage P (scaled) into smem
        {
            const float* scrow = scs + (ct >> 1) * 128;
#pragma unroll
            for (int i = 0; i < 4; i++) {
                const __half2 hsc = __float2half2_rn(scrow[pr_r[i]]);
                uint4 p = pr[i];
                __half2* ph = (__half2*)&p;
#pragma unroll
                for (int j = 0; j < 4; j++) ph[j] = __hmul2(ph[j], hsc);
                *(uint4*)&P[pr_r[i] * PV_STR + pr_u * 8] = p;
            }
        }
        CP_WAIT(0);          // V[buf] arrived
        __syncthreads();

        if (ct < 63) {
            const uint32_t vb1 = vbase0 + (buf ^ 1) * PV_V_HALFS * 2;
            const int k1 = (ct + 1) * 64;
            for (int e = tid; e < 144 * 8; e += 256) {
                const int f = e >> 3, u = e & 7;
                cp_async16(vb1 + (uint32_t)(f * PV_STR + u * 8) * 2, &d_vth[b][f][k1 + u * 8]);
            }
            CP_COMMIT();
#pragma unroll
            for (int i = 0; i < 4; i++)
                pr[i] = *(const uint4*)&d_Pv[b][row0 + pr_r[i]][k1 + pr_u * 8];
        }

        // compute
#pragma unroll
        for (int k16 = 0; k16 < 4; k16++) {
            const uint32_t kb = (uint32_t)(k16 * 16) * 2;
            uint32_t a[2][4];
            ldsm_x4(a[0], Pb + aoff0 + kb);
            ldsm_x4(a[1], Pb + aoff1 + kb);
#pragma unroll
            for (int p = 0; p < 4; p++) {
                uint32_t bb[4];
                ldsm_x4(bb, Vb + boffp[p] + kb);
                mma16816(acc[0][2 * p],     a[0], bb[0], bb[1]);
                mma16816(acc[1][2 * p],     a[1], bb[0], bb[1]);
                mma16816(acc[0][2 * p + 1], a[0], bb[2], bb[3]);
                mma16816(acc[1][2 * p + 1], a[1], bb[2], bb[3]);
            }
            {
                uint32_t bs[2];
                ldsm_x2(bs, Vb + boffs + kb);
                mma16816(acc[0][8], a[0], bs[0], bs[1]);
                mma16816(acc[1][8], a[1], bs[0], bs[1]);
            }
        }
        __syncthreads();
    }

    // normalize + store zi
#pragma unroll
    for (int m = 0; m < 2; m++) {
        const int row = row0 + wr * 32 + m * 16 + g;
        const float li0 = d_linv[b][row];
        const float li1 = d_linv[b][row + 8];
#pragma unroll
        for (int n = 0; n < 9; n++) {
            const int col = wc * 72 + n * 8 + t * 2;
            *(float2*)&d_zi[b][row][col]     = make_float2(acc[m][n][0] * li0, acc[m][n][1] * li0);
            *(float2*)&d_zi[b][row + 8][col] = make_float2(acc[m][n][2] * li1, acc[m][n][3] * li1);
        }
    }
}

// ============================================================
// Kernel 6: fold (overlap-add + count normalize) + W_w conv -> yvec
// ============================================================
__global__ void k_fold(const float* __restrict__ Wmat, const float* __restrict__ Wb) {
    __shared__ float zs[IC_][W_];
    __shared__ float wsm[C_ * IC_];
    __shared__ float bsm[C_];
    const int x = threadIdx.x;
    const int y = blockIdx.x, b = blockIdx.y;
    for (int i = x; i < C_ * IC_; i += 128) wsm[i] = Wmat[i];
    if (x < C_) bsm[x] = Wb[x];

    float v[IC_];
#pragma unroll
    for (int ic = 0; ic < IC_; ic++) v[ic] = 0.f;
    int cnt = 0;
#pragma unroll
    for (int i = 0; i < 3; i++) {
        const int tY = y + 1 - i;
        if (tY < 0 || (tY & 1) || (tY >> 1) >= HP_) continue;
        const int hp = tY >> 1;
#pragma unroll
        for (int j = 0; j < 3; j++) {
            const int tX = x + 1 - j;
            if (tX < 0 || (tX & 1) || (tX >> 1) >= HP_) continue;
            const int wp = tX >> 1;
            const float* zrow = &d_zi[b][hp * 64 + wp][0];
            cnt++;
#pragma unroll
            for (int ic = 0; ic < IC_; ic++) v[ic] += zrow[ic * 9 + i * 3 + j];
        }
    }
    const float invc = 1.0f / (float)cnt;
#pragma unroll
    for (int ic = 0; ic < IC_; ic++) zs[ic][x] = v[ic] * invc;
    __syncthreads();

    for (int o = 0; o < C_; o++) {
        float a = bsm[o];
#pragma unroll
        for (int ic = 0; ic < IC_; ic++) a += wsm[o * IC_ + ic] * zs[ic][x];
        d_yvec[b][o][y][x] = a;
    }
}

// ============================================================
// Kernel 7: out = s + yvec (broadcast over D)
// ============================================================
__global__ void k_out(const float* __restrict__ s, float* __restrict__ out) {
    const int idx = blockIdx.x * 256 + threadIdx.x;
    const int pix = idx & (H_ * W_ - 1);
    const int bo = (idx >> 14) >> 3;  // b*64 + o
    out[idx] = s[idx] + (&d_yvec[0][0][0][0])[bo * (H_ * W_) + pix];
}

// ============================================================
extern "C" void kernel_launch(void* const* d_in, const int* /*in_sizes*/, int /*n_in*/,
                              void* d_out, int /*out_size*/) {
    const float* s   = (const float*)d_in[0];
    const float* g   = (const float*)d_in[1];
    const float* g_w = (const float*)d_in[2];
    const float* g_b = (const float*)d_in[3];
    const float* t_w = (const float*)d_in[4];
    const float* t_b = (const float*)d_in[5];
    const float* p_w = (const float*)d_in[6];
    const float* p_b = (const float*)d_in[7];
    const float* W_w = (const float*)d_in[8];
    const float* W_b = (const float*)d_in[9];
    float* out = (float*)d_out;

    cudaFuncSetAttribute(k_gemmS,  cudaFuncAttributeMaxDynamicSharedMemorySize, SGEMM_SMEM_BYTES);
    cudaFuncSetAttribute(k_gemmPV, cudaFuncAttributeMaxDynamicSharedMemorySize, PV_SMEM_BYTES);

    k_conv<<<dim3(H_, B_), 128>>>(s, g, g_w, g_b, t_w, t_b, p_w, p_b);
    k_patch_qk<<<(B_ * L_ * F_) / 256, 256>>>();
    k_patch_v<<<(B_ * F_ * L_) / 256, 256>>>();

    k_gemmS<<<dim3(32, 32, B_), 512, SGEMM_SMEM_BYTES>>>();
    k_reduce<<<(B_ * L_) / 256, 256>>>();
    k_gemmPV<<<dim3(32, B_), 256, PV_SMEM_BYTES>>>();

    k_fold<<<dim3(H_, B_), 128>>>(W_w, W_b);
    k_out<<<(B_ * C_ * D_ * H_ * W_) / 256, 256>>>(s, out);
}

// round 7
// speedup vs baseline: 2.9493x; 1.0344x over previous
#include <cuda_runtime.h>
#include <cuda_fp16.h>
#include <cstdint>

namespace {
constexpr int B_  = 4;
constexpr int C_  = 64;
constexpr int IC_ = 16;
constexpr int D_  = 8;
constexpr int H_  = 128;
constexpr int W_  = 128;
constexpr int MID_ = 4;
constexpr int HP_ = 64;
constexpr int L_  = 4096;
constexpr int F_  = 144;   // IC*3*3 = 9 * 16
constexpr int NCB_ = 64;   // number of 64-col chunks
constexpr float SCALE_ = 10.0f;

// S-GEMM smem (halfs): Q resident + K double-buffered
constexpr int SQ_STR = 152;                    // 144 + 8 pad
constexpr int SQH_OFF = 0;                     // 128*152
constexpr int SQL_OFF = 128 * SQ_STR;          // 19456
constexpr int SK_BASE = 2 * 128 * SQ_STR;      // 38912
constexpr int SK_HALFS = 64 * SQ_STR;          // 9728 (one hi or lo chunk)
// K offset: SK_BASE + buf*(2*SK_HALFS) + hilo*SK_HALFS
constexpr int SGEMM_SMEM_BYTES = (SK_BASE + 4 * SK_HALFS) * 2;  // 155648

// PV-GEMM smem layout (bytes)
constexpr int PV_STR = 72;
constexpr int PV_SCS_BYTES = NCB_ * 128 * 4;               // 32768
constexpr int PV_P_HALFS = 128 * PV_STR;                   // 9216
constexpr int PV_V_HALFS = 144 * PV_STR;                   // 10368
constexpr int PV_P_OFF = PV_SCS_BYTES;
constexpr int PV_V_OFF = PV_P_OFF + 2 * PV_P_HALFS * 2;
constexpr int PV_SMEM_BYTES = PV_V_OFF + 2 * PV_V_HALFS * 2;  // 111104
}

// ============================================================
// helpers
// ============================================================
__device__ __forceinline__ void mma16816(float* c, const uint32_t* a,
                                         uint32_t b0, uint32_t b1) {
    asm volatile(
        "mma.sync.aligned.m16n8k16.row.col.f32.f16.f16.f32 "
        "{%0,%1,%2,%3}, {%4,%5,%6,%7}, {%8,%9}, {%0,%1,%2,%3};"
        : "+f"(c[0]), "+f"(c[1]), "+f"(c[2]), "+f"(c[3])
        : "r"(a[0]), "r"(a[1]), "r"(a[2]), "r"(a[3]), "r"(b0), "r"(b1));
}

__device__ __forceinline__ void ldsm_x4(uint32_t* r, uint32_t smaddr) {
    asm volatile("ldmatrix.sync.aligned.m8n8.x4.shared.b16 {%0,%1,%2,%3}, [%4];"
                 : "=r"(r[0]), "=r"(r[1]), "=r"(r[2]), "=r"(r[3]) : "r"(smaddr));
}
__device__ __forceinline__ void ldsm_x2(uint32_t* r, uint32_t smaddr) {
    asm volatile("ldmatrix.sync.aligned.m8n8.x2.shared.b16 {%0,%1}, [%2];"
                 : "=r"(r[0]), "=r"(r[1]) : "r"(smaddr));
}

__device__ __forceinline__ void cp_async16(uint32_t smaddr, const void* gptr) {
    asm volatile("cp.async.cg.shared.global [%0], [%1], 16;"
                 :: "r"(smaddr), "l"(gptr) : "memory");
}
#define CP_COMMIT() asm volatile("cp.async.commit_group;" ::: "memory")
#define CP_WAIT(n)  asm volatile("cp.async.wait_group %0;" :: "n"(n) : "memory")

__device__ __forceinline__ uint32_t smem_u32(const void* p) {
    uint32_t a;
    asm("{ .reg .u64 t; cvta.to.shared.u64 t, %1; cvt.u32.u64 %0, t; }" : "=r"(a) : "l"(p));
    return a;
}

__device__ __forceinline__ void split16(float x, __half& h, __half& l) {
    h = __float2half_rn(x);
    l = __float2half_rn(x - __half2float(h));
}

// ============================================================
// scratch (device globals)
// ============================================================
__device__ float d_conv[3][B_][IC_][H_][W_];
__device__ __align__(16) __half d_qh[B_][L_][F_];
__device__ __align__(16) __half d_ql[B_][L_][F_];
__device__ __align__(16) __half d_kh[B_][L_][F_];
__device__ __align__(16) __half d_kl[B_][L_][F_];
__device__ __align__(16) __half d_vth[B_][F_][L_];
__device__ __align__(16) __half d_Pv[B_][L_][L_];     // exp(S - m_chunk), fp16
__device__ float d_mc[B_][NCB_][L_];
__device__ float d_lc[B_][NCB_][L_];
__device__ float d_scale[B_][NCB_][L_];
__device__ float d_linv[B_][L_];
__device__ float d_zi[B_][L_][F_];
__device__ float d_yvec[B_][C_][H_][W_];

// ============================================================
// Kernel 1: 1x1 convs at the mid depth slice only.
// ============================================================
__global__ void k_conv(const float* __restrict__ s, const float* __restrict__ g,
                       const float* __restrict__ gw, const float* __restrict__ gb,
                       const float* __restrict__ tw, const float* __restrict__ tb,
                       const float* __restrict__ pw, const float* __restrict__ pb) {
    __shared__ float wq[IC_ * C_], wv[IC_ * C_], wk[IC_ * C_];
    __shared__ float bq[IC_], bv[IC_], bk[IC_];
    const int tid = threadIdx.x;
    for (int i = tid; i < IC_ * C_; i += 128) { wq[i] = gw[i]; wv[i] = tw[i]; wk[i] = pw[i]; }
    if (tid < IC_) { bq[tid] = gb[tid]; bv[tid] = tb[tid]; bk[tid] = pb[tid]; }
    __syncthreads();

    const int y = blockIdx.x, b = blockIdx.y, x = tid;
    float aq[IC_], av[IC_], ak[IC_];
#pragma unroll
    for (int ic = 0; ic < IC_; ic++) { aq[ic] = bq[ic]; av[ic] = bv[ic]; ak[ic] = bk[ic]; }

    const size_t base = ((size_t)b * C_ * D_ + MID_) * (H_ * W_) + (size_t)y * W_ + x;
    const size_t cstride = (size_t)D_ * H_ * W_;
#pragma unroll 4
    for (int c = 0; c < C_; c++) {
        const float sv = s[base + c * cstride];
        const float gv = g[base + c * cstride];
#pragma unroll
        for (int ic = 0; ic < IC_; ic++) {
            aq[ic] += wq[ic * C_ + c] * sv;
            av[ic] += wv[ic * C_ + c] * gv;
            ak[ic] += wk[ic * C_ + c] * gv;
        }
    }
#pragma unroll
    for (int ic = 0; ic < IC_; ic++) {
        const int o = ((b * IC_ + ic) * H_ + y) * W_ + x;
        (&d_conv[0][0][0][0][0])[o] = aq[ic];
        (&d_conv[1][0][0][0][0])[o] = av[ic];
        (&d_conv[2][0][0][0][0])[o] = ak[ic];
    }
}

// ============================================================
// Kernel 2a: patches -> q (pre-scaled by 10) and k, fp16 hi/lo split.
// ============================================================
__global__ void k_patch_qk() {
    const int idx = blockIdx.x * 256 + threadIdx.x;
    const int f = idx % F_;
    const int t = idx / F_;
    const int l = t & (L_ - 1);
    const int b = t >> 12;
    const int c = f / 9;
    const int r = f - c * 9;
    const int ki = r / 3, kj = r - (r / 3) * 3;
    const int hp = l >> 6, wp = l & 63;
    const int y = hp * 2 - 1 + ki;
    const int x = wp * 2 - 1 + kj;
    const bool in = ((unsigned)y < (unsigned)H_) && ((unsigned)x < (unsigned)W_);
    float q = in ? d_conv[0][b][c][y][x] : 0.0f;
    float k = in ? d_conv[2][b][c][y][x] : 0.0f;
    q *= SCALE_;
    __half qh, ql, kh, kl;
    split16(q, qh, ql);
    split16(k, kh, kl);
    d_qh[b][l][f] = qh; d_ql[b][l][f] = ql;
    d_kh[b][l][f] = kh; d_kl[b][l][f] = kl;
}

// ============================================================
// Kernel 2b: patches -> V transposed [b][f][l], fp16.
// ============================================================
__global__ void k_patch_v() {
    const int idx = blockIdx.x * 256 + threadIdx.x;
    const int b = idx / (F_ * L_);
    const int rem = idx - b * (F_ * L_);
    const int f = rem / L_;
    const int l = rem - f * L_;
    const int c = f / 9;
    const int r = f - c * 9;
    const int ki = r / 3, kj = r - (r / 3) * 3;
    const int hp = l >> 6, wp = l & 63;
    const int y = hp * 2 - 1 + ki;
    const int x = wp * 2 - 1 + kj;
    const bool in = ((unsigned)y < (unsigned)H_) && ((unsigned)x < (unsigned)W_);
    const float v = in ? d_conv[1][b][c][y][x] : 0.0f;
    d_vth[b][f][l] = __float2half_rn(v);
}

// ============================================================
// Kernel 3: persistent S = (10 Q) K^T + fused chunk softmax.
// grid (32 row-tiles, B) = 128 CTAs. 512 threads = 16 warps (4 wr x 4 wc),
// warp tile 32x16. Q hi/lo resident; K 64-col chunks double-buffered.
// ============================================================
__global__ __launch_bounds__(512, 1) void k_gemmS() {
    extern __shared__ __half smh[];
    __shared__ float redbuf[4][128];
    __shared__ float mfin[128];

    const int tid = threadIdx.x;
    const int lane = tid & 31;
    const int warp = tid >> 5;
    const int wr = warp >> 2;           // 0..3 (rows)
    const int wc = warp & 3;            // 0..3 (16-col groups)
    const int g = lane >> 2;            // 0..7
    const int t = lane & 3;             // 0..3
    const int b = blockIdx.y;
    const int row0 = blockIdx.x * 128;

    const uint32_t sbase = smem_u32(smh);

    // prologue: Q hi/lo (resident) + K chunk 0, one cp.async group
    for (int e = tid; e < 128 * 18; e += 512) {
        const int r = e / 18, u = e - (e / 18) * 18;
        const uint32_t so = (uint32_t)(r * SQ_STR + u * 8) * 2;
        cp_async16(sbase + SQH_OFF * 2 + so, &d_qh[b][row0 + r][u * 8]);
        cp_async16(sbase + SQL_OFF * 2 + so, &d_ql[b][row0 + r][u * 8]);
    }
    for (int e = tid; e < 64 * 18; e += 512) {
        const int r = e / 18, u = e - (e / 18) * 18;
        const uint32_t so = (uint32_t)(r * SQ_STR + u * 8) * 2;
        cp_async16(sbase + SK_BASE * 2 + so, &d_kh[b][r][u * 8]);
        cp_async16(sbase + (SK_BASE + SK_HALFS) * 2 + so, &d_kl[b][r][u * 8]);
    }
    CP_COMMIT();

    // LDSM lane offsets
    const uint32_t aoff0 = (uint32_t)((wr * 32 + 0  + (lane & 15)) * SQ_STR + ((lane >> 4) << 3)) * 2;
    const uint32_t aoff1 = (uint32_t)((wr * 32 + 16 + (lane & 15)) * SQ_STR + ((lane >> 4) << 3)) * 2;
    const uint32_t boff  = (uint32_t)((wc * 16 + (lane & 7) + ((lane >> 4) << 3)) * SQ_STR +
                                      (((lane >> 3) & 1) << 3)) * 2;

    for (int ct = 0; ct < NCB_; ct++) {
        const int buf = ct & 1;
        const int col0 = ct * 64;

        // issue next K chunk into other buffer
        if (ct < NCB_ - 1) {
            const uint32_t kb1 = sbase + (SK_BASE + (buf ^ 1) * 2 * SK_HALFS) * 2;
            const int c1 = (ct + 1) * 64;
            for (int e = tid; e < 64 * 18; e += 512) {
                const int r = e / 18, u = e - (e / 18) * 18;
                const uint32_t so = (uint32_t)(r * SQ_STR + u * 8) * 2;
                cp_async16(kb1 + so, &d_kh[b][c1 + r][u * 8]);
                cp_async16(kb1 + SK_HALFS * 2 + so, &d_kl[b][c1 + r][u * 8]);
            }
            CP_COMMIT();
            CP_WAIT(1);
        } else {
            CP_WAIT(0);
        }
        __syncthreads();

        const uint32_t KHb = sbase + (SK_BASE + buf * 2 * SK_HALFS) * 2;
        const uint32_t KLb = KHb + SK_HALFS * 2;

        float acc[2][2][4];
#pragma unroll
        for (int m = 0; m < 2; m++)
#pragma unroll
            for (int n = 0; n < 2; n++)
#pragma unroll
                for (int j = 0; j < 4; j++) acc[m][n][j] = 0.f;

#pragma unroll
        for (int sp = 0; sp < 3; sp++) {
            const uint32_t Ab = sbase + ((sp == 2) ? SQL_OFF : SQH_OFF) * 2;
            const uint32_t Bb = (sp == 1) ? KLb : KHb;
#pragma unroll
            for (int k16 = 0; k16 < 9; k16++) {
                const uint32_t kb = (uint32_t)(k16 * 16) * 2;
                uint32_t a[2][4], bb[4];
                ldsm_x4(a[0], Ab + aoff0 + kb);
                ldsm_x4(a[1], Ab + aoff1 + kb);
                ldsm_x4(bb, Bb + boff + kb);
                mma16816(acc[0][0], a[0], bb[0], bb[1]);
                mma16816(acc[1][0], a[1], bb[0], bb[1]);
                mma16816(acc[0][1], a[0], bb[2], bb[3]);
                mma16816(acc[1][1], a[1], bb[2], bb[3]);
            }
        }

        // ---- fused chunk softmax (rows R[ri] = wr*32 + (ri>>1)*16 + (ri&1)*8 + g) ----
        float rmax[4];
#pragma unroll
        for (int ri = 0; ri < 4; ri++) {
            const int m = ri >> 1, jb = (ri & 1) * 2;
            rmax[ri] = fmaxf(fmaxf(acc[m][0][jb], acc[m][0][jb + 1]),
                             fmaxf(acc[m][1][jb], acc[m][1][jb + 1]));
        }
#pragma unroll
        for (int off = 1; off <= 2; off <<= 1)
#pragma unroll
            for (int ri = 0; ri < 4; ri++)
                rmax[ri] = fmaxf(rmax[ri], __shfl_xor_sync(0xffffffffu, rmax[ri], off));
        if (t == 0) {
#pragma unroll
            for (int ri = 0; ri < 4; ri++)
                redbuf[wc][wr * 32 + (ri >> 1) * 16 + (ri & 1) * 8 + g] = rmax[ri];
        }
        __syncthreads();
        if (tid < 128)
            mfin[tid] = fmaxf(fmaxf(redbuf[0][tid], redbuf[1][tid]),
                              fmaxf(redbuf[2][tid], redbuf[3][tid]));
        __syncthreads();

        float rsum[4];
#pragma unroll
        for (int ri = 0; ri < 4; ri++) {
            const int m = ri >> 1, jb = (ri & 1) * 2;
            const int row = wr * 32 + (ri >> 1) * 16 + (ri & 1) * 8 + g;
            const float mx = mfin[row];
            float sum = 0.f;
#pragma unroll
            for (int n = 0; n < 2; n++) {
                const float e0 = __expf(acc[m][n][jb] - mx);
                const float e1 = __expf(acc[m][n][jb + 1] - mx);
                sum += e0 + e1;
                *(__half2*)&d_Pv[b][row0 + row][col0 + wc * 16 + n * 8 + t * 2] =
                    __floats2half2_rn(e0, e1);
            }
            rsum[ri] = sum;
        }
#pragma unroll
        for (int off = 1; off <= 2; off <<= 1)
#pragma unroll
            for (int ri = 0; ri < 4; ri++)
                rsum[ri] += __shfl_xor_sync(0xffffffffu, rsum[ri], off);
        if (t == 0) {
#pragma unroll
            for (int ri = 0; ri < 4; ri++)
                redbuf[wc][wr * 32 + (ri >> 1) * 16 + (ri & 1) * 8 + g] = rsum[ri];
        }
        __syncthreads();
        if (tid < 128) {
            d_mc[b][ct][row0 + tid] = mfin[tid];
            d_lc[b][ct][row0 + tid] = redbuf[0][tid] + redbuf[1][tid] +
                                      redbuf[2][tid] + redbuf[3][tid];
        }
        __syncthreads();
    }
}

// ============================================================
// Kernel 4: per-row reduction: final max, chunk scales, 1/l.
// ============================================================
__global__ void k_reduce() {
    const int idx = blockIdx.x * 256 + threadIdx.x;   // b*4096 + r
    const int b = idx >> 12, r = idx & 4095;
    float m = -1e30f;
#pragma unroll 8
    for (int c = 0; c < NCB_; c++) m = fmaxf(m, d_mc[b][c][r]);
    float l = 0.0f;
#pragma unroll 8
    for (int c = 0; c < NCB_; c++) {
        const float sc = __expf(d_mc[b][c][r] - m);
        d_scale[b][c][r] = sc;
        l += sc * d_lc[b][c][r];
    }
    d_linv[b][r] = 1.0f / l;
}

// ============================================================
// Kernel 5: zi = (P_scaled / l) V, fp16 HMMA + LDSM, double-buffered V.
// grid (32 row-tiles, B), 256 threads = 8 warps (4 wr x 2 wc), warp 32x72.
// ============================================================
__global__ __launch_bounds__(256, 1) void k_gemmPV() {
    extern __shared__ char smc[];
    float* scs = (float*)smc;                      // [64 cb][128 rows]
    __half* smP = (__half*)(smc + PV_P_OFF);       // [2][128*72]
    __half* smV = (__half*)(smc + PV_V_OFF);       // [2][144*72]

    const int tid = threadIdx.x;
    const int lane = tid & 31;
    const int warp = tid >> 5;
    const int wr = warp >> 1;
    const int wc = warp & 1;
    const int g = lane >> 2;
    const int t = lane & 3;
    const int b = blockIdx.y;
    const int row0 = blockIdx.x * 128;

    // preload all 64 per-row chunk scales
    for (int e = tid; e < NCB_ * 128; e += 256)
        scs[e] = d_scale[b][e >> 7][row0 + (e & 127)];

    float acc[2][9][4];
#pragma unroll
    for (int m = 0; m < 2; m++)
#pragma unroll
        for (int n = 0; n < 9; n++)
#pragma unroll
            for (int j = 0; j < 4; j++) acc[m][n][j] = 0.f;

    const uint32_t pbase = smem_u32(smP);
    const uint32_t vbase0 = smem_u32(smV);
    const uint32_t aoff0 = (uint32_t)((wr * 32 + 0  + (lane & 15)) * PV_STR + ((lane >> 4) << 3)) * 2;
    const uint32_t aoff1 = (uint32_t)((wr * 32 + 16 + (lane & 15)) * PV_STR + ((lane >> 4) << 3)) * 2;
    uint32_t boffp[4];
#pragma unroll
    for (int p = 0; p < 4; p++)
        boffp[p] = (uint32_t)((wc * 72 + p * 16 + (lane & 7) + ((lane >> 4) << 3)) * PV_STR +
                              (((lane >> 3) & 1) << 3)) * 2;
    const uint32_t boffs = (uint32_t)((wc * 72 + 64 + (lane & 7)) * PV_STR +
                                      (((lane >> 3) & 1) << 3)) * 2;

    const int pr_r[4] = { (tid) >> 3, (tid + 256) >> 3, (tid + 512) >> 3, (tid + 768) >> 3 };
    const int pr_u = tid & 7;

    // prologue: issue V chunk 0 + load P chunk 0 into regs
    for (int e = tid; e < 144 * 8; e += 256) {
        const int f = e >> 3, u = e & 7;
        cp_async16(vbase0 + (uint32_t)(f * PV_STR + u * 8) * 2, &d_vth[b][f][0 + u * 8]);
    }
    CP_COMMIT();
    uint4 pr[4];
#pragma unroll
    for (int i = 0; i < 4; i++)
        pr[i] = *(const uint4*)&d_Pv[b][row0 + pr_r[i]][0 + pr_u * 8];
    __syncthreads();   // scs ready

    for (int ct = 0; ct < 64; ct++) {
        const int buf = ct & 1;
        __half* P = smP + buf * PV_P_HALFS;
        const uint32_t Pb = pbase + buf * PV_P_HALFS * 2;
        const uint32_t Vb = vbase0 + buf * PV_V_HALFS * 2;

        // stage P (scaled) into smem
        {
            const float* scrow = scs + ct * 128;
#pragma unroll
            for (int i = 0; i < 4; i++) {
                const __half2 hsc = __float2half2_rn(scrow[pr_r[i]]);
                uint4 p = pr[i];
                __half2* ph = (__half2*)&p;
#pragma unroll
                for (int j = 0; j < 4; j++) ph[j] = __hmul2(ph[j], hsc);
                *(uint4*)&P[pr_r[i] * PV_STR + pr_u * 8] = p;
            }
        }
        CP_WAIT(0);          // V[buf] arrived
        __syncthreads();

        if (ct < 63) {
            const uint32_t vb1 = vbase0 + (buf ^ 1) * PV_V_HALFS * 2;
            const int k1 = (ct + 1) * 64;
            for (int e = tid; e < 144 * 8; e += 256) {
                const int f = e >> 3, u = e & 7;
                cp_async16(vb1 + (uint32_t)(f * PV_STR + u * 8) * 2, &d_vth[b][f][k1 + u * 8]);
            }
            CP_COMMIT();
#pragma unroll
            for (int i = 0; i < 4; i++)
                pr[i] = *(const uint4*)&d_Pv[b][row0 + pr_r[i]][k1 + pr_u * 8];
        }

        // compute
#pragma unroll
        for (int k16 = 0; k16 < 4; k16++) {
            const uint32_t kb = (uint32_t)(k16 * 16) * 2;
            uint32_t a[2][4];
            ldsm_x4(a[0], Pb + aoff0 + kb);
            ldsm_x4(a[1], Pb + aoff1 + kb);
#pragma unroll
            for (int p = 0; p < 4; p++) {
                uint32_t bb[4];
                ldsm_x4(bb, Vb + boffp[p] + kb);
                mma16816(acc[0][2 * p],     a[0], bb[0], bb[1]);
                mma16816(acc[1][2 * p],     a[1], bb[0], bb[1]);
                mma16816(acc[0][2 * p + 1], a[0], bb[2], bb[3]);
                mma16816(acc[1][2 * p + 1], a[1], bb[2], bb[3]);
            }
            {
                uint32_t bs[2];
                ldsm_x2(bs, Vb + boffs + kb);
                mma16816(acc[0][8], a[0], bs[0], bs[1]);
                mma16816(acc[1][8], a[1], bs[0], bs[1]);
            }
        }
        __syncthreads();
    }

    // normalize + store zi
#pragma unroll
    for (int m = 0; m < 2; m++) {
        const int row = row0 + wr * 32 + m * 16 + g;
        const float li0 = d_linv[b][row];
        const float li1 = d_linv[b][row + 8];
#pragma unroll
        for (int n = 0; n < 9; n++) {
            const int col = wc * 72 + n * 8 + t * 2;
            *(float2*)&d_zi[b][row][col]     = make_float2(acc[m][n][0] * li0, acc[m][n][1] * li0);
            *(float2*)&d_zi[b][row + 8][col] = make_float2(acc[m][n][2] * li1, acc[m][n][3] * li1);
        }
    }
}

// ============================================================
// Kernel 6: fold (overlap-add + count normalize) + W_w conv -> yvec
// ============================================================
__global__ void k_fold(const float* __restrict__ Wmat, const float* __restrict__ Wb) {
    __shared__ float zs[IC_][W_];
    __shared__ float wsm[C_ * IC_];
    __shared__ float bsm[C_];
    const int x = threadIdx.x;
    const int y = blockIdx.x, b = blockIdx.y;
    for (int i = x; i < C_ * IC_; i += 128) wsm[i] = Wmat[i];
    if (x < C_) bsm[x] = Wb[x];

    float v[IC_];
#pragma unroll
    for (int ic = 0; ic < IC_; ic++) v[ic] = 0.f;
    int cnt = 0;
#pragma unroll
    for (int i = 0; i < 3; i++) {
        const int tY = y + 1 - i;
        if (tY < 0 || (tY & 1) || (tY >> 1) >= HP_) continue;
        const int hp = tY >> 1;
#pragma unroll
        for (int j = 0; j < 3; j++) {
            const int tX = x + 1 - j;
            if (tX < 0 || (tX & 1) || (tX >> 1) >= HP_) continue;
            const int wp = tX >> 1;
            const float* zrow = &d_zi[b][hp * 64 + wp][0];
            cnt++;
#pragma unroll
            for (int ic = 0; ic < IC_; ic++) v[ic] += zrow[ic * 9 + i * 3 + j];
        }
    }
    const float invc = 1.0f / (float)cnt;
#pragma unroll
    for (int ic = 0; ic < IC_; ic++) zs[ic][x] = v[ic] * invc;
    __syncthreads();

    for (int o = 0; o < C_; o++) {
        float a = bsm[o];
#pragma unroll
        for (int ic = 0; ic < IC_; ic++) a += wsm[o * IC_ + ic] * zs[ic][x];
        d_yvec[b][o][y][x] = a;
    }
}

// ============================================================
// Kernel 7: out = s + yvec (broadcast over D)
// ============================================================
__global__ void k_out(const float* __restrict__ s, float* __restrict__ out) {
    const int idx = blockIdx.x * 256 + threadIdx.x;
    const int pix = idx & (H_ * W_ - 1);
    const int bo = (idx >> 14) >> 3;  // b*64 + o
    out[idx] = s[idx] + (&d_yvec[0][0][0][0])[bo * (H_ * W_) + pix];
}

// ============================================================
extern "C" void kernel_launch(void* const* d_in, const int* /*in_sizes*/, int /*n_in*/,
                              void* d_out, int /*out_size*/) {
    const float* s   = (const float*)d_in[0];
    const float* g   = (const float*)d_in[1];
    const float* g_w = (const float*)d_in[2];
    const float* g_b = (const float*)d_in[3];
    const float* t_w = (const float*)d_in[4];
    const float* t_b = (const float*)d_in[5];
    const float* p_w = (const float*)d_in[6];
    const float* p_b = (const float*)d_in[7];
    const float* W_w = (const float*)d_in[8];
    const float* W_b = (const float*)d_in[9];
    float* out = (float*)d_out;

    cudaFuncSetAttribute(k_gemmS,  cudaFuncAttributeMaxDynamicSharedMemorySize, SGEMM_SMEM_BYTES);
    cudaFuncSetAttribute(k_gemmPV, cudaFuncAttributeMaxDynamicSharedMemorySize, PV_SMEM_BYTES);

    k_conv<<<dim3(H_, B_), 128>>>(s, g, g_w, g_b, t_w, t_b, p_w, p_b);
    k_patch_qk<<<(B_ * L_ * F_) / 256, 256>>>();
    k_patch_v<<<(B_ * F_ * L_) / 256, 256>>>();

    k_gemmS<<<dim3(32, B_), 512, SGEMM_SMEM_BYTES>>>();
    k_reduce<<<(B_ * L_) / 256, 256>>>();
    k_gemmPV<<<dim3(32, B_), 256, PV_SMEM_BYTES>>>();

    k_fold<<<dim3(H_, B_), 128>>>(W_w, W_b);
    k_out<<<(B_ * C_ * D_ * H_ * W_) / 256, 256>>>(s, out);
}

// round 8
// speedup vs baseline: 3.1014x; 1.0515x over previous
#include <cuda_runtime.h>
#include <cuda_fp16.h>
#include <cstdint>

namespace {
constexpr int B_  = 4;
constexpr int C_  = 64;
constexpr int IC_ = 16;
constexpr int D_  = 8;
constexpr int H_  = 128;
constexpr int W_  = 128;
constexpr int MID_ = 4;
constexpr int HP_ = 64;
constexpr int L_  = 4096;
constexpr int F_  = 144;   // IC*3*3 = 9 * 16
constexpr int NCB_ = 64;   // number of 64-col chunks
constexpr float SCALE_ = 10.0f;

// S-GEMM smem (halfs): Q resident + K double-buffered
constexpr int SQ_STR = 152;                    // 144 + 8 pad
constexpr int SQH_OFF = 0;
constexpr int SQL_OFF = 128 * SQ_STR;
constexpr int SK_BASE = 2 * 128 * SQ_STR;
constexpr int SK_HALFS = 64 * SQ_STR;
constexpr int SGEMM_SMEM_BYTES = (SK_BASE + 4 * SK_HALFS) * 2;  // 155648

// PV-GEMM smem layout (bytes)
constexpr int PV_STR = 72;
constexpr int PV_SCS_BYTES = NCB_ * 128 * 4;               // 32768
constexpr int PV_P_HALFS = 128 * PV_STR;                   // 9216
constexpr int PV_V_HALFS = 144 * PV_STR;                   // 10368
constexpr int PV_P_OFF = PV_SCS_BYTES;
constexpr int PV_V_OFF = PV_P_OFF + 2 * PV_P_HALFS * 2;
constexpr int PV_SMEM_BYTES = PV_V_OFF + 2 * PV_V_HALFS * 2;  // 111104
}

// ============================================================
// helpers
// ============================================================
__device__ __forceinline__ void mma16816(float* c, const uint32_t* a,
                                         uint32_t b0, uint32_t b1) {
    asm volatile(
        "mma.sync.aligned.m16n8k16.row.col.f32.f16.f16.f32 "
        "{%0,%1,%2,%3}, {%4,%5,%6,%7}, {%8,%9}, {%0,%1,%2,%3};"
        : "+f"(c[0]), "+f"(c[1]), "+f"(c[2]), "+f"(c[3])
        : "r"(a[0]), "r"(a[1]), "r"(a[2]), "r"(a[3]), "r"(b0), "r"(b1));
}

__device__ __forceinline__ void ldsm_x4(uint32_t* r, uint32_t smaddr) {
    asm volatile("ldmatrix.sync.aligned.m8n8.x4.shared.b16 {%0,%1,%2,%3}, [%4];"
                 : "=r"(r[0]), "=r"(r[1]), "=r"(r[2]), "=r"(r[3]) : "r"(smaddr));
}
__device__ __forceinline__ void ldsm_x2(uint32_t* r, uint32_t smaddr) {
    asm volatile("ldmatrix.sync.aligned.m8n8.x2.shared.b16 {%0,%1}, [%2];"
                 : "=r"(r[0]), "=r"(r[1]) : "r"(smaddr));
}

__device__ __forceinline__ void cp_async16(uint32_t smaddr, const void* gptr) {
    asm volatile("cp.async.cg.shared.global [%0], [%1], 16;"
                 :: "r"(smaddr), "l"(gptr) : "memory");
}
#define CP_COMMIT() asm volatile("cp.async.commit_group;" ::: "memory")
#define CP_WAIT(n)  asm volatile("cp.async.wait_group %0;" :: "n"(n) : "memory")

__device__ __forceinline__ uint32_t smem_u32(const void* p) {
    uint32_t a;
    asm("{ .reg .u64 t; cvta.to.shared.u64 t, %1; cvt.u32.u64 %0, t; }" : "=r"(a) : "l"(p));
    return a;
}

__device__ __forceinline__ void split16(float x, __half& h, __half& l) {
    h = __float2half_rn(x);
    l = __float2half_rn(x - __half2float(h));
}

// ============================================================
// scratch (device globals)
// ============================================================
__device__ float d_conv[3][B_][IC_][H_][W_];
__device__ __align__(16) __half d_qh[B_][L_][F_];
__device__ __align__(16) __half d_ql[B_][L_][F_];
__device__ __align__(16) __half d_kh[B_][L_][F_];
__device__ __align__(16) __half d_kl[B_][L_][F_];
__device__ __align__(16) __half d_vth[B_][F_][L_];
__device__ __align__(16) __half d_Pv[B_][L_][L_];     // exp(S - m_chunk), fp16
__device__ float d_mc[B_][NCB_][L_];
__device__ float d_lc[B_][NCB_][L_];
__device__ float d_scale[B_][NCB_][L_];
__device__ float d_linv[B_][L_];
__device__ float d_zi[B_][L_][F_];
__device__ float d_yvec[B_][C_][H_][W_];

// ============================================================
// Kernel 1: 1x1 convs at the mid depth slice only.
// ============================================================
__global__ void k_conv(const float* __restrict__ s, const float* __restrict__ g,
                       const float* __restrict__ gw, const float* __restrict__ gb,
                       const float* __restrict__ tw, const float* __restrict__ tb,
                       const float* __restrict__ pw, const float* __restrict__ pb) {
    __shared__ float wq[IC_ * C_], wv[IC_ * C_], wk[IC_ * C_];
    __shared__ float bq[IC_], bv[IC_], bk[IC_];
    const int tid = threadIdx.x;
    for (int i = tid; i < IC_ * C_; i += 128) { wq[i] = gw[i]; wv[i] = tw[i]; wk[i] = pw[i]; }
    if (tid < IC_) { bq[tid] = gb[tid]; bv[tid] = tb[tid]; bk[tid] = pb[tid]; }
    __syncthreads();

    const int y = blockIdx.x, b = blockIdx.y, x = tid;
    float aq[IC_], av[IC_], ak[IC_];
#pragma unroll
    for (int ic = 0; ic < IC_; ic++) { aq[ic] = bq[ic]; av[ic] = bv[ic]; ak[ic] = bk[ic]; }

    const size_t base = ((size_t)b * C_ * D_ + MID_) * (H_ * W_) + (size_t)y * W_ + x;
    const size_t cstride = (size_t)D_ * H_ * W_;
#pragma unroll 4
    for (int c = 0; c < C_; c++) {
        const float sv = s[base + c * cstride];
        const float gv = g[base + c * cstride];
#pragma unroll
        for (int ic = 0; ic < IC_; ic++) {
            aq[ic] += wq[ic * C_ + c] * sv;
            av[ic] += wv[ic * C_ + c] * gv;
            ak[ic] += wk[ic * C_ + c] * gv;
        }
    }
#pragma unroll
    for (int ic = 0; ic < IC_; ic++) {
        const int o = ((b * IC_ + ic) * H_ + y) * W_ + x;
        (&d_conv[0][0][0][0][0])[o] = aq[ic];
        (&d_conv[1][0][0][0][0])[o] = av[ic];
        (&d_conv[2][0][0][0][0])[o] = ak[ic];
    }
}

// ============================================================
// Kernel 2a: patches -> q (pre-scaled by 10) and k, fp16 hi/lo split.
// ============================================================
__global__ void k_patch_qk() {
    const int idx = blockIdx.x * 256 + threadIdx.x;
    const int f = idx % F_;
    const int t = idx / F_;
    const int l = t & (L_ - 1);
    const int b = t >> 12;
    const int c = f / 9;
    const int r = f - c * 9;
    const int ki = r / 3, kj = r - (r / 3) * 3;
    const int hp = l >> 6, wp = l & 63;
    const int y = hp * 2 - 1 + ki;
    const int x = wp * 2 - 1 + kj;
    const bool in = ((unsigned)y < (unsigned)H_) && ((unsigned)x < (unsigned)W_);
    float q = in ? d_conv[0][b][c][y][x] : 0.0f;
    float k = in ? d_conv[2][b][c][y][x] : 0.0f;
    q *= SCALE_;
    __half qh, ql, kh, kl;
    split16(q, qh, ql);
    split16(k, kh, kl);
    d_qh[b][l][f] = qh; d_ql[b][l][f] = ql;
    d_kh[b][l][f] = kh; d_kl[b][l][f] = kl;
}

// ============================================================
// Kernel 2b: patches -> V transposed [b][f][l], fp16.
// ============================================================
__global__ void k_patch_v() {
    const int idx = blockIdx.x * 256 + threadIdx.x;
    const int b = idx / (F_ * L_);
    const int rem = idx - b * (F_ * L_);
    const int f = rem / L_;
    const int l = rem - f * L_;
    const int c = f / 9;
    const int r = f - c * 9;
    const int ki = r / 3, kj = r - (r / 3) * 3;
    const int hp = l >> 6, wp = l & 63;
    const int y = hp * 2 - 1 + ki;
    const int x = wp * 2 - 1 + kj;
    const bool in = ((unsigned)y < (unsigned)H_) && ((unsigned)x < (unsigned)W_);
    const float v = in ? d_conv[1][b][c][y][x] : 0.0f;
    d_vth[b][f][l] = __float2half_rn(v);
}

// ============================================================
// Kernel 3: persistent S = (10 Q) K^T + fused chunk softmax.
// grid (32 row-tiles, B) = 128 CTAs. 512 threads = 16 warps (4 wr x 4 wc),
// warp tile 32x16. FUSED split passes: per k16 load ah,al,bh,bl once,
// issue all 12 MMAs (ah*bh + ah*bl + al*bh).
// ============================================================
__global__ __launch_bounds__(512, 1) void k_gemmS() {
    extern __shared__ __half smh[];
    __shared__ float redbuf[4][128];
    __shared__ float mfin[128];

    const int tid = threadIdx.x;
    const int lane = tid & 31;
    const int warp = tid >> 5;
    const int wr = warp >> 2;           // 0..3 (rows)
    const int wc = warp & 3;            // 0..3 (16-col groups)
    const int g = lane >> 2;            // 0..7
    const int t = lane & 3;             // 0..3
    const int b = blockIdx.y;
    const int row0 = blockIdx.x * 128;

    const uint32_t sbase = smem_u32(smh);

    // prologue: Q hi/lo (resident) + K chunk 0
    for (int e = tid; e < 128 * 18; e += 512) {
        const int r = e / 18, u = e - (e / 18) * 18;
        const uint32_t so = (uint32_t)(r * SQ_STR + u * 8) * 2;
        cp_async16(sbase + SQH_OFF * 2 + so, &d_qh[b][row0 + r][u * 8]);
        cp_async16(sbase + SQL_OFF * 2 + so, &d_ql[b][row0 + r][u * 8]);
    }
    for (int e = tid; e < 64 * 18; e += 512) {
        const int r = e / 18, u = e - (e / 18) * 18;
        const uint32_t so = (uint32_t)(r * SQ_STR + u * 8) * 2;
        cp_async16(sbase + SK_BASE * 2 + so, &d_kh[b][r][u * 8]);
        cp_async16(sbase + (SK_BASE + SK_HALFS) * 2 + so, &d_kl[b][r][u * 8]);
    }
    CP_COMMIT();

    // LDSM lane offsets
    const uint32_t aoff0 = (uint32_t)((wr * 32 + 0  + (lane & 15)) * SQ_STR + ((lane >> 4) << 3)) * 2;
    const uint32_t aoff1 = (uint32_t)((wr * 32 + 16 + (lane & 15)) * SQ_STR + ((lane >> 4) << 3)) * 2;
    const uint32_t boff  = (uint32_t)((wc * 16 + (lane & 7) + ((lane >> 4) << 3)) * SQ_STR +
                                      (((lane >> 3) & 1) << 3)) * 2;
    const uint32_t QHb = sbase + SQH_OFF * 2;
    const uint32_t QLb = sbase + SQL_OFF * 2;

    for (int ct = 0; ct < NCB_; ct++) {
        const int buf = ct & 1;
        const int col0 = ct * 64;

        // issue next K chunk into other buffer
        if (ct < NCB_ - 1) {
            const uint32_t kb1 = sbase + (SK_BASE + (buf ^ 1) * 2 * SK_HALFS) * 2;
            const int c1 = (ct + 1) * 64;
            for (int e = tid; e < 64 * 18; e += 512) {
                const int r = e / 18, u = e - (e / 18) * 18;
                const uint32_t so = (uint32_t)(r * SQ_STR + u * 8) * 2;
                cp_async16(kb1 + so, &d_kh[b][c1 + r][u * 8]);
                cp_async16(kb1 + SK_HALFS * 2 + so, &d_kl[b][c1 + r][u * 8]);
            }
            CP_COMMIT();
            CP_WAIT(1);
        } else {
            CP_WAIT(0);
        }
        __syncthreads();

        const uint32_t KHb = sbase + (SK_BASE + buf * 2 * SK_HALFS) * 2;
        const uint32_t KLb = KHb + SK_HALFS * 2;

        float acc[2][2][4];
#pragma unroll
        for (int m = 0; m < 2; m++)
#pragma unroll
            for (int n = 0; n < 2; n++)
#pragma unroll
                for (int j = 0; j < 4; j++) acc[m][n][j] = 0.f;

#pragma unroll
        for (int k16 = 0; k16 < 9; k16++) {
            const uint32_t kb = (uint32_t)(k16 * 16) * 2;
            uint32_t ah[2][4], al[2][4], bh[4], bl[4];
            ldsm_x4(ah[0], QHb + aoff0 + kb);
            ldsm_x4(ah[1], QHb + aoff1 + kb);
            ldsm_x4(bh, KHb + boff + kb);
            ldsm_x4(al[0], QLb + aoff0 + kb);
            ldsm_x4(al[1], QLb + aoff1 + kb);
            ldsm_x4(bl, KLb + boff + kb);
            // ah * bh
            mma16816(acc[0][0], ah[0], bh[0], bh[1]);
            mma16816(acc[1][0], ah[1], bh[0], bh[1]);
            mma16816(acc[0][1], ah[0], bh[2], bh[3]);
            mma16816(acc[1][1], ah[1], bh[2], bh[3]);
            // ah * bl
            mma16816(acc[0][0], ah[0], bl[0], bl[1]);
            mma16816(acc[1][0], ah[1], bl[0], bl[1]);
            mma16816(acc[0][1], ah[0], bl[2], bl[3]);
            mma16816(acc[1][1], ah[1], bl[2], bl[3]);
            // al * bh
            mma16816(acc[0][0], al[0], bh[0], bh[1]);
            mma16816(acc[1][0], al[1], bh[0], bh[1]);
            mma16816(acc[0][1], al[0], bh[2], bh[3]);
            mma16816(acc[1][1], al[1], bh[2], bh[3]);
        }

        // ---- fused chunk softmax (rows R[ri] = wr*32 + (ri>>1)*16 + (ri&1)*8 + g) ----
        float rmax[4];
#pragma unroll
        for (int ri = 0; ri < 4; ri++) {
            const int m = ri >> 1, jb = (ri & 1) * 2;
            rmax[ri] = fmaxf(fmaxf(acc[m][0][jb], acc[m][0][jb + 1]),
                             fmaxf(acc[m][1][jb], acc[m][1][jb + 1]));
        }
#pragma unroll
        for (int off = 1; off <= 2; off <<= 1)
#pragma unroll
            for (int ri = 0; ri < 4; ri++)
                rmax[ri] = fmaxf(rmax[ri], __shfl_xor_sync(0xffffffffu, rmax[ri], off));
        if (t == 0) {
#pragma unroll
            for (int ri = 0; ri < 4; ri++)
                redbuf[wc][wr * 32 + (ri >> 1) * 16 + (ri & 1) * 8 + g] = rmax[ri];
        }
        __syncthreads();
        if (tid < 128)
            mfin[tid] = fmaxf(fmaxf(redbuf[0][tid], redbuf[1][tid]),
                              fmaxf(redbuf[2][tid], redbuf[3][tid]));
        __syncthreads();

        float rsum[4];
#pragma unroll
        for (int ri = 0; ri < 4; ri++) {
            const int m = ri >> 1, jb = (ri & 1) * 2;
            const int row = wr * 32 + (ri >> 1) * 16 + (ri & 1) * 8 + g;
            const float mx = mfin[row];
            float sum = 0.f;
#pragma unroll
            for (int n = 0; n < 2; n++) {
                const float e0 = __expf(acc[m][n][jb] - mx);
                const float e1 = __expf(acc[m][n][jb + 1] - mx);
                sum += e0 + e1;
                *(__half2*)&d_Pv[b][row0 + row][col0 + wc * 16 + n * 8 + t * 2] =
                    __floats2half2_rn(e0, e1);
            }
            rsum[ri] = sum;
        }
#pragma unroll
        for (int off = 1; off <= 2; off <<= 1)
#pragma unroll
            for (int ri = 0; ri < 4; ri++)
                rsum[ri] += __shfl_xor_sync(0xffffffffu, rsum[ri], off);
        if (t == 0) {
#pragma unroll
            for (int ri = 0; ri < 4; ri++)
                redbuf[wc][wr * 32 + (ri >> 1) * 16 + (ri & 1) * 8 + g] = rsum[ri];
        }
        __syncthreads();
        if (tid < 128) {
            d_mc[b][ct][row0 + tid] = mfin[tid];
            d_lc[b][ct][row0 + tid] = redbuf[0][tid] + redbuf[1][tid] +
                                      redbuf[2][tid] + redbuf[3][tid];
        }
        __syncthreads();
    }
}

// ============================================================
// Kernel 4: per-row reduction: final max, chunk scales, 1/l.
// ============================================================
__global__ void k_reduce() {
    const int idx = blockIdx.x * 256 + threadIdx.x;   // b*4096 + r
    const int b = idx >> 12, r = idx & 4095;
    float m = -1e30f;
#pragma unroll 8
    for (int c = 0; c < NCB_; c++) m = fmaxf(m, d_mc[b][c][r]);
    float l = 0.0f;
#pragma unroll 8
    for (int c = 0; c < NCB_; c++) {
        const float sc = __expf(d_mc[b][c][r] - m);
        d_scale[b][c][r] = sc;
        l += sc * d_lc[b][c][r];
    }
    d_linv[b][r] = 1.0f / l;
}

// ============================================================
// Kernel 5: zi = (P_scaled / l) V, fp16 HMMA + LDSM, double-buffered V.
// grid (32 row-tiles, B), 512 threads = 16 warps (8 wr x 2 wc),
// warp tile 16x72.
// ============================================================
__global__ __launch_bounds__(512, 1) void k_gemmPV() {
    extern __shared__ char smc[];
    float* scs = (float*)smc;                      // [64 cb][128 rows]
    __half* smP = (__half*)(smc + PV_P_OFF);       // [2][128*72]
    __half* smV = (__half*)(smc + PV_V_OFF);       // [2][144*72]

    const int tid = threadIdx.x;
    const int lane = tid & 31;
    const int warp = tid >> 5;
    const int wr = warp >> 1;          // 0..7 (16-row groups)
    const int wc = warp & 1;           // 0..1 (72-col halves)
    const int g = lane >> 2;
    const int t = lane & 3;
    const int b = blockIdx.y;
    const int row0 = blockIdx.x * 128;

    // preload all 64 per-row chunk scales
    for (int e = tid; e < NCB_ * 128; e += 512)
        scs[e] = d_scale[b][e >> 7][row0 + (e & 127)];

    float acc[9][4];
#pragma unroll
    for (int n = 0; n < 9; n++)
#pragma unroll
        for (int j = 0; j < 4; j++) acc[n][j] = 0.f;

    const uint32_t pbase = smem_u32(smP);
    const uint32_t vbase0 = smem_u32(smV);
    const uint32_t aoff = (uint32_t)((wr * 16 + (lane & 15)) * PV_STR + ((lane >> 4) << 3)) * 2;
    uint32_t boffp[4];
#pragma unroll
    for (int p = 0; p < 4; p++)
        boffp[p] = (uint32_t)((wc * 72 + p * 16 + (lane & 7) + ((lane >> 4) << 3)) * PV_STR +
                              (((lane >> 3) & 1) << 3)) * 2;
    const uint32_t boffs = (uint32_t)((wc * 72 + 64 + (lane & 7)) * PV_STR +
                                      (((lane >> 3) & 1) << 3)) * 2;

    // thread's P-staging coordinates: 1024 uint4 / 512 threads = 2 each
    const int pr_r[2] = { tid >> 3, (tid + 512) >> 3 };
    const int pr_u = tid & 7;

    // prologue: issue V chunk 0 + load P chunk 0 into regs
    for (int e = tid; e < 144 * 8; e += 512) {
        const int f = e >> 3, u = e & 7;
        cp_async16(vbase0 + (uint32_t)(f * PV_STR + u * 8) * 2, &d_vth[b][f][0 + u * 8]);
    }
    CP_COMMIT();
    uint4 pr[2];
#pragma unroll
    for (int i = 0; i < 2; i++)
        pr[i] = *(const uint4*)&d_Pv[b][row0 + pr_r[i]][0 + pr_u * 8];
    __syncthreads();   // scs ready

    for (int ct = 0; ct < 64; ct++) {
        const int buf = ct & 1;
        __half* P = smP + buf * PV_P_HALFS;
        const uint32_t Pb = pbase + buf * PV_P_HALFS * 2;
        const uint32_t Vb = vbase0 + buf * PV_V_HALFS * 2;

        // stage P (scaled) into smem
        {
            const float* scrow = scs + ct * 128;
#pragma unroll
            for (int i = 0; i < 2; i++) {
                const __half2 hsc = __float2half2_rn(scrow[pr_r[i]]);
                uint4 p = pr[i];
                __half2* ph = (__half2*)&p;
#pragma unroll
                for (int j = 0; j < 4; j++) ph[j] = __hmul2(ph[j], hsc);
                *(uint4*)&P[pr_r[i] * PV_STR + pr_u * 8] = p;
            }
        }
        CP_WAIT(0);          // V[buf] arrived
        __syncthreads();

        if (ct < 63) {
            const uint32_t vb1 = vbase0 + (buf ^ 1) * PV_V_HALFS * 2;
            const int k1 = (ct + 1) * 64;
            for (int e = tid; e < 144 * 8; e += 512) {
                const int f = e >> 3, u = e & 7;
                cp_async16(vb1 + (uint32_t)(f * PV_STR + u * 8) * 2, &d_vth[b][f][k1 + u * 8]);
            }
            CP_COMMIT();
#pragma unroll
            for (int i = 0; i < 2; i++)
                pr[i] = *(const uint4*)&d_Pv[b][row0 + pr_r[i]][k1 + pr_u * 8];
        }

        // compute
#pragma unroll
        for (int k16 = 0; k16 < 4; k16++) {
            const uint32_t kb = (uint32_t)(k16 * 16) * 2;
            uint32_t a[4];
            ldsm_x4(a, Pb + aoff + kb);
#pragma unroll
            for (int p = 0; p < 4; p++) {
                uint32_t bb[4];
                ldsm_x4(bb, Vb + boffp[p] + kb);
                mma16816(acc[2 * p],     a, bb[0], bb[1]);
                mma16816(acc[2 * p + 1], a, bb[2], bb[3]);
            }
            {
                uint32_t bs[2];
                ldsm_x2(bs, Vb + boffs + kb);
                mma16816(acc[8], a, bs[0], bs[1]);
            }
        }
        __syncthreads();
    }

    // normalize + store zi  (acc rows: g and g+8 within wr*16 group)
    {
        const int rowA = row0 + wr * 16 + g;
        const int rowB = rowA + 8;
        const float liA = d_linv[b][rowA];
        const float liB = d_linv[b][rowB];
#pragma unroll
        for (int n = 0; n < 9; n++) {
            const int col = wc * 72 + n * 8 + t * 2;
            *(float2*)&d_zi[b][rowA][col] = make_float2(acc[n][0] * liA, acc[n][1] * liA);
            *(float2*)&d_zi[b][rowB][col] = make_float2(acc[n][2] * liB, acc[n][3] * liB);
        }
    }
}

// ============================================================
// Kernel 6: fold (overlap-add + count normalize) + W_w conv -> yvec
// ============================================================
__global__ void k_fold(const float* __restrict__ Wmat, const float* __restrict__ Wb) {
    __shared__ float zs[IC_][W_];
    __shared__ float wsm[C_ * IC_];
    __shared__ float bsm[C_];
    const int x = threadIdx.x;
    const int y = blockIdx.x, b = blockIdx.y;
    for (int i = x; i < C_ * IC_; i += 128) wsm[i] = Wmat[i];
    if (x < C_) bsm[x] = Wb[x];

    float v[IC_];
#pragma unroll
    for (int ic = 0; ic < IC_; ic++) v[ic] = 0.f;
    int cnt = 0;
#pragma unroll
    for (int i = 0; i < 3; i++) {
        const int tY = y + 1 - i;
        if (tY < 0 || (tY & 1) || (tY >> 1) >= HP_) continue;
        const int hp = tY >> 1;
#pragma unroll
        for (int j = 0; j < 3; j++) {
            const int tX = x + 1 - j;
            if (tX < 0 || (tX & 1) || (tX >> 1) >= HP_) continue;
            const int wp = tX >> 1;
            const float* zrow = &d_zi[b][hp * 64 + wp][0];
            cnt++;
#pragma unroll
            for (int ic = 0; ic < IC_; ic++) v[ic] += zrow[ic * 9 + i * 3 + j];
        }
    }
    const float invc = 1.0f / (float)cnt;
#pragma unroll
    for (int ic = 0; ic < IC_; ic++) zs[ic][x] = v[ic] * invc;
    __syncthreads();

    for (int o = 0; o < C_; o++) {
        float a = bsm[o];
#pragma unroll
        for (int ic = 0; ic < IC_; ic++) a += wsm[o * IC_ + ic] * zs[ic][x];
        d_yvec[b][o][y][x] = a;
    }
}

// ============================================================
// Kernel 7: out = s + yvec (broadcast over D)
// ============================================================
__global__ void k_out(const float* __restrict__ s, float* __restrict__ out) {
    const int idx = blockIdx.x * 256 + threadIdx.x;
    const int pix = idx & (H_ * W_ - 1);
    const int bo = (idx >> 14) >> 3;  // b*64 + o
    out[idx] = s[idx] + (&d_yvec[0][0][0][0])[bo * (H_ * W_) + pix];
}

// ============================================================
extern "C" void kernel_launch(void* const* d_in, const int* /*in_sizes*/, int /*n_in*/,
                              void* d_out, int /*out_size*/) {
    const float* s   = (const float*)d_in[0];
    const float* g   = (const float*)d_in[1];
    const float* g_w = (const float*)d_in[2];
    const float* g_b = (const float*)d_in[3];
    const float* t_w = (const float*)d_in[4];
    const float* t_b = (const float*)d_in[5];
    const float* p_w = (const float*)d_in[6];
    const float* p_b = (const float*)d_in[7];
    const float* W_w = (const float*)d_in[8];
    const float* W_b = (const float*)d_in[9];
    float* out = (float*)d_out;

    cudaFuncSetAttribute(k_gemmS,  cudaFuncAttributeMaxDynamicSharedMemorySize, SGEMM_SMEM_BYTES);
    cudaFuncSetAttribute(k_gemmPV, cudaFuncAttributeMaxDynamicSharedMemorySize, PV_SMEM_BYTES);

    k_conv<<<dim3(H_, B_), 128>>>(s, g, g_w, g_b, t_w, t_b, p_w, p_b);
    k_patch_qk<<<(B_ * L_ * F_) / 256, 256>>>();
    k_patch_v<<<(B_ * F_ * L_) / 256, 256>>>();

    k_gemmS<<<dim3(32, B_), 512, SGEMM_SMEM_BYTES>>>();
    k_reduce<<<(B_ * L_) / 256, 256>>>();
    k_gemmPV<<<dim3(32, B_), 512, PV_SMEM_BYTES>>>();

    k_fold<<<dim3(H_, B_), 128>>>(W_w, W_b);
    k_out<<<(B_ * C_ * D_ * H_ * W_) / 256, 256>>>(s, out);
}

// round 9
// speedup vs baseline: 3.1566x; 1.0178x over previous
#include <cuda_runtime.h>
#include <cuda_fp16.h>
#include <cstdint>

namespace {
constexpr int B_  = 4;
constexpr int C_  = 64;
constexpr int IC_ = 16;
constexpr int D_  = 8;
constexpr int H_  = 128;
constexpr int W_  = 128;
constexpr int MID_ = 4;
constexpr int HP_ = 64;
constexpr int L_  = 4096;
constexpr int F_  = 144;    // IC*3*3 = 9 * 16
constexpr int NCB_ = 128;   // number of 32-col softmax chunks
constexpr float SCALE_ = 10.0f;

// S-GEMM smem: k16-tiled swizzled layout, no padding.
// operand plane = 9 tiles x (128 rows x 32B) = 36864 B
constexpr int TILE_B = 4096;
constexpr int OP_B   = 9 * TILE_B;          // 36864
constexpr int SQH_B  = 0;
constexpr int SQL_B  = OP_B;
constexpr int SK_B   = 2 * OP_B;            // K: buf*(2*OP_B) + hilo*OP_B
constexpr int SGEMM_SMEM_BYTES = 6 * OP_B;  // 221184

// PV-GEMM smem layout (bytes)
constexpr int PV_STR = 72;
constexpr int PV_P_HALFS = 128 * PV_STR;                   // 9216
constexpr int PV_V_HALFS = 144 * PV_STR;                   // 10368
constexpr int PV_P_OFF = 0;
constexpr int PV_V_OFF = 2 * PV_P_HALFS * 2;               // 36864
constexpr int PV_SMEM_BYTES = PV_V_OFF + 2 * PV_V_HALFS * 2;  // 78336
}

// ============================================================
// helpers
// ============================================================
__device__ __forceinline__ void mma16816(float* c, const uint32_t* a,
                                         uint32_t b0, uint32_t b1) {
    asm volatile(
        "mma.sync.aligned.m16n8k16.row.col.f32.f16.f16.f32 "
        "{%0,%1,%2,%3}, {%4,%5,%6,%7}, {%8,%9}, {%0,%1,%2,%3};"
        : "+f"(c[0]), "+f"(c[1]), "+f"(c[2]), "+f"(c[3])
        : "r"(a[0]), "r"(a[1]), "r"(a[2]), "r"(a[3]), "r"(b0), "r"(b1));
}

__device__ __forceinline__ void ldsm_x4(uint32_t* r, uint32_t smaddr) {
    asm volatile("ldmatrix.sync.aligned.m8n8.x4.shared.b16 {%0,%1,%2,%3}, [%4];"
                 : "=r"(r[0]), "=r"(r[1]), "=r"(r[2]), "=r"(r[3]) : "r"(smaddr));
}
__device__ __forceinline__ void ldsm_x2(uint32_t* r, uint32_t smaddr) {
    asm volatile("ldmatrix.sync.aligned.m8n8.x2.shared.b16 {%0,%1}, [%2];"
                 : "=r"(r[0]), "=r"(r[1]) : "r"(smaddr));
}

__device__ __forceinline__ void cp_async16(uint32_t smaddr, const void* gptr) {
    asm volatile("cp.async.cg.shared.global [%0], [%1], 16;"
                 :: "r"(smaddr), "l"(gptr) : "memory");
}
#define CP_COMMIT() asm volatile("cp.async.commit_group;" ::: "memory")
#define CP_WAIT(n)  asm volatile("cp.async.wait_group %0;" :: "n"(n) : "memory")

__device__ __forceinline__ uint32_t smem_u32(const void* p) {
    uint32_t a;
    asm("{ .reg .u64 t; cvta.to.shared.u64 t, %1; cvt.u32.u64 %0, t; }" : "=r"(a) : "l"(p));
    return a;
}

// XOR swizzle within a 128-row x 32B k16 tile: bit7 -> bit4
__device__ __forceinline__ uint32_t swz(uint32_t o) { return o ^ ((o & 0x80u) >> 3); }

__device__ __forceinline__ void split16(float x, __half& h, __half& l) {
    h = __float2half_rn(x);
    l = __float2half_rn(x - __half2float(h));
}

// ============================================================
// scratch (device globals)
// ============================================================
__device__ float d_conv[3][B_][IC_][H_][W_];
__device__ __align__(16) __half d_qh[B_][L_][F_];
__device__ __align__(16) __half d_ql[B_][L_][F_];
__device__ __align__(16) __half d_kh[B_][L_][F_];
__device__ __align__(16) __half d_kl[B_][L_][F_];
__device__ __align__(16) __half d_vth[B_][F_][L_];
__device__ __align__(16) __half d_Pv[B_][L_][L_];     // exp(S - m_chunk32), fp16
__device__ float d_mc[B_][NCB_][L_];
__device__ float d_lc[B_][NCB_][L_];
__device__ float d_scale[B_][NCB_][L_];
__device__ float d_linv[B_][L_];
__device__ float d_zi[B_][L_][F_];
__device__ float d_yvec[B_][C_][H_][W_];

// ============================================================
// Kernel 1: 1x1 convs at the mid depth slice only.
// ============================================================
__global__ void k_conv(const float* __restrict__ s, const float* __restrict__ g,
                       const float* __restrict__ gw, const float* __restrict__ gb,
                       const float* __restrict__ tw, const float* __restrict__ tb,
                       const float* __restrict__ pw, const float* __restrict__ pb) {
    __shared__ float wq[IC_ * C_], wv[IC_ * C_], wk[IC_ * C_];
    __shared__ float bq[IC_], bv[IC_], bk[IC_];
    const int tid = threadIdx.x;
    for (int i = tid; i < IC_ * C_; i += 128) { wq[i] = gw[i]; wv[i] = tw[i]; wk[i] = pw[i]; }
    if (tid < IC_) { bq[tid] = gb[tid]; bv[tid] = tb[tid]; bk[tid] = pb[tid]; }
    __syncthreads();

    const int y = blockIdx.x, b = blockIdx.y, x = tid;
    float aq[IC_], av[IC_], ak[IC_];
#pragma unroll
    for (int ic = 0; ic < IC_; ic++) { aq[ic] = bq[ic]; av[ic] = bv[ic]; ak[ic] = bk[ic]; }

    const size_t base = ((size_t)b * C_ * D_ + MID_) * (H_ * W_) + (size_t)y * W_ + x;
    const size_t cstride = (size_t)D_ * H_ * W_;
#pragma unroll 4
    for (int c = 0; c < C_; c++) {
        const float sv = s[base + c * cstride];
        const float gv = g[base + c * cstride];
#pragma unroll
        for (int ic = 0; ic < IC_; ic++) {
            aq[ic] += wq[ic * C_ + c] * sv;
            av[ic] += wv[ic * C_ + c] * gv;
            ak[ic] += wk[ic * C_ + c] * gv;
        }
    }
#pragma unroll
    for (int ic = 0; ic < IC_; ic++) {
        const int o = ((b * IC_ + ic) * H_ + y) * W_ + x;
        (&d_conv[0][0][0][0][0])[o] = aq[ic];
        (&d_conv[1][0][0][0][0])[o] = av[ic];
        (&d_conv[2][0][0][0][0])[o] = ak[ic];
    }
}

// ============================================================
// Kernel 2a: patches -> q (pre-scaled by 10) and k, fp16 hi/lo split.
// ============================================================
__global__ void k_patch_qk() {
    const int idx = blockIdx.x * 256 + threadIdx.x;
    const int f = idx % F_;
    const int t = idx / F_;
    const int l = t & (L_ - 1);
    const int b = t >> 12;
    const int c = f / 9;
    const int r = f - c * 9;
    const int ki = r / 3, kj = r - (r / 3) * 3;
    const int hp = l >> 6, wp = l & 63;
    const int y = hp * 2 - 1 + ki;
    const int x = wp * 2 - 1 + kj;
    const bool in = ((unsigned)y < (unsigned)H_) && ((unsigned)x < (unsigned)W_);
    float q = in ? d_conv[0][b][c][y][x] : 0.0f;
    float k = in ? d_conv[2][b][c][y][x] : 0.0f;
    q *= SCALE_;
    __half qh, ql, kh, kl;
    split16(q, qh, ql);
    split16(k, kh, kl);
    d_qh[b][l][f] = qh; d_ql[b][l][f] = ql;
    d_kh[b][l][f] = kh; d_kl[b][l][f] = kl;
}

// ============================================================
// Kernel 2b: patches -> V transposed [b][f][l], fp16.
// ============================================================
__global__ void k_patch_v() {
    const int idx = blockIdx.x * 256 + threadIdx.x;
    const int b = idx / (F_ * L_);
    const int rem = idx - b * (F_ * L_);
    const int f = rem / L_;
    const int l = rem - f * L_;
    const int c = f / 9;
    const int r = f - c * 9;
    const int ki = r / 3, kj = r - (r / 3) * 3;
    const int hp = l >> 6, wp = l & 63;
    const int y = hp * 2 - 1 + ki;
    const int x = wp * 2 - 1 + kj;
    const bool in = ((unsigned)y < (unsigned)H_) && ((unsigned)x < (unsigned)W_);
    const float v = in ? d_conv[1][b][c][y][x] : 0.0f;
    d_vth[b][f][l] = __float2half_rn(v);
}

// ============================================================
// Kernel 3: persistent S = (10 Q) K^T + per-warp chunk softmax.
// grid (32 row-tiles, B) = 128 CTAs, 512 threads = 16 warps (4 wr x 4 wc),
// warp tile 32x32 on 128-col K chunks (double-buffered, swizzled k16 tiles).
// Softmax chunk = 32 cols per warp -> zero cross-warp reductions.
// ============================================================
__global__ __launch_bounds__(512, 1) void k_gemmS() {
    extern __shared__ char smc[];
    const uint32_t sbase = smem_u32(smc);

    const int tid = threadIdx.x;
    const int lane = tid & 31;
    const int warp = tid >> 5;
    const int wr = warp >> 2;           // 0..3 (32-row groups)
    const int wc = warp & 3;            // 0..3 (32-col groups)
    const int g = lane >> 2;            // 0..7
    const int t = lane & 3;             // 0..3
    const int b = blockIdx.y;
    const int row0 = blockIdx.x * 128;

    // prologue: Q hi/lo (resident) + K chunk 0, one cp.async group
    for (int e = tid; e < 128 * 18; e += 512) {
        const int r = e / 18, u = e - (e / 18) * 18;
        const int k16 = u >> 1, h = u & 1;
        const uint32_t o = (uint32_t)k16 * TILE_B + swz((uint32_t)(r * 32 + h * 16));
        const int fc = k16 * 16 + h * 8;
        cp_async16(sbase + SQH_B + o, &d_qh[b][row0 + r][fc]);
        cp_async16(sbase + SQL_B + o, &d_ql[b][row0 + r][fc]);
        cp_async16(sbase + SK_B + o, &d_kh[b][r][fc]);
        cp_async16(sbase + SK_B + OP_B + o, &d_kl[b][r][fc]);
    }
    CP_COMMIT();

    // LDSM lane offsets (within an operand plane; add tile base per k16)
    uint32_t aoff[2], boff[2];
#pragma unroll
    for (int m = 0; m < 2; m++)
        aoff[m] = swz((uint32_t)((wr * 32 + m * 16 + (lane & 15)) * 32 + ((lane >> 4) & 1) * 16));
#pragma unroll
    for (int n16 = 0; n16 < 2; n16++)
        boff[n16] = swz((uint32_t)((wc * 32 + n16 * 16 + (lane & 7) + ((lane >> 4) << 3)) * 32 +
                                   (((lane >> 3) & 1) << 4)));

    const uint32_t QH = sbase + SQH_B;
    const uint32_t QL = sbase + SQL_B;

    for (int ct = 0; ct < 32; ct++) {
        const int buf = ct & 1;
        const int col0 = ct * 128;

        CP_WAIT(0);
        __syncthreads();

        // issue next K chunk (other buffer) — safe: all warps past previous compute
        if (ct < 31) {
            const uint32_t kb1 = sbase + SK_B + (uint32_t)(buf ^ 1) * 2 * OP_B;
            const int c1 = (ct + 1) * 128;
            for (int e = tid; e < 128 * 18; e += 512) {
                const int r = e / 18, u = e - (e / 18) * 18;
                const int k16 = u >> 1, h = u & 1;
                const uint32_t o = (uint32_t)k16 * TILE_B + swz((uint32_t)(r * 32 + h * 16));
                const int fc = k16 * 16 + h * 8;
                cp_async16(kb1 + o, &d_kh[b][c1 + r][fc]);
                cp_async16(kb1 + OP_B + o, &d_kl[b][c1 + r][fc]);
            }
            CP_COMMIT();
        }

        const uint32_t KH = sbase + SK_B + (uint32_t)buf * 2 * OP_B;
        const uint32_t KL = KH + OP_B;

        float acc[2][4][4];
#pragma unroll
        for (int m = 0; m < 2; m++)
#pragma unroll
            for (int n = 0; n < 4; n++)
#pragma unroll
                for (int j = 0; j < 4; j++) acc[m][n][j] = 0.f;

#pragma unroll
        for (int k16 = 0; k16 < 9; k16++) {
            const uint32_t tb = (uint32_t)k16 * TILE_B;
            uint32_t ah[2][4], al[2][4], bh[2][4], bl[2][4];
            ldsm_x4(ah[0], QH + tb + aoff[0]);
            ldsm_x4(ah[1], QH + tb + aoff[1]);
            ldsm_x4(bh[0], KH + tb + boff[0]);
            ldsm_x4(bh[1], KH + tb + boff[1]);
            ldsm_x4(al[0], QL + tb + aoff[0]);
            ldsm_x4(al[1], QL + tb + aoff[1]);
            ldsm_x4(bl[0], KL + tb + boff[0]);
            ldsm_x4(bl[1], KL + tb + boff[1]);
#pragma unroll
            for (int m = 0; m < 2; m++) {
                // hi*hi
                mma16816(acc[m][0], ah[m], bh[0][0], bh[0][1]);
                mma16816(acc[m][1], ah[m], bh[0][2], bh[0][3]);
                mma16816(acc[m][2], ah[m], bh[1][0], bh[1][1]);
                mma16816(acc[m][3], ah[m], bh[1][2], bh[1][3]);
                // hi*lo
                mma16816(acc[m][0], ah[m], bl[0][0], bl[0][1]);
                mma16816(acc[m][1], ah[m], bl[0][2], bl[0][3]);
                mma16816(acc[m][2], ah[m], bl[1][0], bl[1][1]);
                mma16816(acc[m][3], ah[m], bl[1][2], bl[1][3]);
                // lo*hi
                mma16816(acc[m][0], al[m], bh[0][0], bh[0][1]);
                mma16816(acc[m][1], al[m], bh[0][2], bh[0][3]);
                mma16816(acc[m][2], al[m], bh[1][0], bh[1][1]);
                mma16816(acc[m][3], al[m], bh[1][2], bh[1][3]);
            }
        }

        // ---- per-warp chunk softmax (chunk = this warp's 32 cols) ----
        const int cb = ct * 4 + wc;
#pragma unroll
        for (int ri = 0; ri < 4; ri++) {
            const int m = ri >> 1, jb = (ri & 1) * 2;
            const int row = wr * 32 + (ri >> 1) * 16 + (ri & 1) * 8 + g;
            float mx = acc[m][0][jb];
#pragma unroll
            for (int n = 0; n < 4; n++)
                mx = fmaxf(mx, fmaxf(acc[m][n][jb], acc[m][n][jb + 1]));
            mx = fmaxf(mx, __shfl_xor_sync(0xffffffffu, mx, 1));
            mx = fmaxf(mx, __shfl_xor_sync(0xffffffffu, mx, 2));
            float sum = 0.f;
#pragma unroll
            for (int n = 0; n < 4; n++) {
                const float e0 = __expf(acc[m][n][jb] - mx);
                const float e1 = __expf(acc[m][n][jb + 1] - mx);
                sum += e0 + e1;
                *(__half2*)&d_Pv[b][row0 + row][col0 + wc * 32 + n * 8 + t * 2] =
                    __floats2half2_rn(e0, e1);
            }
            sum += __shfl_xor_sync(0xffffffffu, sum, 1);
            sum += __shfl_xor_sync(0xffffffffu, sum, 2);
            if (t == 0) {
                d_mc[b][cb][row0 + row] = mx;
                d_lc[b][cb][row0 + row] = sum;
            }
        }
    }
}

// ============================================================
// Kernel 4: per-row reduction: final max, chunk scales, 1/l.
// ============================================================
__global__ void k_reduce() {
    const int idx = blockIdx.x * 256 + threadIdx.x;   // b*4096 + r
    const int b = idx >> 12, r = idx & 4095;
    float m = -1e30f;
#pragma unroll 8
    for (int c = 0; c < NCB_; c++) m = fmaxf(m, d_mc[b][c][r]);
    float l = 0.0f;
#pragma unroll 8
    for (int c = 0; c < NCB_; c++) {
        const float sc = __expf(d_mc[b][c][r] - m);
        d_scale[b][c][r] = sc;
        l += sc * d_lc[b][c][r];
    }
    d_linv[b][r] = 1.0f / l;
}

// ============================================================
// Kernel 5: zi = (P_scaled / l) V, fp16 HMMA + LDSM, double-buffered V.
// grid (32 row-tiles, B), 512 threads = 16 warps (8 wr x 2 wc), warp 16x72.
// Scales (32-col granularity) prefetched via LDG.
// ============================================================
__global__ __launch_bounds__(512, 1) void k_gemmPV() {
    extern __shared__ char smc[];
    __half* smP = (__half*)(smc + PV_P_OFF);       // [2][128*72]
    __half* smV = (__half*)(smc + PV_V_OFF);       // [2][144*72]

    const int tid = threadIdx.x;
    const int lane = tid & 31;
    const int warp = tid >> 5;
    const int wr = warp >> 1;          // 0..7 (16-row groups)
    const int wc = warp & 1;           // 0..1 (72-col halves)
    const int g = lane >> 2;
    const int t = lane & 3;
    const int b = blockIdx.y;
    const int row0 = blockIdx.x * 128;

    float acc[9][4];
#pragma unroll
    for (int n = 0; n < 9; n++)
#pragma unroll
        for (int j = 0; j < 4; j++) acc[n][j] = 0.f;

    const uint32_t pbase = smem_u32(smP);
    const uint32_t vbase0 = smem_u32(smV);
    const uint32_t aoff = (uint32_t)((wr * 16 + (lane & 15)) * PV_STR + ((lane >> 4) << 3)) * 2;
    uint32_t boffp[4];
#pragma unroll
    for (int p = 0; p < 4; p++)
        boffp[p] = (uint32_t)((wc * 72 + p * 16 + (lane & 7) + ((lane >> 4) << 3)) * PV_STR +
                              (((lane >> 3) & 1) << 3)) * 2;
    const uint32_t boffs = (uint32_t)((wc * 72 + 64 + (lane & 7)) * PV_STR +
                                      (((lane >> 3) & 1) << 3)) * 2;

    // thread's P-staging coordinates: 1024 uint4 / 512 threads = 2 each
    const int pr_r[2] = { tid >> 3, (tid + 512) >> 3 };
    const int pr_u = tid & 7;
    const int subc = pr_u >> 2;   // which 32-col chunk within the 64-col V chunk

    // prologue: issue V chunk 0 + load P chunk 0 + scales into regs
    for (int e = tid; e < 144 * 8; e += 512) {
        const int f = e >> 3, u = e & 7;
        cp_async16(vbase0 + (uint32_t)(f * PV_STR + u * 8) * 2, &d_vth[b][f][0 + u * 8]);
    }
    CP_COMMIT();
    uint4 pr[2];
    float sc_r[2];
#pragma unroll
    for (int i = 0; i < 2; i++) {
        pr[i] = *(const uint4*)&d_Pv[b][row0 + pr_r[i]][0 + pr_u * 8];
        sc_r[i] = d_scale[b][subc][row0 + pr_r[i]];
    }

    for (int ct = 0; ct < 64; ct++) {
        const int buf = ct & 1;
        __half* P = smP + buf * PV_P_HALFS;
        const uint32_t Pb = pbase + buf * PV_P_HALFS * 2;
        const uint32_t Vb = vbase0 + buf * PV_V_HALFS * 2;

        // stage P (scaled) into smem
#pragma unroll
        for (int i = 0; i < 2; i++) {
            const __half2 hsc = __float2half2_rn(sc_r[i]);
            uint4 p = pr[i];
            __half2* ph = (__half2*)&p;
#pragma unroll
            for (int j = 0; j < 4; j++) ph[j] = __hmul2(ph[j], hsc);
            *(uint4*)&P[pr_r[i] * PV_STR + pr_u * 8] = p;
        }
        CP_WAIT(0);          // V[buf] arrived
        __syncthreads();

        if (ct < 63) {
            const uint32_t vb1 = vbase0 + (buf ^ 1) * PV_V_HALFS * 2;
            const int k1 = (ct + 1) * 64;
            for (int e = tid; e < 144 * 8; e += 512) {
                const int f = e >> 3, u = e & 7;
                cp_async16(vb1 + (uint32_t)(f * PV_STR + u * 8) * 2, &d_vth[b][f][k1 + u * 8]);
            }
            CP_COMMIT();
#pragma unroll
            for (int i = 0; i < 2; i++) {
                pr[i] = *(const uint4*)&d_Pv[b][row0 + pr_r[i]][k1 + pr_u * 8];
                sc_r[i] = d_scale[b][(ct + 1) * 2 + subc][row0 + pr_r[i]];
            }
        }

        // compute
#pragma unroll
        for (int k16 = 0; k16 < 4; k16++) {
            const uint32_t kb = (uint32_t)(k16 * 16) * 2;
            uint32_t a[4];
            ldsm_x4(a, Pb + aoff + kb);
#pragma unroll
            for (int p = 0; p < 4; p++) {
                uint32_t bb[4];
                ldsm_x4(bb, Vb + boffp[p] + kb);
                mma16816(acc[2 * p],     a, bb[0], bb[1]);
                mma16816(acc[2 * p + 1], a, bb[2], bb[3]);
            }
            {
                uint32_t bs[2];
                ldsm_x2(bs, Vb + boffs + kb);
                mma16816(acc[8], a, bs[0], bs[1]);
            }
        }
        __syncthreads();
    }

    // normalize + store zi  (acc rows: g and g+8 within wr*16 group)
    {
        const int rowA = row0 + wr * 16 + g;
        const int rowB = rowA + 8;
        const float liA = d_linv[b][rowA];
        const float liB = d_linv[b][rowB];
#pragma unroll
        for (int n = 0; n < 9; n++) {
            const int col = wc * 72 + n * 8 + t * 2;
            *(float2*)&d_zi[b][rowA][col] = make_float2(acc[n][0] * liA, acc[n][1] * liA);
            *(float2*)&d_zi[b][rowB][col] = make_float2(acc[n][2] * liB, acc[n][3] * liB);
        }
    }
}

// ============================================================
// Kernel 6: fold (overlap-add + count normalize) + W_w conv -> yvec
// ============================================================
__global__ void k_fold(const float* __restrict__ Wmat, const float* __restrict__ Wb) {
    __shared__ float zs[IC_][W_];
    __shared__ float wsm[C_ * IC_];
    __shared__ float bsm[C_];
    const int x = threadIdx.x;
    const int y = blockIdx.x, b = blockIdx.y;
    for (int i = x; i < C_ * IC_; i += 128) wsm[i] = Wmat[i];
    if (x < C_) bsm[x] = Wb[x];

    float v[IC_];
#pragma unroll
    for (int ic = 0; ic < IC_; ic++) v[ic] = 0.f;
    int cnt = 0;
#pragma unroll
    for (int i = 0; i < 3; i++) {
        const int tY = y + 1 - i;
        if (tY < 0 || (tY & 1) || (tY >> 1) >= HP_) continue;
        const int hp = tY >> 1;
#pragma unroll
        for (int j = 0; j < 3; j++) {
            const int tX = x + 1 - j;
            if (tX < 0 || (tX & 1) || (tX >> 1) >= HP_) continue;
            const int wp = tX >> 1;
            const float* zrow = &d_zi[b][hp * 64 + wp][0];
            cnt++;
#pragma unroll
            for (int ic = 0; ic < IC_; ic++) v[ic] += zrow[ic * 9 + i * 3 + j];
        }
    }
    const float invc = 1.0f / (float)cnt;
#pragma unroll
    for (int ic = 0; ic < IC_; ic++) zs[ic][x] = v[ic] * invc;
    __syncthreads();

    for (int o = 0; o < C_; o++) {
        float a = bsm[o];
#pragma unroll
        for (int ic = 0; ic < IC_; ic++) a += wsm[o * IC_ + ic] * zs[ic][x];
        d_yvec[b][o][y][x] = a;
    }
}

// ============================================================
// Kernel 7: out = s + yvec (broadcast over D)
// ============================================================
__global__ void k_out(const float* __restrict__ s, float* __restrict__ out) {
    const int idx = blockIdx.x * 256 + threadIdx.x;
    const int pix = idx & (H_ * W_ - 1);
    const int bo = (idx >> 14) >> 3;  // b*64 + o
    out[idx] = s[idx] + (&d_yvec[0][0][0][0])[bo * (H_ * W_) + pix];
}

// ============================================================
extern "C" void kernel_launch(void* const* d_in, const int* /*in_sizes*/, int /*n_in*/,
                              void* d_out, int /*out_size*/) {
    const float* s   = (const float*)d_in[0];
    const float* g   = (const float*)d_in[1];
    const float* g_w = (const float*)d_in[2];
    const float* g_b = (const float*)d_in[3];
    const float* t_w = (const float*)d_in[4];
    const float* t_b = (const float*)d_in[5];
    const float* p_w = (const float*)d_in[6];
    const float* p_b = (const float*)d_in[7];
    const float* W_w = (const float*)d_in[8];
    const float* W_b = (const float*)d_in[9];
    float* out = (float*)d_out;

    cudaFuncSetAttribute(k_gemmS,  cudaFuncAttributeMaxDynamicSharedMemorySize, SGEMM_SMEM_BYTES);
    cudaFuncSetAttribute(k_gemmPV, cudaFuncAttributeMaxDynamicSharedMemorySize, PV_SMEM_BYTES);

    k_conv<<<dim3(H_, B_), 128>>>(s, g, g_w, g_b, t_w, t_b, p_w, p_b);
    k_patch_qk<<<(B_ * L_ * F_) / 256, 256>>>();
    k_patch_v<<<(B_ * F_ * L_) / 256, 256>>>();

    k_gemmS<<<dim3(32, B_), 512, SGEMM_SMEM_BYTES>>>();
    k_reduce<<<(B_ * L_) / 256, 256>>>();
    k_gemmPV<<<dim3(32, B_), 512, PV_SMEM_BYTES>>>();

    k_fold<<<dim3(H_, B_), 128>>>(W_w, W_b);
    k_out<<<(B_ * C_ * D_ * H_ * W_) / 256, 256>>>(s, out);
}

// round 10
// speedup vs baseline: 3.8256x; 1.2119x over previous
#include <cuda_runtime.h>
#include <cuda_fp16.h>
#include <cstdint>

namespace {
constexpr int B_  = 4;
constexpr int C_  = 64;
constexpr int IC_ = 16;
constexpr int D_  = 8;
constexpr int H_  = 128;
constexpr int W_  = 128;
constexpr int MID_ = 4;
constexpr int HP_ = 64;
constexpr int L_  = 4096;
constexpr int F_  = 144;    // IC*3*3 = 9 * 16
constexpr int NCB_ = 128;   // number of 32-col softmax chunks
constexpr float SCALE_ = 10.0f;
constexpr float LOG2E_ = 1.4426950408889634f;

// S-GEMM smem: k16-tiled swizzled layout, no padding.
// operand plane = 9 tiles x (128 rows x 32B) = 36864 B
constexpr int TILE_B = 4096;
constexpr int OP_B   = 9 * TILE_B;          // 36864
constexpr int SQ_B   = 0;
constexpr int SK_B   = OP_B;                // K: SK_B + buf*OP_B
constexpr int SGEMM_SMEM_BYTES = 3 * OP_B;  // 110592

// PV-GEMM smem layout (bytes)
constexpr int PV_STR = 72;
constexpr int PV_P_HALFS = 128 * PV_STR;                   // 9216
constexpr int PV_V_HALFS = 144 * PV_STR;                   // 10368
constexpr int PV_P_OFF = 0;
constexpr int PV_V_OFF = 2 * PV_P_HALFS * 2;               // 36864
constexpr int PV_SMEM_BYTES = PV_V_OFF + 2 * PV_V_HALFS * 2;  // 78336
}

// ============================================================
// helpers
// ============================================================
__device__ __forceinline__ void mma16816(float* c, const uint32_t* a,
                                         uint32_t b0, uint32_t b1) {
    asm volatile(
        "mma.sync.aligned.m16n8k16.row.col.f32.f16.f16.f32 "
        "{%0,%1,%2,%3}, {%4,%5,%6,%7}, {%8,%9}, {%0,%1,%2,%3};"
        : "+f"(c[0]), "+f"(c[1]), "+f"(c[2]), "+f"(c[3])
        : "r"(a[0]), "r"(a[1]), "r"(a[2]), "r"(a[3]), "r"(b0), "r"(b1));
}

__device__ __forceinline__ void ldsm_x4(uint32_t* r, uint32_t smaddr) {
    asm volatile("ldmatrix.sync.aligned.m8n8.x4.shared.b16 {%0,%1,%2,%3}, [%4];"
                 : "=r"(r[0]), "=r"(r[1]), "=r"(r[2]), "=r"(r[3]) : "r"(smaddr));
}
__device__ __forceinline__ void ldsm_x2(uint32_t* r, uint32_t smaddr) {
    asm volatile("ldmatrix.sync.aligned.m8n8.x2.shared.b16 {%0,%1}, [%2];"
                 : "=r"(r[0]), "=r"(r[1]) : "r"(smaddr));
}

__device__ __forceinline__ void cp_async16(uint32_t smaddr, const void* gptr) {
    asm volatile("cp.async.cg.shared.global [%0], [%1], 16;"
                 :: "r"(smaddr), "l"(gptr) : "memory");
}
#define CP_COMMIT() asm volatile("cp.async.commit_group;" ::: "memory")
#define CP_WAIT(n)  asm volatile("cp.async.wait_group %0;" :: "n"(n) : "memory")

__device__ __forceinline__ uint32_t smem_u32(const void* p) {
    uint32_t a;
    asm("{ .reg .u64 t; cvta.to.shared.u64 t, %1; cvt.u32.u64 %0, t; }" : "=r"(a) : "l"(p));
    return a;
}

// XOR swizzle within a 128-row x 32B k16 tile: bit7 -> bit4
__device__ __forceinline__ uint32_t swz(uint32_t o) { return o ^ ((o & 0x80u) >> 3); }

// ============================================================
// scratch (device globals)
// ============================================================
__device__ float d_conv[3][B_][IC_][H_][W_];
__device__ __align__(16) __half d_qh[B_][L_][F_];   // 10*log2e*q, fp16
__device__ __align__(16) __half d_kh[B_][L_][F_];
__device__ __align__(16) __half d_vth[B_][F_][L_];
__device__ __align__(16) __half d_Pv[B_][L_][L_];   // 2^(L - m_chunk32), fp16
__device__ float d_mc[B_][NCB_][L_];                // base-2 chunk max
__device__ float d_lc[B_][NCB_][L_];
__device__ float d_scale[B_][NCB_][L_];
__device__ float d_linv[B_][L_];
__device__ float d_zi[B_][L_][F_];
__device__ float d_yvec[B_][C_][H_][W_];

// ============================================================
// Kernel 1: 1x1 convs at the mid depth slice only.
// ============================================================
__global__ void k_conv(const float* __restrict__ s, const float* __restrict__ g,
                       const float* __restrict__ gw, const float* __restrict__ gb,
                       const float* __restrict__ tw, const float* __restrict__ tb,
                       const float* __restrict__ pw, const float* __restrict__ pb) {
    __shared__ float wq[IC_ * C_], wv[IC_ * C_], wk[IC_ * C_];
    __shared__ float bq[IC_], bv[IC_], bk[IC_];
    const int tid = threadIdx.x;
    for (int i = tid; i < IC_ * C_; i += 128) { wq[i] = gw[i]; wv[i] = tw[i]; wk[i] = pw[i]; }
    if (tid < IC_) { bq[tid] = gb[tid]; bv[tid] = tb[tid]; bk[tid] = pb[tid]; }
    __syncthreads();

    const int y = blockIdx.x, b = blockIdx.y, x = tid;
    float aq[IC_], av[IC_], ak[IC_];
#pragma unroll
    for (int ic = 0; ic < IC_; ic++) { aq[ic] = bq[ic]; av[ic] = bv[ic]; ak[ic] = bk[ic]; }

    const size_t base = ((size_t)b * C_ * D_ + MID_) * (H_ * W_) + (size_t)y * W_ + x;
    const size_t cstride = (size_t)D_ * H_ * W_;
#pragma unroll 4
    for (int c = 0; c < C_; c++) {
        const float sv = s[base + c * cstride];
        const float gv = g[base + c * cstride];
#pragma unroll
        for (int ic = 0; ic < IC_; ic++) {
            aq[ic] += wq[ic * C_ + c] * sv;
            av[ic] += wv[ic * C_ + c] * gv;
            ak[ic] += wk[ic * C_ + c] * gv;
        }
    }
#pragma unroll
    for (int ic = 0; ic < IC_; ic++) {
        const int o = ((b * IC_ + ic) * H_ + y) * W_ + x;
        (&d_conv[0][0][0][0][0])[o] = aq[ic];
        (&d_conv[1][0][0][0][0])[o] = av[ic];
        (&d_conv[2][0][0][0][0])[o] = ak[ic];
    }
}

// ============================================================
// Kernel 2a: patches -> q (scaled by 10*log2e) and k, fp16.
// ============================================================
__global__ void k_patch_qk() {
    const int idx = blockIdx.x * 256 + threadIdx.x;
    const int f = idx % F_;
    const int t = idx / F_;
    const int l = t & (L_ - 1);
    const int b = t >> 12;
    const int c = f / 9;
    const int r = f - c * 9;
    const int ki = r / 3, kj = r - (r / 3) * 3;
    const int hp = l >> 6, wp = l & 63;
    const int y = hp * 2 - 1 + ki;
    const int x = wp * 2 - 1 + kj;
    const bool in = ((unsigned)y < (unsigned)H_) && ((unsigned)x < (unsigned)W_);
    const float q = in ? d_conv[0][b][c][y][x] : 0.0f;
    const float k = in ? d_conv[2][b][c][y][x] : 0.0f;
    d_qh[b][l][f] = __float2half_rn(q * (SCALE_ * LOG2E_));
    d_kh[b][l][f] = __float2half_rn(k);
}

// ============================================================
// Kernel 2b: patches -> V transposed [b][f][l], fp16.
// ============================================================
__global__ void k_patch_v() {
    const int idx = blockIdx.x * 256 + threadIdx.x;
    const int b = idx / (F_ * L_);
    const int rem = idx - b * (F_ * L_);
    const int f = rem / L_;
    const int l = rem - f * L_;
    const int c = f / 9;
    const int r = f - c * 9;
    const int ki = r / 3, kj = r - (r / 3) * 3;
    const int hp = l >> 6, wp = l & 63;
    const int y = hp * 2 - 1 + ki;
    const int x = wp * 2 - 1 + kj;
    const bool in = ((unsigned)y < (unsigned)H_) && ((unsigned)x < (unsigned)W_);
    const float v = in ? d_conv[1][b][c][y][x] : 0.0f;
    d_vth[b][f][l] = __float2half_rn(v);
}

// ============================================================
// Kernel 3: persistent L = Q' K^T (single fp16 pass, base-2 logits)
// + per-warp chunk softmax (exp2).
// grid (32 row-tiles, B) = 128 CTAs, 512 threads = 16 warps (4 wr x 4 wc),
// warp tile 32x32 on 128-col K chunks (double-buffered, swizzled k16 tiles).
// ============================================================
__global__ __launch_bounds__(512, 1) void k_gemmS() {
    extern __shared__ char smc[];
    const uint32_t sbase = smem_u32(smc);

    const int tid = threadIdx.x;
    const int lane = tid & 31;
    const int warp = tid >> 5;
    const int wr = warp >> 2;           // 0..3 (32-row groups)
    const int wc = warp & 3;            // 0..3 (32-col groups)
    const int g = lane >> 2;            // 0..7
    const int t = lane & 3;             // 0..3
    const int b = blockIdx.y;
    const int row0 = blockIdx.x * 128;

    // prologue: Q (resident) + K chunk 0, one cp.async group
    for (int e = tid; e < 128 * 18; e += 512) {
        const int r = e / 18, u = e - (e / 18) * 18;
        const int k16 = u >> 1, h = u & 1;
        const uint32_t o = (uint32_t)k16 * TILE_B + swz((uint32_t)(r * 32 + h * 16));
        const int fc = k16 * 16 + h * 8;
        cp_async16(sbase + SQ_B + o, &d_qh[b][row0 + r][fc]);
        cp_async16(sbase + SK_B + o, &d_kh[b][r][fc]);
    }
    CP_COMMIT();

    // LDSM lane offsets (within an operand plane; add tile base per k16)
    uint32_t aoff[2], boff[2];
#pragma unroll
    for (int m = 0; m < 2; m++)
        aoff[m] = swz((uint32_t)((wr * 32 + m * 16 + (lane & 15)) * 32 + ((lane >> 4) & 1) * 16));
#pragma unroll
    for (int n16 = 0; n16 < 2; n16++)
        boff[n16] = swz((uint32_t)((wc * 32 + n16 * 16 + (lane & 7) + ((lane >> 4) << 3)) * 32 +
                                   (((lane >> 3) & 1) << 4)));

    const uint32_t Qb = sbase + SQ_B;

    for (int ct = 0; ct < 32; ct++) {
        const int buf = ct & 1;
        const int col0 = ct * 128;

        CP_WAIT(0);
        __syncthreads();

        // issue next K chunk (other buffer)
        if (ct < 31) {
            const uint32_t kb1 = sbase + SK_B + (uint32_t)(buf ^ 1) * OP_B;
            const int c1 = (ct + 1) * 128;
            for (int e = tid; e < 128 * 18; e += 512) {
                const int r = e / 18, u = e - (e / 18) * 18;
                const int k16 = u >> 1, h = u & 1;
                const uint32_t o = (uint32_t)k16 * TILE_B + swz((uint32_t)(r * 32 + h * 16));
                cp_async16(kb1 + o, &d_kh[b][c1 + r][k16 * 16 + h * 8]);
            }
            CP_COMMIT();
        }

        const uint32_t Kb = sbase + SK_B + (uint32_t)buf * OP_B;

        float acc[2][4][4];
#pragma unroll
        for (int m = 0; m < 2; m++)
#pragma unroll
            for (int n = 0; n < 4; n++)
#pragma unroll
                for (int j = 0; j < 4; j++) acc[m][n][j] = 0.f;

#pragma unroll
        for (int k16 = 0; k16 < 9; k16++) {
            const uint32_t tb = (uint32_t)k16 * TILE_B;
            uint32_t a[2][4], bb[2][4];
            ldsm_x4(a[0], Qb + tb + aoff[0]);
            ldsm_x4(a[1], Qb + tb + aoff[1]);
            ldsm_x4(bb[0], Kb + tb + boff[0]);
            ldsm_x4(bb[1], Kb + tb + boff[1]);
#pragma unroll
            for (int m = 0; m < 2; m++) {
                mma16816(acc[m][0], a[m], bb[0][0], bb[0][1]);
                mma16816(acc[m][1], a[m], bb[0][2], bb[0][3]);
                mma16816(acc[m][2], a[m], bb[1][0], bb[1][1]);
                mma16816(acc[m][3], a[m], bb[1][2], bb[1][3]);
            }
        }

        // ---- per-warp chunk softmax (chunk = this warp's 32 cols; base-2) ----
        const int cb = ct * 4 + wc;
#pragma unroll
        for (int ri = 0; ri < 4; ri++) {
            const int m = ri >> 1, jb = (ri & 1) * 2;
            const int row = wr * 32 + (ri >> 1) * 16 + (ri & 1) * 8 + g;
            float mx = acc[m][0][jb];
#pragma unroll
            for (int n = 0; n < 4; n++)
                mx = fmaxf(mx, fmaxf(acc[m][n][jb], acc[m][n][jb + 1]));
            mx = fmaxf(mx, __shfl_xor_sync(0xffffffffu, mx, 1));
            mx = fmaxf(mx, __shfl_xor_sync(0xffffffffu, mx, 2));
            float sum = 0.f;
#pragma unroll
            for (int n = 0; n < 4; n++) {
                const float e0 = exp2f(acc[m][n][jb] - mx);
                const float e1 = exp2f(acc[m][n][jb + 1] - mx);
                sum += e0 + e1;
                *(__half2*)&d_Pv[b][row0 + row][col0 + wc * 32 + n * 8 + t * 2] =
                    __floats2half2_rn(e0, e1);
            }
            sum += __shfl_xor_sync(0xffffffffu, sum, 1);
            sum += __shfl_xor_sync(0xffffffffu, sum, 2);
            if (t == 0) {
                d_mc[b][cb][row0 + row] = mx;
                d_lc[b][cb][row0 + row] = sum;
            }
        }
    }
}

// ============================================================
// Kernel 4: per-row reduction: final max, chunk scales, 1/l (base-2).
// ============================================================
__global__ void k_reduce() {
    const int idx = blockIdx.x * 256 + threadIdx.x;   // b*4096 + r
    const int b = idx >> 12, r = idx & 4095;
    float m = -1e30f;
#pragma unroll 8
    for (int c = 0; c < NCB_; c++) m = fmaxf(m, d_mc[b][c][r]);
    float l = 0.0f;
#pragma unroll 8
    for (int c = 0; c < NCB_; c++) {
        const float sc = exp2f(d_mc[b][c][r] - m);
        d_scale[b][c][r] = sc;
        l += sc * d_lc[b][c][r];
    }
    d_linv[b][r] = 1.0f / l;
}

// ============================================================
// Kernel 5: zi = (P_scaled / l) V, fp16 HMMA + LDSM, double-buffered V.
// grid (32 row-tiles, B), 512 threads = 16 warps (8 wr x 2 wc), warp 16x72.
// ============================================================
__global__ __launch_bounds__(512, 1) void k_gemmPV() {
    extern __shared__ char smc[];
    __half* smP = (__half*)(smc + PV_P_OFF);       // [2][128*72]
    __half* smV = (__half*)(smc + PV_V_OFF);       // [2][144*72]

    const int tid = threadIdx.x;
    const int lane = tid & 31;
    const int warp = tid >> 5;
    const int wr = warp >> 1;          // 0..7 (16-row groups)
    const int wc = warp & 1;           // 0..1 (72-col halves)
    const int g = lane >> 2;
    const int t = lane & 3;
    const int b = blockIdx.y;
    const int row0 = blockIdx.x * 128;

    float acc[9][4];
#pragma unroll
    for (int n = 0; n < 9; n++)
#pragma unroll
        for (int j = 0; j < 4; j++) acc[n][j] = 0.f;

    const uint32_t pbase = smem_u32(smP);
    const uint32_t vbase0 = smem_u32(smV);
    const uint32_t aoff = (uint32_t)((wr * 16 + (lane & 15)) * PV_STR + ((lane >> 4) << 3)) * 2;
    uint32_t boffp[4];
#pragma unroll
    for (int p = 0; p < 4; p++)
        boffp[p] = (uint32_t)((wc * 72 + p * 16 + (lane & 7) + ((lane >> 4) << 3)) * PV_STR +
                              (((lane >> 3) & 1) << 3)) * 2;
    const uint32_t boffs = (uint32_t)((wc * 72 + 64 + (lane & 7)) * PV_STR +
                                      (((lane >> 3) & 1) << 3)) * 2;

    // thread's P-staging coordinates: 1024 uint4 / 512 threads = 2 each
    const int pr_r[2] = { tid >> 3, (tid + 512) >> 3 };
    const int pr_u = tid & 7;
    const int subc = pr_u >> 2;   // which 32-col chunk within the 64-col V chunk

    // prologue: issue V chunk 0 + load P chunk 0 + scales into regs
    for (int e = tid; e < 144 * 8; e += 512) {
        const int f = e >> 3, u = e & 7;
        cp_async16(vbase0 + (uint32_t)(f * PV_STR + u * 8) * 2, &d_vth[b][f][0 + u * 8]);
    }
    CP_COMMIT();
    uint4 pr[2];
    float sc_r[2];
#pragma unroll
    for (int i = 0; i < 2; i++) {
        pr[i] = *(const uint4*)&d_Pv[b][row0 + pr_r[i]][0 + pr_u * 8];
        sc_r[i] = d_scale[b][subc][row0 + pr_r[i]];
    }

    for (int ct = 0; ct < 64; ct++) {
        const int buf = ct & 1;
        __half* P = smP + buf * PV_P_HALFS;
        const uint32_t Pb = pbase + buf * PV_P_HALFS * 2;
        const uint32_t Vb = vbase0 + buf * PV_V_HALFS * 2;

        // stage P (scaled) into smem
#pragma unroll
        for (int i = 0; i < 2; i++) {
            const __half2 hsc = __float2half2_rn(sc_r[i]);
            uint4 p = pr[i];
            __half2* ph = (__half2*)&p;
#pragma unroll
            for (int j = 0; j < 4; j++) ph[j] = __hmul2(ph[j], hsc);
            *(uint4*)&P[pr_r[i] * PV_STR + pr_u * 8] = p;
        }
        CP_WAIT(0);          // V[buf] arrived
        __syncthreads();

        if (ct < 63) {
            const uint32_t vb1 = vbase0 + (buf ^ 1) * PV_V_HALFS * 2;
            const int k1 = (ct + 1) * 64;
            for (int e = tid; e < 144 * 8; e += 512) {
                const int f = e >> 3, u = e & 7;
                cp_async16(vb1 + (uint32_t)(f * PV_STR + u * 8) * 2, &d_vth[b][f][k1 + u * 8]);
            }
            CP_COMMIT();
#pragma unroll
            for (int i = 0; i < 2; i++) {
                pr[i] = *(const uint4*)&d_Pv[b][row0 + pr_r[i]][k1 + pr_u * 8];
                sc_r[i] = d_scale[b][(ct + 1) * 2 + subc][row0 + pr_r[i]];
            }
        }

        // compute
#pragma unroll
        for (int k16 = 0; k16 < 4; k16++) {
            const uint32_t kb = (uint32_t)(k16 * 16) * 2;
            uint32_t a[4];
            ldsm_x4(a, Pb + aoff + kb);
#pragma unroll
            for (int p = 0; p < 4; p++) {
                uint32_t bb[4];
                ldsm_x4(bb, Vb + boffp[p] + kb);
                mma16816(acc[2 * p],     a, bb[0], bb[1]);
                mma16816(acc[2 * p + 1], a, bb[2], bb[3]);
            }
            {
                uint32_t bs[2];
                ldsm_x2(bs, Vb + boffs + kb);
                mma16816(acc[8], a, bs[0], bs[1]);
            }
        }
        __syncthreads();
    }

    // normalize + store zi
    {
        const int rowA = row0 + wr * 16 + g;
        const int rowB = rowA + 8;
        const float liA = d_linv[b][rowA];
        const float liB = d_linv[b][rowB];
#pragma unroll
        for (int n = 0; n < 9; n++) {
            const int col = wc * 72 + n * 8 + t * 2;
            *(float2*)&d_zi[b][rowA][col] = make_float2(acc[n][0] * liA, acc[n][1] * liA);
            *(float2*)&d_zi[b][rowB][col] = make_float2(acc[n][2] * liB, acc[n][3] * liB);
        }
    }
}

// ============================================================
// Kernel 6: fold (overlap-add + count normalize) + W_w conv -> yvec
// ============================================================
__global__ void k_fold(const float* __restrict__ Wmat, const float* __restrict__ Wb) {
    __shared__ float zs[IC_][W_];
    __shared__ float wsm[C_ * IC_];
    __shared__ float bsm[C_];
    const int x = threadIdx.x;
    const int y = blockIdx.x, b = blockIdx.y;
    for (int i = x; i < C_ * IC_; i += 128) wsm[i] = Wmat[i];
    if (x < C_) bsm[x] = Wb[x];

    float v[IC_];
#pragma unroll
    for (int ic = 0; ic < IC_; ic++) v[ic] = 0.f;
    int cnt = 0;
#pragma unroll
    for (int i = 0; i < 3; i++) {
        const int tY = y + 1 - i;
        if (tY < 0 || (tY & 1) || (tY >> 1) >= HP_) continue;
        const int hp = tY >> 1;
#pragma unroll
        for (int j = 0; j < 3; j++) {
            const int tX = x + 1 - j;
            if (tX < 0 || (tX & 1) || (tX >> 1) >= HP_) continue;
            const int wp = tX >> 1;
            const float* zrow = &d_zi[b][hp * 64 + wp][0];
            cnt++;
#pragma unroll
            for (int ic = 0; ic < IC_; ic++) v[ic] += zrow[ic * 9 + i * 3 + j];
        }
    }
    const float invc = 1.0f / (float)cnt;
#pragma unroll
    for (int ic = 0; ic < IC_; ic++) zs[ic][x] = v[ic] * invc;
    __syncthreads();

    for (int o = 0; o < C_; o++) {
        float a = bsm[o];
#pragma unroll
        for (int ic = 0; ic < IC_; ic++) a += wsm[o * IC_ + ic] * zs[ic][x];
        d_yvec[b][o][y][x] = a;
    }
}

// ============================================================
// Kernel 7: out = s + yvec (broadcast over D)
// ============================================================
__global__ void k_out(const float* __restrict__ s, float* __restrict__ out) {
    const int idx = blockIdx.x * 256 + threadIdx.x;
    const int pix = idx & (H_ * W_ - 1);
    const int bo = (idx >> 14) >> 3;  // b*64 + o
    out[idx] = s[idx] + (&d_yvec[0][0][0][0])[bo * (H_ * W_) + pix];
}

// ============================================================
extern "C" void kernel_launch(void* const* d_in, const int* /*in_sizes*/, int /*n_in*/,
                              void* d_out, int /*out_size*/) {
    const float* s   = (const float*)d_in[0];
    const float* g   = (const float*)d_in[1];
    const float* g_w = (const float*)d_in[2];
    const float* g_b = (const float*)d_in[3];
    const float* t_w = (const float*)d_in[4];
    const float* t_b = (const float*)d_in[5];
    const float* p_w = (const float*)d_in[6];
    const float* p_b = (const float*)d_in[7];
    const float* W_w = (const float*)d_in[8];
    const float* W_b = (const float*)d_in[9];
    float* out = (float*)d_out;

    cudaFuncSetAttribute(k_gemmS,  cudaFuncAttributeMaxDynamicSharedMemorySize, SGEMM_SMEM_BYTES);
    cudaFuncSetAttribute(k_gemmPV, cudaFuncAttributeMaxDynamicSharedMemorySize, PV_SMEM_BYTES);

    k_conv<<<dim3(H_, B_), 128>>>(s, g, g_w, g_b, t_w, t_b, p_w, p_b);
    k_patch_qk<<<(B_ * L_ * F_) / 256, 256>>>();
    k_patch_v<<<(B_ * F_ * L_) / 256, 256>>>();

    k_gemmS<<<dim3(32, B_), 512, SGEMM_SMEM_BYTES>>>();
    k_reduce<<<(B_ * L_) / 256, 256>>>();
    k_gemmPV<<<dim3(32, B_), 512, PV_SMEM_BYTES>>>();

    k_fold<<<dim3(H_, B_), 128>>>(W_w, W_b);
    k_out<<<(B_ * C_ * D_ * H_ * W_) / 256, 256>>>(s, out);
}

// round 11
// speedup vs baseline: 4.7782x; 1.2490x over previous
#include <cuda_runtime.h>
#include <cuda_fp16.h>
#include <cstdint>

namespace {
constexpr int B_  = 4;
constexpr int C_  = 64;
constexpr int IC_ = 16;
constexpr int D_  = 8;
constexpr int H_  = 128;
constexpr int W_  = 128;
constexpr int MID_ = 4;
constexpr int HP_ = 64;
constexpr int L_  = 4096;
constexpr int F_  = 144;    // IC*3*3 = 9 * 16
constexpr float SCALE_ = 10.0f;
constexpr float LOG2E_ = 1.4426950408889634f;

// flash smem layout (bytes), k16-tiled swizzled operands
constexpr int TILE_B  = 4096;                 // 128 rows x 32B (Q/K/P)
constexpr int VTILE_B = 4608;                 // 144 rows x 32B (V)
constexpr int Q_OFF = 0;                      // 9*4096 = 36864
constexpr int K_OFF = 36864;                  // 2 bufs x 36864
constexpr int V_OFF = K_OFF + 2 * 36864;      // 110592; 2 bufs x 8*4608 = 36864
constexpr int P_OFF = V_OFF + 2 * 36864;      // 184320; 8*4096 = 32768
constexpr int ST_OFF = P_OFF + 32768;         // 217088; alphas/mrun/lrun 3*512
constexpr int FLASH_SMEM = ST_OFF + 1536;     // 218624
}

// ============================================================
// helpers
// ============================================================
__device__ __forceinline__ void mma16816(float* c, const uint32_t* a,
                                         uint32_t b0, uint32_t b1) {
    asm volatile(
        "mma.sync.aligned.m16n8k16.row.col.f32.f16.f16.f32 "
        "{%0,%1,%2,%3}, {%4,%5,%6,%7}, {%8,%9}, {%0,%1,%2,%3};"
        : "+f"(c[0]), "+f"(c[1]), "+f"(c[2]), "+f"(c[3])
        : "r"(a[0]), "r"(a[1]), "r"(a[2]), "r"(a[3]), "r"(b0), "r"(b1));
}

__device__ __forceinline__ void ldsm_x4(uint32_t* r, uint32_t smaddr) {
    asm volatile("ldmatrix.sync.aligned.m8n8.x4.shared.b16 {%0,%1,%2,%3}, [%4];"
                 : "=r"(r[0]), "=r"(r[1]), "=r"(r[2]), "=r"(r[3]) : "r"(smaddr));
}
__device__ __forceinline__ void ldsm_x2(uint32_t* r, uint32_t smaddr) {
    asm volatile("ldmatrix.sync.aligned.m8n8.x2.shared.b16 {%0,%1}, [%2];"
                 : "=r"(r[0]), "=r"(r[1]) : "r"(smaddr));
}

__device__ __forceinline__ void cp_async16(uint32_t smaddr, const void* gptr) {
    asm volatile("cp.async.cg.shared.global [%0], [%1], 16;"
                 :: "r"(smaddr), "l"(gptr) : "memory");
}
#define CP_COMMIT() asm volatile("cp.async.commit_group;" ::: "memory")
#define CP_WAIT(n)  asm volatile("cp.async.wait_group %0;" :: "n"(n) : "memory")

__device__ __forceinline__ uint32_t smem_u32(const void* p) {
    uint32_t a;
    asm("{ .reg .u64 t; cvta.to.shared.u64 t, %1; cvt.u32.u64 %0, t; }" : "=r"(a) : "l"(p));
    return a;
}

// XOR swizzle within a k16 tile: bit7 -> bit4
__device__ __forceinline__ uint32_t swz(uint32_t o) { return o ^ ((o & 0x80u) >> 3); }

// ============================================================
// scratch (device globals)
// ============================================================
__device__ float d_conv[3][B_][IC_][H_][W_];
__device__ __align__(16) __half d_qh[B_][L_][F_];   // 10*log2e*q, fp16
__device__ __align__(16) __half d_kh[B_][L_][F_];
__device__ __align__(16) __half d_vth[B_][F_][L_];  // V transposed
__device__ float d_zi[B_][L_][F_];
__device__ float d_yvec[B_][C_][H_][W_];

// ============================================================
// Kernel 1: 1x1 convs at the mid depth slice only.
// ============================================================
__global__ void k_conv(const float* __restrict__ s, const float* __restrict__ g,
                       const float* __restrict__ gw, const float* __restrict__ gb,
                       const float* __restrict__ tw, const float* __restrict__ tb,
                       const float* __restrict__ pw, const float* __restrict__ pb) {
    __shared__ float wq[IC_ * C_], wv[IC_ * C_], wk[IC_ * C_];
    __shared__ float bq[IC_], bv[IC_], bk[IC_];
    const int tid = threadIdx.x;
    for (int i = tid; i < IC_ * C_; i += 128) { wq[i] = gw[i]; wv[i] = tw[i]; wk[i] = pw[i]; }
    if (tid < IC_) { bq[tid] = gb[tid]; bv[tid] = tb[tid]; bk[tid] = pb[tid]; }
    __syncthreads();

    const int y = blockIdx.x, b = blockIdx.y, x = tid;
    float aq[IC_], av[IC_], ak[IC_];
#pragma unroll
    for (int ic = 0; ic < IC_; ic++) { aq[ic] = bq[ic]; av[ic] = bv[ic]; ak[ic] = bk[ic]; }

    const size_t base = ((size_t)b * C_ * D_ + MID_) * (H_ * W_) + (size_t)y * W_ + x;
    const size_t cstride = (size_t)D_ * H_ * W_;
#pragma unroll 4
    for (int c = 0; c < C_; c++) {
        const float sv = s[base + c * cstride];
        const float gv = g[base + c * cstride];
#pragma unroll
        for (int ic = 0; ic < IC_; ic++) {
            aq[ic] += wq[ic * C_ + c] * sv;
            av[ic] += wv[ic * C_ + c] * gv;
            ak[ic] += wk[ic * C_ + c] * gv;
        }
    }
#pragma unroll
    for (int ic = 0; ic < IC_; ic++) {
        const int o = ((b * IC_ + ic) * H_ + y) * W_ + x;
        (&d_conv[0][0][0][0][0])[o] = aq[ic];
        (&d_conv[1][0][0][0][0])[o] = av[ic];
        (&d_conv[2][0][0][0][0])[o] = ak[ic];
    }
}

// ============================================================
// Kernel 2a: patches -> q (scaled by 10*log2e) and k, fp16.
// ============================================================
__global__ void k_patch_qk() {
    const int idx = blockIdx.x * 256 + threadIdx.x;
    const int f = idx % F_;
    const int t = idx / F_;
    const int l = t & (L_ - 1);
    const int b = t >> 12;
    const int c = f / 9;
    const int r = f - c * 9;
    const int ki = r / 3, kj = r - (r / 3) * 3;
    const int hp = l >> 6, wp = l & 63;
    const int y = hp * 2 - 1 + ki;
    const int x = wp * 2 - 1 + kj;
    const bool in = ((unsigned)y < (unsigned)H_) && ((unsigned)x < (unsigned)W_);
    const float q = in ? d_conv[0][b][c][y][x] : 0.0f;
    const float k = in ? d_conv[2][b][c][y][x] : 0.0f;
    d_qh[b][l][f] = __float2half_rn(q * (SCALE_ * LOG2E_));
    d_kh[b][l][f] = __float2half_rn(k);
}

// ============================================================
// Kernel 2b: patches -> V transposed [b][f][l], fp16.
// ============================================================
__global__ void k_patch_v() {
    const int idx = blockIdx.x * 256 + threadIdx.x;
    const int b = idx / (F_ * L_);
    const int rem = idx - b * (F_ * L_);
    const int f = rem / L_;
    const int l = rem - f * L_;
    const int c = f / 9;
    const int r = f - c * 9;
    const int ki = r / 3, kj = r - (r / 3) * 3;
    const int hp = l >> 6, wp = l & 63;
    const int y = hp * 2 - 1 + ki;
    const int x = wp * 2 - 1 + kj;
    const bool in = ((unsigned)y < (unsigned)H_) && ((unsigned)x < (unsigned)W_);
    const float v = in ? d_conv[1][b][c][y][x] : 0.0f;
    d_vth[b][f][l] = __float2half_rn(v);
}

// ============================================================
// Kernel 3: FUSED online-flash attention.
// grid (32 row-tiles, B) = 128 CTAs, 512 threads = 16 warps.
// S-phase: 4x4 warps, 32x32 tiles; PV-phase: 8x2 warps, 16x72 tiles.
// Q resident; K/V 128-col chunks double-buffered; P chunk-local in smem.
// ============================================================
__global__ __launch_bounds__(512, 1) void k_flash() {
    extern __shared__ char smc[];
    __shared__ float redbuf[4][128];
    const uint32_t sbase = smem_u32(smc);
    float* alphas = (float*)(smc + ST_OFF);
    float* mrun   = alphas + 128;
    float* lrun   = mrun + 128;

    const int tid = threadIdx.x;
    const int lane = tid & 31;
    const int warp = tid >> 5;
    const int swr = warp >> 2, swc = warp & 3;   // S layout
    const int pwr = warp >> 1, pwc = warp & 1;   // PV layout
    const int g = lane >> 2;
    const int t = lane & 3;
    const int b = blockIdx.y;
    const int row0 = blockIdx.x * 128;

    if (tid < 128) { mrun[tid] = -1e30f; lrun[tid] = 0.f; }

    float O[9][4];
#pragma unroll
    for (int n = 0; n < 9; n++)
#pragma unroll
        for (int j = 0; j < 4; j++) O[n][j] = 0.f;

    // prologue: Q (resident) + K chunk 0 + V chunk 0
    for (int e = tid; e < 128 * 18; e += 512) {
        const int r = e / 18, u = e - (e / 18) * 18;
        const int k16 = u >> 1, h = u & 1;
        const uint32_t o = (uint32_t)k16 * TILE_B + swz((uint32_t)(r * 32 + h * 16));
        const int fc = k16 * 16 + h * 8;
        cp_async16(sbase + Q_OFF + o, &d_qh[b][row0 + r][fc]);
        cp_async16(sbase + K_OFF + o, &d_kh[b][r][fc]);
    }
    for (int e = tid; e < 144 * 16; e += 512) {
        const int f = e >> 4, u = e & 15;
        const int k16 = u >> 1, h = u & 1;
        const uint32_t o = (uint32_t)k16 * VTILE_B + swz((uint32_t)(f * 32 + h * 16));
        cp_async16(sbase + V_OFF + o, &d_vth[b][f][k16 * 16 + h * 8]);
    }
    CP_COMMIT();

    // LDSM lane offsets
    uint32_t aoffS[2], boffS[2];
#pragma unroll
    for (int m = 0; m < 2; m++)
        aoffS[m] = swz((uint32_t)((swr * 32 + m * 16 + (lane & 15)) * 32 + ((lane >> 4) & 1) * 16));
#pragma unroll
    for (int n16 = 0; n16 < 2; n16++)
        boffS[n16] = swz((uint32_t)((swc * 32 + n16 * 16 + (lane & 7) + ((lane >> 4) << 3)) * 32 +
                                    (((lane >> 3) & 1) << 4)));
    const uint32_t aoffP = swz((uint32_t)((pwr * 16 + (lane & 15)) * 32 + ((lane >> 4) & 1) * 16));
    uint32_t boffV[4];
#pragma unroll
    for (int p = 0; p < 4; p++)
        boffV[p] = swz((uint32_t)((pwc * 72 + p * 16 + (lane & 7) + ((lane >> 4) << 3)) * 32 +
                                  (((lane >> 3) & 1) << 4)));
    const uint32_t boffV2 = swz((uint32_t)((pwc * 72 + 64 + (lane & 7)) * 32 +
                                           (((lane >> 3) & 1) << 4)));

    const uint32_t Qb = sbase + Q_OFF;
    const uint32_t Pb = sbase + P_OFF;

    for (int ct = 0; ct < 32; ct++) {
        const int buf = ct & 1;
        CP_WAIT(0);
        __syncthreads();   // K/V[buf] ready; previous chunk's P fully consumed

        // issue next K/V chunk into other buffer
        if (ct < 31) {
            const int c1 = (ct + 1) * 128;
            const uint32_t kb1 = sbase + K_OFF + (uint32_t)(buf ^ 1) * 36864;
            const uint32_t vb1 = sbase + V_OFF + (uint32_t)(buf ^ 1) * 36864;
            for (int e = tid; e < 128 * 18; e += 512) {
                const int r = e / 18, u = e - (e / 18) * 18;
                const int k16 = u >> 1, h = u & 1;
                const uint32_t o = (uint32_t)k16 * TILE_B + swz((uint32_t)(r * 32 + h * 16));
                cp_async16(kb1 + o, &d_kh[b][c1 + r][k16 * 16 + h * 8]);
            }
            for (int e = tid; e < 144 * 16; e += 512) {
                const int f = e >> 4, u = e & 15;
                const int k16 = u >> 1, h = u & 1;
                const uint32_t o = (uint32_t)k16 * VTILE_B + swz((uint32_t)(f * 32 + h * 16));
                cp_async16(vb1 + o, &d_vth[b][f][c1 + k16 * 16 + h * 8]);
            }
            CP_COMMIT();
        }

        const uint32_t Kb = sbase + K_OFF + (uint32_t)buf * 36864;
        const uint32_t Vb = sbase + V_OFF + (uint32_t)buf * 36864;

        // ---- S = Q' K^T (base-2 logits) ----
        float acc[2][4][4];
#pragma unroll
        for (int m = 0; m < 2; m++)
#pragma unroll
            for (int n = 0; n < 4; n++)
#pragma unroll
                for (int j = 0; j < 4; j++) acc[m][n][j] = 0.f;

#pragma unroll
        for (int k16 = 0; k16 < 9; k16++) {
            const uint32_t tb = (uint32_t)k16 * TILE_B;
            uint32_t a[2][4], bb[2][4];
            ldsm_x4(a[0], Qb + tb + aoffS[0]);
            ldsm_x4(a[1], Qb + tb + aoffS[1]);
            ldsm_x4(bb[0], Kb + tb + boffS[0]);
            ldsm_x4(bb[1], Kb + tb + boffS[1]);
#pragma unroll
            for (int m = 0; m < 2; m++) {
                mma16816(acc[m][0], a[m], bb[0][0], bb[0][1]);
                mma16816(acc[m][1], a[m], bb[0][2], bb[0][3]);
                mma16816(acc[m][2], a[m], bb[1][0], bb[1][1]);
                mma16816(acc[m][3], a[m], bb[1][2], bb[1][3]);
            }
        }

        // ---- row max (32 cols per warp -> cross-wc via redbuf) ----
#pragma unroll
        for (int ri = 0; ri < 4; ri++) {
            const int m = ri >> 1, jb = (ri & 1) * 2;
            const int row = swr * 32 + (ri >> 1) * 16 + (ri & 1) * 8 + g;
            float mx = acc[m][0][jb];
#pragma unroll
            for (int n = 0; n < 4; n++)
                mx = fmaxf(mx, fmaxf(acc[m][n][jb], acc[m][n][jb + 1]));
            mx = fmaxf(mx, __shfl_xor_sync(0xffffffffu, mx, 1));
            mx = fmaxf(mx, __shfl_xor_sync(0xffffffffu, mx, 2));
            if (t == 0) redbuf[swc][row] = mx;
        }
        __syncthreads();

        if (tid < 128) {
            const float mold = mrun[tid];
            const float mnew = fmaxf(mold,
                fmaxf(fmaxf(redbuf[0][tid], redbuf[1][tid]),
                      fmaxf(redbuf[2][tid], redbuf[3][tid])));
            mrun[tid] = mnew;
            alphas[tid] = exp2f(mold - mnew);
        }
        __syncthreads();

        // ---- P = exp2(S - m) into smem; partial sums; O rescale ----
#pragma unroll
        for (int ri = 0; ri < 4; ri++) {
            const int m = ri >> 1, jb = (ri & 1) * 2;
            const int row = swr * 32 + (ri >> 1) * 16 + (ri & 1) * 8 + g;
            const float mx = mrun[row];
            float sum = 0.f;
#pragma unroll
            for (int n = 0; n < 4; n++) {
                const float e0 = exp2f(acc[m][n][jb] - mx);
                const float e1 = exp2f(acc[m][n][jb + 1] - mx);
                sum += e0 + e1;
                const int col = swc * 32 + n * 8 + t * 2;
                const uint32_t off = (uint32_t)(col >> 4) * TILE_B +
                                     swz((uint32_t)(row * 32 + (col & 15) * 2));
                *(__half2*)(smc + P_OFF + off) = __floats2half2_rn(e0, e1);
            }
            sum += __shfl_xor_sync(0xffffffffu, sum, 1);
            sum += __shfl_xor_sync(0xffffffffu, sum, 2);
            if (t == 0) redbuf[swc][row] = sum;
        }
        {
            const float alA = alphas[pwr * 16 + g];
            const float alB = alphas[pwr * 16 + g + 8];
#pragma unroll
            for (int n = 0; n < 9; n++) {
                O[n][0] *= alA; O[n][1] *= alA;
                O[n][2] *= alB; O[n][3] *= alB;
            }
        }
        __syncthreads();

        if (tid < 128)
            lrun[tid] = lrun[tid] * alphas[tid] +
                        (redbuf[0][tid] + redbuf[1][tid]) +
                        (redbuf[2][tid] + redbuf[3][tid]);

        // ---- O += P V (8 k16) ----
#pragma unroll
        for (int k16 = 0; k16 < 8; k16++) {
            const uint32_t ptb = Pb + (uint32_t)k16 * TILE_B;
            const uint32_t vtb = Vb + (uint32_t)k16 * VTILE_B;
            uint32_t a[4];
            ldsm_x4(a, ptb + aoffP);
#pragma unroll
            for (int p = 0; p < 4; p++) {
                uint32_t bb[4];
                ldsm_x4(bb, vtb + boffV[p]);
                mma16816(O[2 * p],     a, bb[0], bb[1]);
                mma16816(O[2 * p + 1], a, bb[2], bb[3]);
            }
            {
                uint32_t bs[2];
                ldsm_x2(bs, vtb + boffV2);
                mma16816(O[8], a, bs[0], bs[1]);
            }
        }
        // chunk-top sync protects P/stats/redbuf for the next iteration
    }

    __syncthreads();   // lrun final values visible to all
    {
        const int rA = pwr * 16 + g;
        const int rB = rA + 8;
        const float liA = 1.0f / lrun[rA];
        const float liB = 1.0f / lrun[rB];
#pragma unroll
        for (int n = 0; n < 9; n++) {
            const int col = pwc * 72 + n * 8 + t * 2;
            *(float2*)&d_zi[b][row0 + rA][col] = make_float2(O[n][0] * liA, O[n][1] * liA);
            *(float2*)&d_zi[b][row0 + rB][col] = make_float2(O[n][2] * liB, O[n][3] * liB);
        }
    }
}

// ============================================================
// Kernel 4: fold (overlap-add + count normalize) + W_w conv -> yvec
// ============================================================
__global__ void k_fold(const float* __restrict__ Wmat, const float* __restrict__ Wb) {
    __shared__ float zs[IC_][W_];
    __shared__ float wsm[C_ * IC_];
    __shared__ float bsm[C_];
    const int x = threadIdx.x;
    const int y = blockIdx.x, b = blockIdx.y;
    for (int i = x; i < C_ * IC_; i += 128) wsm[i] = Wmat[i];
    if (x < C_) bsm[x] = Wb[x];

    float v[IC_];
#pragma unroll
    for (int ic = 0; ic < IC_; ic++) v[ic] = 0.f;
    int cnt = 0;
#pragma unroll
    for (int i = 0; i < 3; i++) {
        const int tY = y + 1 - i;
        if (tY < 0 || (tY & 1) || (tY >> 1) >= HP_) continue;
        const int hp = tY >> 1;
#pragma unroll
        for (int j = 0; j < 3; j++) {
            const int tX = x + 1 - j;
            if (tX < 0 || (tX & 1) || (tX >> 1) >= HP_) continue;
            const int wp = tX >> 1;
            const float* zrow = &d_zi[b][hp * 64 + wp][0];
            cnt++;
#pragma unroll
            for (int ic = 0; ic < IC_; ic++) v[ic] += zrow[ic * 9 + i * 3 + j];
        }
    }
    const float invc = 1.0f / (float)cnt;
#pragma unroll
    for (int ic = 0; ic < IC_; ic++) zs[ic][x] = v[ic] * invc;
    __syncthreads();

    for (int o = 0; o < C_; o++) {
        float a = bsm[o];
#pragma unroll
        for (int ic = 0; ic < IC_; ic++) a += wsm[o * IC_ + ic] * zs[ic][x];
        d_yvec[b][o][y][x] = a;
    }
}

// ============================================================
// Kernel 5: out = s + yvec (broadcast over D)
// ============================================================
__global__ void k_out(const float* __restrict__ s, float* __restrict__ out) {
    const int idx = blockIdx.x * 256 + threadIdx.x;
    const int pix = idx & (H_ * W_ - 1);
    const int bo = (idx >> 14) >> 3;  // b*64 + o
    out[idx] = s[idx] + (&d_yvec[0][0][0][0])[bo * (H_ * W_) + pix];
}

// ============================================================
extern "C" void kernel_launch(void* const* d_in, const int* /*in_sizes*/, int /*n_in*/,
                              void* d_out, int /*out_size*/) {
    const float* s   = (const float*)d_in[0];
    const float* g   = (const float*)d_in[1];
    const float* g_w = (const float*)d_in[2];
    const float* g_b = (const float*)d_in[3];
    const float* t_w = (const float*)d_in[4];
    const float* t_b = (const float*)d_in[5];
    const float* p_w = (const float*)d_in[6];
    const float* p_b = (const float*)d_in[7];
    const float* W_w = (const float*)d_in[8];
    const float* W_b = (const float*)d_in[9];
    float* out = (float*)d_out;

    cudaFuncSetAttribute(k_flash, cudaFuncAttributeMaxDynamicSharedMemorySize, FLASH_SMEM);

    k_conv<<<dim3(H_, B_), 128>>>(s, g, g_w, g_b, t_w, t_b, p_w, p_b);
    k_patch_qk<<<(B_ * L_ * F_) / 256, 256>>>();
    k_patch_v<<<(B_ * F_ * L_) / 256, 256>>>();

    k_flash<<<dim3(32, B_), 512, FLASH_SMEM>>>();

    k_fold<<<dim3(H_, B_), 128>>>(W_w, W_b);
    k_out<<<(B_ * C_ * D_ * H_ * W_) / 256, 256>>>(s, out);
}

// round 12
// speedup vs baseline: 4.7825x; 1.0009x over previous
#include <cuda_runtime.h>
#include <cuda_fp16.h>
#include <cstdint>

namespace {
constexpr int B_  = 4;
constexpr int C_  = 64;
constexpr int IC_ = 16;
constexpr int D_  = 8;
constexpr int H_  = 128;
constexpr int W_  = 128;
constexpr int MID_ = 4;
constexpr int HP_ = 64;
constexpr int L_  = 4096;
constexpr int F_  = 144;    // IC*3*3 = 9 * 16
constexpr float SCALE_ = 10.0f;
constexpr float LOG2E_ = 1.4426950408889634f;

// flash smem layout (bytes), k16-tiled swizzled operands
constexpr int TILE_B  = 4096;                 // 128 rows x 32B (Q/K/P)
constexpr int VTILE_B = 4608;                 // 144 rows x 32B (V)
constexpr int Q_OFF = 0;                      // 9*4096 = 36864
constexpr int K_OFF = 36864;                  // 2 bufs x 36864
constexpr int V_OFF = K_OFF + 2 * 36864;      // 110592; 2 bufs x 8*4608
constexpr int P_OFF = V_OFF + 2 * 36864;      // 184320; 8*4096 = 32768
constexpr int ST_OFF = P_OFF + 32768;         // 217088; alphas/lrun 2*512
constexpr int FLASH_SMEM = ST_OFF + 1024;     // 218112
}

// ============================================================
// helpers
// ============================================================
__device__ __forceinline__ void mma16816(float* c, const uint32_t* a,
                                         uint32_t b0, uint32_t b1) {
    asm volatile(
        "mma.sync.aligned.m16n8k16.row.col.f32.f16.f16.f32 "
        "{%0,%1,%2,%3}, {%4,%5,%6,%7}, {%8,%9}, {%0,%1,%2,%3};"
        : "+f"(c[0]), "+f"(c[1]), "+f"(c[2]), "+f"(c[3])
        : "r"(a[0]), "r"(a[1]), "r"(a[2]), "r"(a[3]), "r"(b0), "r"(b1));
}

__device__ __forceinline__ void ldsm_x4(uint32_t* r, uint32_t smaddr) {
    asm volatile("ldmatrix.sync.aligned.m8n8.x4.shared.b16 {%0,%1,%2,%3}, [%4];"
                 : "=r"(r[0]), "=r"(r[1]), "=r"(r[2]), "=r"(r[3]) : "r"(smaddr));
}
__device__ __forceinline__ void ldsm_x2(uint32_t* r, uint32_t smaddr) {
    asm volatile("ldmatrix.sync.aligned.m8n8.x2.shared.b16 {%0,%1}, [%2];"
                 : "=r"(r[0]), "=r"(r[1]) : "r"(smaddr));
}

__device__ __forceinline__ void cp_async16(uint32_t smaddr, const void* gptr) {
    asm volatile("cp.async.cg.shared.global [%0], [%1], 16;"
                 :: "r"(smaddr), "l"(gptr) : "memory");
}
#define CP_COMMIT() asm volatile("cp.async.commit_group;" ::: "memory")
#define CP_WAIT(n)  asm volatile("cp.async.wait_group %0;" :: "n"(n) : "memory")

__device__ __forceinline__ uint32_t smem_u32(const void* p) {
    uint32_t a;
    asm("{ .reg .u64 t; cvta.to.shared.u64 t, %1; cvt.u32.u64 %0, t; }" : "=r"(a) : "l"(p));
    return a;
}

// XOR swizzle within a k16 tile: bit7 -> bit4
__device__ __forceinline__ uint32_t swz(uint32_t o) { return o ^ ((o & 0x80u) >> 3); }

// ============================================================
// scratch (device globals)
// ============================================================
__device__ float d_conv[3][B_][IC_][H_][W_];
__device__ __align__(16) __half d_qh[B_][L_][F_];   // 10*log2e*q, fp16
__device__ __align__(16) __half d_kh[B_][L_][F_];
__device__ __align__(16) __half d_vth[B_][F_][L_];  // V transposed
__device__ float d_zi[B_][L_][F_];

// ============================================================
// Kernel 1: 1x1 convs at the mid depth slice only.
// ============================================================
__global__ void k_conv(const float* __restrict__ s, const float* __restrict__ g,
                       const float* __restrict__ gw, const float* __restrict__ gb,
                       const float* __restrict__ tw, const float* __restrict__ tb,
                       const float* __restrict__ pw, const float* __restrict__ pb) {
    __shared__ float wq[IC_ * C_], wv[IC_ * C_], wk[IC_ * C_];
    __shared__ float bq[IC_], bv[IC_], bk[IC_];
    const int tid = threadIdx.x;
    for (int i = tid; i < IC_ * C_; i += 128) { wq[i] = gw[i]; wv[i] = tw[i]; wk[i] = pw[i]; }
    if (tid < IC_) { bq[tid] = gb[tid]; bv[tid] = tb[tid]; bk[tid] = pb[tid]; }
    __syncthreads();

    const int y = blockIdx.x, b = blockIdx.y, x = tid;
    float aq[IC_], av[IC_], ak[IC_];
#pragma unroll
    for (int ic = 0; ic < IC_; ic++) { aq[ic] = bq[ic]; av[ic] = bv[ic]; ak[ic] = bk[ic]; }

    const size_t base = ((size_t)b * C_ * D_ + MID_) * (H_ * W_) + (size_t)y * W_ + x;
    const size_t cstride = (size_t)D_ * H_ * W_;
#pragma unroll 4
    for (int c = 0; c < C_; c++) {
        const float sv = s[base + c * cstride];
        const float gv = g[base + c * cstride];
#pragma unroll
        for (int ic = 0; ic < IC_; ic++) {
            aq[ic] += wq[ic * C_ + c] * sv;
            av[ic] += wv[ic * C_ + c] * gv;
            ak[ic] += wk[ic * C_ + c] * gv;
        }
    }
#pragma unroll
    for (int ic = 0; ic < IC_; ic++) {
        const int o = ((b * IC_ + ic) * H_ + y) * W_ + x;
        (&d_conv[0][0][0][0][0])[o] = aq[ic];
        (&d_conv[1][0][0][0][0])[o] = av[ic];
        (&d_conv[2][0][0][0][0])[o] = ak[ic];
    }
}

// ============================================================
// Kernel 2: patch extraction, locality-tiled.
// grid (HP_, B_), 128 threads. Block handles one hp row (64 wp positions):
// q/k staged [wp][144] then coalesced uint4 writeout; v staged [f][64].
// ============================================================
__global__ void k_patch() {
    __shared__ __half q_s[64][F_];   // 18432 B
    __shared__ __half k_s[64][F_];   // 18432 B
    const int hp = blockIdx.x, b = blockIdx.y;
    const int tid = threadIdx.x;

    // phase 1: compute q,k patches (8 f per item, one wp)
    for (int e = tid; e < 64 * 18; e += 128) {
        const int wp = e / 18, u = e - (e / 18) * 18;
        __half qv[8], kv[8];
#pragma unroll
        for (int j = 0; j < 8; j++) {
            const int f = u * 8 + j;
            const int c = f / 9, r = f - (f / 9) * 9;
            const int ki = r / 3, kj = r - (r / 3) * 3;
            const int y = hp * 2 - 1 + ki;
            const int x = wp * 2 - 1 + kj;
            const bool in = ((unsigned)y < (unsigned)H_) && ((unsigned)x < (unsigned)W_);
            const float q = in ? d_conv[0][b][c][y][x] : 0.0f;
            const float k = in ? d_conv[2][b][c][y][x] : 0.0f;
            qv[j] = __float2half_rn(q * (SCALE_ * LOG2E_));
            kv[j] = __float2half_rn(k);
        }
        *(uint4*)&q_s[wp][u * 8] = *(uint4*)qv;
        *(uint4*)&k_s[wp][u * 8] = *(uint4*)kv;
    }
    __syncthreads();

    // phase 2: coalesced writeout of q,k
    for (int e = tid; e < 64 * 18; e += 128) {
        const int wp = e / 18, u = e - (e / 18) * 18;
        const int l = hp * 64 + wp;
        *(uint4*)&d_qh[b][l][u * 8] = *(const uint4*)&q_s[wp][u * 8];
        *(uint4*)&d_kh[b][l][u * 8] = *(const uint4*)&k_s[wp][u * 8];
    }
    __syncthreads();

    // phase 3: v patches, f-major staging (reuse q_s as [144][64])
    __half* v_s = &q_s[0][0];
    for (int e = tid; e < F_ * 8; e += 128) {
        const int f = e >> 3, u = e & 7;
        const int c = f / 9, r = f - (f / 9) * 9;
        const int ki = r / 3, kj = r - (r / 3) * 3;
        const int y = hp * 2 - 1 + ki;
        __half vv[8];
#pragma unroll
        for (int j = 0; j < 8; j++) {
            const int wp = u * 8 + j;
            const int x = wp * 2 - 1 + kj;
            const bool in = ((unsigned)y < (unsigned)H_) && ((unsigned)x < (unsigned)W_);
            vv[j] = __float2half_rn(in ? d_conv[1][b][c][y][x] : 0.0f);
        }
        *(uint4*)&v_s[f * 64 + u * 8] = *(uint4*)vv;
    }
    __syncthreads();
    for (int e = tid; e < F_ * 8; e += 128) {
        const int f = e >> 3, u = e & 7;
        *(uint4*)&d_vth[b][f][hp * 64 + u * 8] = *(const uint4*)&v_s[f * 64 + u * 8];
    }
}

// ============================================================
// Kernel 3: FUSED online-flash attention.
// grid (32 row-tiles, B) = 128 CTAs, 512 threads = 16 warps.
// S-phase: 4x4 warps 32x32; PV-phase: 8x2 warps 16x72.
// Per-thread running row-max registers; 3 syncs per chunk.
// ============================================================
__global__ __launch_bounds__(512, 1) void k_flash() {
    extern __shared__ char smc[];
    __shared__ float redmax[4][128];
    __shared__ float redsum[4][128];
    const uint32_t sbase = smem_u32(smc);
    float* alphas = (float*)(smc + ST_OFF);
    float* lrun   = alphas + 128;

    const int tid = threadIdx.x;
    const int lane = tid & 31;
    const int warp = tid >> 5;
    const int swr = warp >> 2, swc = warp & 3;   // S layout
    const int pwr = warp >> 1, pwc = warp & 1;   // PV layout
    const int g = lane >> 2;
    const int t = lane & 3;
    const int b = blockIdx.y;
    const int row0 = blockIdx.x * 128;

    if (tid < 128) lrun[tid] = 0.f;

    float O[9][4];
#pragma unroll
    for (int n = 0; n < 9; n++)
#pragma unroll
        for (int j = 0; j < 4; j++) O[n][j] = 0.f;

    float mrow[4];
#pragma unroll
    for (int ri = 0; ri < 4; ri++) mrow[ri] = -1e30f;

    // row index per ri (S layout)
    int rowIdx[4];
#pragma unroll
    for (int ri = 0; ri < 4; ri++)
        rowIdx[ri] = swr * 32 + (ri >> 1) * 16 + (ri & 1) * 8 + g;

    // prologue: Q (resident) + K chunk 0 + V chunk 0
    for (int e = tid; e < 128 * 18; e += 512) {
        const int r = e / 18, u = e - (e / 18) * 18;
        const int k16 = u >> 1, h = u & 1;
        const uint32_t o = (uint32_t)k16 * TILE_B + swz((uint32_t)(r * 32 + h * 16));
        const int fc = k16 * 16 + h * 8;
        cp_async16(sbase + Q_OFF + o, &d_qh[b][row0 + r][fc]);
        cp_async16(sbase + K_OFF + o, &d_kh[b][r][fc]);
    }
    for (int e = tid; e < 144 * 16; e += 512) {
        const int f = e >> 4, u = e & 15;
        const int k16 = u >> 1, h = u & 1;
        const uint32_t o = (uint32_t)k16 * VTILE_B + swz((uint32_t)(f * 32 + h * 16));
        cp_async16(sbase + V_OFF + o, &d_vth[b][f][k16 * 16 + h * 8]);
    }
    CP_COMMIT();

    // LDSM lane offsets
    uint32_t aoffS[2], boffS[2];
#pragma unroll
    for (int m = 0; m < 2; m++)
        aoffS[m] = swz((uint32_t)((swr * 32 + m * 16 + (lane & 15)) * 32 + ((lane >> 4) & 1) * 16));
#pragma unroll
    for (int n16 = 0; n16 < 2; n16++)
        boffS[n16] = swz((uint32_t)((swc * 32 + n16 * 16 + (lane & 7) + ((lane >> 4) << 3)) * 32 +
                                    (((lane >> 3) & 1) << 4)));
    const uint32_t aoffP = swz((uint32_t)((pwr * 16 + (lane & 15)) * 32 + ((lane >> 4) & 1) * 16));
    uint32_t boffV[4];
#pragma unroll
    for (int p = 0; p < 4; p++)
        boffV[p] = swz((uint32_t)((pwc * 72 + p * 16 + (lane & 7) + ((lane >> 4) << 3)) * 32 +
                                  (((lane >> 3) & 1) << 4)));
    const uint32_t boffV2 = swz((uint32_t)((pwc * 72 + 64 + (lane & 7)) * 32 +
                                           (((lane >> 3) & 1) << 4)));

    const uint32_t Qb = sbase + Q_OFF;
    const uint32_t Pb = sbase + P_OFF;

    for (int ct = 0; ct < 32; ct++) {
        const int buf = ct & 1;
        CP_WAIT(0);
        __syncthreads();   // (C) K/V[buf] ready; prior P/red/lrun consumers done

        // issue next K/V chunk into other buffer
        if (ct < 31) {
            const int c1 = (ct + 1) * 128;
            const uint32_t kb1 = sbase + K_OFF + (uint32_t)(buf ^ 1) * 36864;
            const uint32_t vb1 = sbase + V_OFF + (uint32_t)(buf ^ 1) * 36864;
            for (int e = tid; e < 128 * 18; e += 512) {
                const int r = e / 18, u = e - (e / 18) * 18;
                const int k16 = u >> 1, h = u & 1;
                const uint32_t o = (uint32_t)k16 * TILE_B + swz((uint32_t)(r * 32 + h * 16));
                cp_async16(kb1 + o, &d_kh[b][c1 + r][k16 * 16 + h * 8]);
            }
            for (int e = tid; e < 144 * 16; e += 512) {
                const int f = e >> 4, u = e & 15;
                const int k16 = u >> 1, h = u & 1;
                const uint32_t o = (uint32_t)k16 * VTILE_B + swz((uint32_t)(f * 32 + h * 16));
                cp_async16(vb1 + o, &d_vth[b][f][c1 + k16 * 16 + h * 8]);
            }
            CP_COMMIT();
        }

        const uint32_t Kb = sbase + K_OFF + (uint32_t)buf * 36864;
        const uint32_t Vb = sbase + V_OFF + (uint32_t)buf * 36864;

        // ---- S = Q' K^T (base-2 logits) ----
        float acc[2][4][4];
#pragma unroll
        for (int m = 0; m < 2; m++)
#pragma unroll
            for (int n = 0; n < 4; n++)
#pragma unroll
                for (int j = 0; j < 4; j++) acc[m][n][j] = 0.f;

#pragma unroll
        for (int k16 = 0; k16 < 9; k16++) {
            const uint32_t tb = (uint32_t)k16 * TILE_B;
            uint32_t a[2][4], bb[2][4];
            ldsm_x4(a[0], Qb + tb + aoffS[0]);
            ldsm_x4(a[1], Qb + tb + aoffS[1]);
            ldsm_x4(bb[0], Kb + tb + boffS[0]);
            ldsm_x4(bb[1], Kb + tb + boffS[1]);
#pragma unroll
            for (int m = 0; m < 2; m++) {
                mma16816(acc[m][0], a[m], bb[0][0], bb[0][1]);
                mma16816(acc[m][1], a[m], bb[0][2], bb[0][3]);
                mma16816(acc[m][2], a[m], bb[1][0], bb[1][1]);
                mma16816(acc[m][3], a[m], bb[1][2], bb[1][3]);
            }
        }

        // ---- warp-local row max into redmax ----
#pragma unroll
        for (int ri = 0; ri < 4; ri++) {
            const int m = ri >> 1, jb = (ri & 1) * 2;
            float mx = acc[m][0][jb];
#pragma unroll
            for (int n = 0; n < 4; n++)
                mx = fmaxf(mx, fmaxf(acc[m][n][jb], acc[m][n][jb + 1]));
            mx = fmaxf(mx, __shfl_xor_sync(0xffffffffu, mx, 1));
            mx = fmaxf(mx, __shfl_xor_sync(0xffffffffu, mx, 2));
            if (t == 0) redmax[swc][rowIdx[ri]] = mx;
        }
        __syncthreads();   // (A)

        // ---- P = exp2(S - m) into smem; alphas; partial sums ----
#pragma unroll
        for (int ri = 0; ri < 4; ri++) {
            const int m = ri >> 1, jb = (ri & 1) * 2;
            const int row = rowIdx[ri];
            const float mnew = fmaxf(mrow[ri],
                fmaxf(fmaxf(redmax[0][row], redmax[1][row]),
                      fmaxf(redmax[2][row], redmax[3][row])));
            const float alpha = exp2f(mrow[ri] - mnew);
            mrow[ri] = mnew;
            float sum = 0.f;
#pragma unroll
            for (int n = 0; n < 4; n++) {
                const float e0 = exp2f(acc[m][n][jb] - mnew);
                const float e1 = exp2f(acc[m][n][jb + 1] - mnew);
                sum += e0 + e1;
                const int col = swc * 32 + n * 8 + t * 2;
                const uint32_t off = (uint32_t)(col >> 4) * TILE_B +
                                     swz((uint32_t)(row * 32 + (col & 15) * 2));
                *(__half2*)(smc + P_OFF + off) = __floats2half2_rn(e0, e1);
            }
            sum += __shfl_xor_sync(0xffffffffu, sum, 1);
            sum += __shfl_xor_sync(0xffffffffu, sum, 2);
            if (t == 0) {
                redsum[swc][row] = sum;
                if (swc == 0) alphas[row] = alpha;
            }
        }
        __syncthreads();   // (B)

        if (tid < 128)
            lrun[tid] = lrun[tid] * alphas[tid] +
                        (redsum[0][tid] + redsum[1][tid]) +
                        (redsum[2][tid] + redsum[3][tid]);

        // ---- O rescale + O += P V (8 k16) ----
        {
            const float alA = alphas[pwr * 16 + g];
            const float alB = alphas[pwr * 16 + g + 8];
#pragma unroll
            for (int n = 0; n < 9; n++) {
                O[n][0] *= alA; O[n][1] *= alA;
                O[n][2] *= alB; O[n][3] *= alB;
            }
        }
#pragma unroll
        for (int k16 = 0; k16 < 8; k16++) {
            const uint32_t ptb = Pb + (uint32_t)k16 * TILE_B;
            const uint32_t vtb = Vb + (uint32_t)k16 * VTILE_B;
            uint32_t a[4];
            ldsm_x4(a, ptb + aoffP);
#pragma unroll
            for (int p = 0; p < 4; p++) {
                uint32_t bb[4];
                ldsm_x4(bb, vtb + boffV[p]);
                mma16816(O[2 * p],     a, bb[0], bb[1]);
                mma16816(O[2 * p + 1], a, bb[2], bb[3]);
            }
            {
                uint32_t bs[2];
                ldsm_x2(bs, vtb + boffV2);
                mma16816(O[8], a, bs[0], bs[1]);
            }
        }
    }

    __syncthreads();   // lrun final values visible to all
    {
        const int rA = pwr * 16 + g;
        const int rB = rA + 8;
        const float liA = 1.0f / lrun[rA];
        const float liB = 1.0f / lrun[rB];
#pragma unroll
        for (int n = 0; n < 9; n++) {
            const int col = pwc * 72 + n * 8 + t * 2;
            *(float2*)&d_zi[b][row0 + rA][col] = make_float2(O[n][0] * liA, O[n][1] * liA);
            *(float2*)&d_zi[b][row0 + rB][col] = make_float2(O[n][2] * liB, O[n][3] * liB);
        }
    }
}

// ============================================================
// Kernel 4: fold + W_w conv + residual add -> out (all 8 depths).
// grid (H, B), 128 threads.
// ============================================================
__global__ void k_foldout(const float* __restrict__ s, float* __restrict__ out,
                          const float* __restrict__ Wmat, const float* __restrict__ Wb) {
    __shared__ float zs[IC_][W_];
    __shared__ float wsm[C_ * IC_];
    __shared__ float bsm[C_];
    const int x = threadIdx.x;
    const int y = blockIdx.x, b = blockIdx.y;
    for (int i = x; i < C_ * IC_; i += 128) wsm[i] = Wmat[i];
    if (x < C_) bsm[x] = Wb[x];

    float v[IC_];
#pragma unroll
    for (int ic = 0; ic < IC_; ic++) v[ic] = 0.f;
    int cnt = 0;
#pragma unroll
    for (int i = 0; i < 3; i++) {
        const int tY = y + 1 - i;
        if (tY < 0 || (tY & 1) || (tY >> 1) >= HP_) continue;
        const int hp = tY >> 1;
#pragma unroll
        for (int j = 0; j < 3; j++) {
            const int tX = x + 1 - j;
            if (tX < 0 || (tX & 1) || (tX >> 1) >= HP_) continue;
            const int wp = tX >> 1;
            const float* zrow = &d_zi[b][hp * 64 + wp][0];
            cnt++;
#pragma unroll
            for (int ic = 0; ic < IC_; ic++) v[ic] += zrow[ic * 9 + i * 3 + j];
        }
    }
    const float invc = 1.0f / (float)cnt;
#pragma unroll
    for (int ic = 0; ic < IC_; ic++) zs[ic][x] = v[ic] * invc;
    __syncthreads();

    for (int o = 0; o < C_; o++) {
        float a = bsm[o];
#pragma unroll
        for (int ic = 0; ic < IC_; ic++) a += wsm[o * IC_ + ic] * zs[ic][x];
        const size_t base = ((size_t)(b * C_ + o) * D_) * (H_ * W_) + (size_t)y * W_ + x;
#pragma unroll
        for (int d = 0; d < D_; d++)
            out[base + (size_t)d * (H_ * W_)] = s[base + (size_t)d * (H_ * W_)] + a;
    }
}

// ============================================================
extern "C" void kernel_launch(void* const* d_in, const int* /*in_sizes*/, int /*n_in*/,
                              void* d_out, int /*out_size*/) {
    const float* s   = (const float*)d_in[0];
    const float* g   = (const float*)d_in[1];
    const float* g_w = (const float*)d_in[2];
    const float* g_b = (const float*)d_in[3];
    const float* t_w = (const float*)d_in[4];
    const float* t_b = (const float*)d_in[5];
    const float* p_w = (const float*)d_in[6];
    const float* p_b = (const float*)d_in[7];
    const float* W_w = (const float*)d_in[8];
    const float* W_b = (const float*)d_in[9];
    float* out = (float*)d_out;

    cudaFuncSetAttribute(k_flash, cudaFuncAttributeMaxDynamicSharedMemorySize, FLASH_SMEM);

    k_conv<<<dim3(H_, B_), 128>>>(s, g, g_w, g_b, t_w, t_b, p_w, p_b);
    k_patch<<<dim3(HP_, B_), 128>>>();

    k_flash<<<dim3(32, B_), 512, FLASH_SMEM>>>();

    k_foldout<<<dim3(H_, B_), 128>>>(s, out, W_w, W_b);
}

// round 13
// speedup vs baseline: 5.4003x; 1.1292x over previous
#include <cuda_runtime.h>
#include <cuda_fp16.h>
#include <cstdint>

namespace {
constexpr int B_  = 4;
constexpr int C_  = 64;
constexpr int IC_ = 16;
constexpr int D_  = 8;
constexpr int H_  = 128;
constexpr int W_  = 128;
constexpr int MID_ = 4;
constexpr int HP_ = 64;
constexpr int L_  = 4096;
constexpr int F_  = 144;    // IC*3*3 = 9 * 16
constexpr float SCALE_ = 10.0f;
constexpr float LOG2E_ = 1.4426950408889634f;

// flash smem layout (bytes), k16-tiled swizzled operands
constexpr int TILE_B  = 4096;                 // 128 rows x 32B (Q/K/P)
constexpr int VTILE_B = 4608;                 // 144 rows x 32B (V)
constexpr int Q_OFF = 0;                      // 9*4096 = 36864
constexpr int K_OFF = 36864;                  // 2 bufs x 36864
constexpr int V_OFF = K_OFF + 2 * 36864;      // 110592; 2 bufs x 8*4608
constexpr int P_OFF = V_OFF + 2 * 36864;      // 184320; 8*4096 = 32768
constexpr int ST_OFF = P_OFF + 32768;         // 217088; alphas/lrun 2*512
constexpr int FLASH_SMEM = ST_OFF + 1024;     // 218112
}

// ============================================================
// helpers
// ============================================================
__device__ __forceinline__ void mma16816(float* c, const uint32_t* a,
                                         uint32_t b0, uint32_t b1) {
    asm volatile(
        "mma.sync.aligned.m16n8k16.row.col.f32.f16.f16.f32 "
        "{%0,%1,%2,%3}, {%4,%5,%6,%7}, {%8,%9}, {%0,%1,%2,%3};"
        : "+f"(c[0]), "+f"(c[1]), "+f"(c[2]), "+f"(c[3])
        : "r"(a[0]), "r"(a[1]), "r"(a[2]), "r"(a[3]), "r"(b0), "r"(b1));
}

__device__ __forceinline__ void ldsm_x4(uint32_t* r, uint32_t smaddr) {
    asm volatile("ldmatrix.sync.aligned.m8n8.x4.shared.b16 {%0,%1,%2,%3}, [%4];"
                 : "=r"(r[0]), "=r"(r[1]), "=r"(r[2]), "=r"(r[3]) : "r"(smaddr));
}
__device__ __forceinline__ void ldsm_x2(uint32_t* r, uint32_t smaddr) {
    asm volatile("ldmatrix.sync.aligned.m8n8.x2.shared.b16 {%0,%1}, [%2];"
                 : "=r"(r[0]), "=r"(r[1]) : "r"(smaddr));
}

__device__ __forceinline__ void cp_async16(uint32_t smaddr, const void* gptr) {
    asm volatile("cp.async.cg.shared.global [%0], [%1], 16;"
                 :: "r"(smaddr), "l"(gptr) : "memory");
}
#define CP_COMMIT() asm volatile("cp.async.commit_group;" ::: "memory")
#define CP_WAIT(n)  asm volatile("cp.async.wait_group %0;" :: "n"(n) : "memory")

__device__ __forceinline__ uint32_t smem_u32(const void* p) {
    uint32_t a;
    asm("{ .reg .u64 t; cvta.to.shared.u64 t, %1; cvt.u32.u64 %0, t; }" : "=r"(a) : "l"(p));
    return a;
}

// XOR swizzle within a k16 tile: bit7 -> bit4
__device__ __forceinline__ uint32_t swz(uint32_t o) { return o ^ ((o & 0x80u) >> 3); }

// ============================================================
// scratch (device globals)
// ============================================================
__device__ float d_conv[3][B_][IC_][H_][W_];
__device__ __align__(16) __half d_qh[B_][L_][F_];   // 10*log2e*q, fp16
__device__ __align__(16) __half d_kh[B_][L_][F_];
__device__ __align__(16) __half d_vth[B_][F_][L_];  // V transposed
__device__ float d_zi[B_][L_][F_];
__device__ __align__(16) float d_yvec[B_][C_][H_][W_];

// ============================================================
// Kernel 1: 1x1 convs at the mid depth slice only.
// ============================================================
__global__ void k_conv(const float* __restrict__ s, const float* __restrict__ g,
                       const float* __restrict__ gw, const float* __restrict__ gb,
                       const float* __restrict__ tw, const float* __restrict__ tb,
                       const float* __restrict__ pw, const float* __restrict__ pb) {
    __shared__ float wq[IC_ * C_], wv[IC_ * C_], wk[IC_ * C_];
    __shared__ float bq[IC_], bv[IC_], bk[IC_];
    const int tid = threadIdx.x;
    for (int i = tid; i < IC_ * C_; i += 128) { wq[i] = gw[i]; wv[i] = tw[i]; wk[i] = pw[i]; }
    if (tid < IC_) { bq[tid] = gb[tid]; bv[tid] = tb[tid]; bk[tid] = pb[tid]; }
    __syncthreads();

    const int y = blockIdx.x, b = blockIdx.y, x = tid;
    float aq[IC_], av[IC_], ak[IC_];
#pragma unroll
    for (int ic = 0; ic < IC_; ic++) { aq[ic] = bq[ic]; av[ic] = bv[ic]; ak[ic] = bk[ic]; }

    const size_t base = ((size_t)b * C_ * D_ + MID_) * (H_ * W_) + (size_t)y * W_ + x;
    const size_t cstride = (size_t)D_ * H_ * W_;
#pragma unroll 4
    for (int c = 0; c < C_; c++) {
        const float sv = s[base + c * cstride];
        const float gv = g[base + c * cstride];
#pragma unroll
        for (int ic = 0; ic < IC_; ic++) {
            aq[ic] += wq[ic * C_ + c] * sv;
            av[ic] += wv[ic * C_ + c] * gv;
            ak[ic] += wk[ic * C_ + c] * gv;
        }
    }
#pragma unroll
    for (int ic = 0; ic < IC_; ic++) {
        const int o = ((b * IC_ + ic) * H_ + y) * W_ + x;
        (&d_conv[0][0][0][0][0])[o] = aq[ic];
        (&d_conv[1][0][0][0][0])[o] = av[ic];
        (&d_conv[2][0][0][0][0])[o] = ak[ic];
    }
}

// ============================================================
// Kernel 2: patch extraction, locality-tiled.
// grid (HP_, B_), 128 threads.
// ============================================================
__global__ void k_patch() {
    __shared__ __half q_s[64][F_];   // 18432 B
    __shared__ __half k_s[64][F_];   // 18432 B
    const int hp = blockIdx.x, b = blockIdx.y;
    const int tid = threadIdx.x;

    // phase 1: compute q,k patches (8 f per item, one wp)
    for (int e = tid; e < 64 * 18; e += 128) {
        const int wp = e / 18, u = e - (e / 18) * 18;
        __half qv[8], kv[8];
#pragma unroll
        for (int j = 0; j < 8; j++) {
            const int f = u * 8 + j;
            const int c = f / 9, r = f - (f / 9) * 9;
            const int ki = r / 3, kj = r - (r / 3) * 3;
            const int y = hp * 2 - 1 + ki;
            const int x = wp * 2 - 1 + kj;
            const bool in = ((unsigned)y < (unsigned)H_) && ((unsigned)x < (unsigned)W_);
            const float q = in ? d_conv[0][b][c][y][x] : 0.0f;
            const float k = in ? d_conv[2][b][c][y][x] : 0.0f;
            qv[j] = __float2half_rn(q * (SCALE_ * LOG2E_));
            kv[j] = __float2half_rn(k);
        }
        *(uint4*)&q_s[wp][u * 8] = *(uint4*)qv;
        *(uint4*)&k_s[wp][u * 8] = *(uint4*)kv;
    }
    __syncthreads();

    // phase 2: coalesced writeout of q,k
    for (int e = tid; e < 64 * 18; e += 128) {
        const int wp = e / 18, u = e - (e / 18) * 18;
        const int l = hp * 64 + wp;
        *(uint4*)&d_qh[b][l][u * 8] = *(const uint4*)&q_s[wp][u * 8];
        *(uint4*)&d_kh[b][l][u * 8] = *(const uint4*)&k_s[wp][u * 8];
    }
    __syncthreads();

    // phase 3: v patches, f-major staging (reuse q_s as [144][64])
    __half* v_s = &q_s[0][0];
    for (int e = tid; e < F_ * 8; e += 128) {
        const int f = e >> 3, u = e & 7;
        const int c = f / 9, r = f - (f / 9) * 9;
        const int ki = r / 3, kj = r - (r / 3) * 3;
        const int y = hp * 2 - 1 + ki;
        __half vv[8];
#pragma unroll
        for (int j = 0; j < 8; j++) {
            const int wp = u * 8 + j;
            const int x = wp * 2 - 1 + kj;
            const bool in = ((unsigned)y < (unsigned)H_) && ((unsigned)x < (unsigned)W_);
            vv[j] = __float2half_rn(in ? d_conv[1][b][c][y][x] : 0.0f);
        }
        *(uint4*)&v_s[f * 64 + u * 8] = *(uint4*)vv;
    }
    __syncthreads();
    for (int e = tid; e < F_ * 8; e += 128) {
        const int f = e >> 3, u = e & 7;
        *(uint4*)&d_vth[b][f][hp * 64 + u * 8] = *(const uint4*)&v_s[f * 64 + u * 8];
    }
}

// ============================================================
// Kernel 3: FUSED online-flash attention.
// grid (32 row-tiles, B) = 128 CTAs, 512 threads = 16 warps.
// ============================================================
__global__ __launch_bounds__(512, 1) void k_flash() {
    extern __shared__ char smc[];
    __shared__ float redmax[4][128];
    __shared__ float redsum[4][128];
    const uint32_t sbase = smem_u32(smc);
    float* alphas = (float*)(smc + ST_OFF);
    float* lrun   = alphas + 128;

    const int tid = threadIdx.x;
    const int lane = tid & 31;
    const int warp = tid >> 5;
    const int swr = warp >> 2, swc = warp & 3;   // S layout
    const int pwr = warp >> 1, pwc = warp & 1;   // PV layout
    const int g = lane >> 2;
    const int t = lane & 3;
    const int b = blockIdx.y;
    const int row0 = blockIdx.x * 128;

    if (tid < 128) lrun[tid] = 0.f;

    float O[9][4];
#pragma unroll
    for (int n = 0; n < 9; n++)
#pragma unroll
        for (int j = 0; j < 4; j++) O[n][j] = 0.f;

    float mrow[4];
#pragma unroll
    for (int ri = 0; ri < 4; ri++) mrow[ri] = -1e30f;

    int rowIdx[4];
#pragma unroll
    for (int ri = 0; ri < 4; ri++)
        rowIdx[ri] = swr * 32 + (ri >> 1) * 16 + (ri & 1) * 8 + g;

    // prologue: Q (resident) + K chunk 0 + V chunk 0
    for (int e = tid; e < 128 * 18; e += 512) {
        const int r = e / 18, u = e - (e / 18) * 18;
        const int k16 = u >> 1, h = u & 1;
        const uint32_t o = (uint32_t)k16 * TILE_B + swz((uint32_t)(r * 32 + h * 16));
        const int fc = k16 * 16 + h * 8;
        cp_async16(sbase + Q_OFF + o, &d_qh[b][row0 + r][fc]);
        cp_async16(sbase + K_OFF + o, &d_kh[b][r][fc]);
    }
    for (int e = tid; e < 144 * 16; e += 512) {
        const int f = e >> 4, u = e & 15;
        const int k16 = u >> 1, h = u & 1;
        const uint32_t o = (uint32_t)k16 * VTILE_B + swz((uint32_t)(f * 32 + h * 16));
        cp_async16(sbase + V_OFF + o, &d_vth[b][f][k16 * 16 + h * 8]);
    }
    CP_COMMIT();

    // LDSM lane offsets
    uint32_t aoffS[2], boffS[2];
#pragma unroll
    for (int m = 0; m < 2; m++)
        aoffS[m] = swz((uint32_t)((swr * 32 + m * 16 + (lane & 15)) * 32 + ((lane >> 4) & 1) * 16));
#pragma unroll
    for (int n16 = 0; n16 < 2; n16++)
        boffS[n16] = swz((uint32_t)((swc * 32 + n16 * 16 + (lane & 7) + ((lane >> 4) << 3)) * 32 +
                                    (((lane >> 3) & 1) << 4)));
    const uint32_t aoffP = swz((uint32_t)((pwr * 16 + (lane & 15)) * 32 + ((lane >> 4) & 1) * 16));
    uint32_t boffV[4];
#pragma unroll
    for (int p = 0; p < 4; p++)
        boffV[p] = swz((uint32_t)((pwc * 72 + p * 16 + (lane & 7) + ((lane >> 4) << 3)) * 32 +
                                  (((lane >> 3) & 1) << 4)));
    const uint32_t boffV2 = swz((uint32_t)((pwc * 72 + 64 + (lane & 7)) * 32 +
                                           (((lane >> 3) & 1) << 4)));

    const uint32_t Qb = sbase + Q_OFF;
    const uint32_t Pb = sbase + P_OFF;

    for (int ct = 0; ct < 32; ct++) {
        const int buf = ct & 1;
        CP_WAIT(0);
        __syncthreads();   // (C) K/V[buf] ready; prior P/red/lrun consumers done

        // issue next K/V chunk into other buffer
        if (ct < 31) {
            const int c1 = (ct + 1) * 128;
            const uint32_t kb1 = sbase + K_OFF + (uint32_t)(buf ^ 1) * 36864;
            const uint32_t vb1 = sbase + V_OFF + (uint32_t)(buf ^ 1) * 36864;
            for (int e = tid; e < 128 * 18; e += 512) {
                const int r = e / 18, u = e - (e / 18) * 18;
                const int k16 = u >> 1, h = u & 1;
                const uint32_t o = (uint32_t)k16 * TILE_B + swz((uint32_t)(r * 32 + h * 16));
                cp_async16(kb1 + o, &d_kh[b][c1 + r][k16 * 16 + h * 8]);
            }
            for (int e = tid; e < 144 * 16; e += 512) {
                const int f = e >> 4, u = e & 15;
                const int k16 = u >> 1, h = u & 1;
                const uint32_t o = (uint32_t)k16 * VTILE_B + swz((uint32_t)(f * 32 + h * 16));
                cp_async16(vb1 + o, &d_vth[b][f][c1 + k16 * 16 + h * 8]);
            }
            CP_COMMIT();
        }

        const uint32_t Kb = sbase + K_OFF + (uint32_t)buf * 36864;
        const uint32_t Vb = sbase + V_OFF + (uint32_t)buf * 36864;

        // ---- S = Q' K^T (base-2 logits) ----
        float acc[2][4][4];
#pragma unroll
        for (int m = 0; m < 2; m++)
#pragma unroll
            for (int n = 0; n < 4; n++)
#pragma unroll
                for (int j = 0; j < 4; j++) acc[m][n][j] = 0.f;

#pragma unroll
        for (int k16 = 0; k16 < 9; k16++) {
            const uint32_t tb = (uint32_t)k16 * TILE_B;
            uint32_t a[2][4], bb[2][4];
            ldsm_x4(a[0], Qb + tb + aoffS[0]);
            ldsm_x4(a[1], Qb + tb + aoffS[1]);
            ldsm_x4(bb[0], Kb + tb + boffS[0]);
            ldsm_x4(bb[1], Kb + tb + boffS[1]);
#pragma unroll
            for (int m = 0; m < 2; m++) {
                mma16816(acc[m][0], a[m], bb[0][0], bb[0][1]);
                mma16816(acc[m][1], a[m], bb[0][2], bb[0][3]);
                mma16816(acc[m][2], a[m], bb[1][0], bb[1][1]);
                mma16816(acc[m][3], a[m], bb[1][2], bb[1][3]);
            }
        }

        // ---- warp-local row max into redmax ----
#pragma unroll
        for (int ri = 0; ri < 4; ri++) {
            const int m = ri >> 1, jb = (ri & 1) * 2;
            float mx = acc[m][0][jb];
#pragma unroll
            for (int n = 0; n < 4; n++)
                mx = fmaxf(mx, fmaxf(acc[m][n][jb], acc[m][n][jb + 1]));
            mx = fmaxf(mx, __shfl_xor_sync(0xffffffffu, mx, 1));
            mx = fmaxf(mx, __shfl_xor_sync(0xffffffffu, mx, 2));
            if (t == 0) redmax[swc][rowIdx[ri]] = mx;
        }
        __syncthreads();   // (A)

        // ---- P = exp2(S - m) into smem; alphas; partial sums ----
#pragma unroll
        for (int ri = 0; ri < 4; ri++) {
            const int m = ri >> 1, jb = (ri & 1) * 2;
            const int row = rowIdx[ri];
            const float mnew = fmaxf(mrow[ri],
                fmaxf(fmaxf(redmax[0][row], redmax[1][row]),
                      fmaxf(redmax[2][row], redmax[3][row])));
            const float alpha = exp2f(mrow[ri] - mnew);
            mrow[ri] = mnew;
            float sum = 0.f;
#pragma unroll
            for (int n = 0; n < 4; n++) {
                const float e0 = exp2f(acc[m][n][jb] - mnew);
                const float e1 = exp2f(acc[m][n][jb + 1] - mnew);
                sum += e0 + e1;
                const int col = swc * 32 + n * 8 + t * 2;
                const uint32_t off = (uint32_t)(col >> 4) * TILE_B +
                                     swz((uint32_t)(row * 32 + (col & 15) * 2));
                *(__half2*)(smc + P_OFF + off) = __floats2half2_rn(e0, e1);
            }
            sum += __shfl_xor_sync(0xffffffffu, sum, 1);
            sum += __shfl_xor_sync(0xffffffffu, sum, 2);
            if (t == 0) {
                redsum[swc][row] = sum;
                if (swc == 0) alphas[row] = alpha;
            }
        }
        __syncthreads();   // (B)

        if (tid < 128)
            lrun[tid] = lrun[tid] * alphas[tid] +
                        (redsum[0][tid] + redsum[1][tid]) +
                        (redsum[2][tid] + redsum[3][tid]);

        // ---- O rescale + O += P V (8 k16) ----
        {
            const float alA = alphas[pwr * 16 + g];
            const float alB = alphas[pwr * 16 + g + 8];
#pragma unroll
            for (int n = 0; n < 9; n++) {
                O[n][0] *= alA; O[n][1] *= alA;
                O[n][2] *= alB; O[n][3] *= alB;
            }
        }
#pragma unroll
        for (int k16 = 0; k16 < 8; k16++) {
            const uint32_t ptb = Pb + (uint32_t)k16 * TILE_B;
            const uint32_t vtb = Vb + (uint32_t)k16 * VTILE_B;
            uint32_t a[4];
            ldsm_x4(a, ptb + aoffP);
#pragma unroll
            for (int p = 0; p < 4; p++) {
                uint32_t bb[4];
                ldsm_x4(bb, vtb + boffV[p]);
                mma16816(O[2 * p],     a, bb[0], bb[1]);
                mma16816(O[2 * p + 1], a, bb[2], bb[3]);
            }
            {
                uint32_t bs[2];
                ldsm_x2(bs, vtb + boffV2);
                mma16816(O[8], a, bs[0], bs[1]);
            }
        }
    }

    __syncthreads();   // lrun final values visible to all
    {
        const int rA = pwr * 16 + g;
        const int rB = rA + 8;
        const float liA = 1.0f / lrun[rA];
        const float liB = 1.0f / lrun[rB];
#pragma unroll
        for (int n = 0; n < 9; n++) {
            const int col = pwc * 72 + n * 8 + t * 2;
            *(float2*)&d_zi[b][row0 + rA][col] = make_float2(O[n][0] * liA, O[n][1] * liA);
            *(float2*)&d_zi[b][row0 + rB][col] = make_float2(O[n][2] * liB, O[n][3] * liB);
        }
    }
}

// ============================================================
// Kernel 4: fold (overlap-add + count normalize) + W_w conv -> yvec
// grid (H, B), 128 threads.
// ============================================================
__global__ void k_fold(const float* __restrict__ Wmat, const float* __restrict__ Wb) {
    __shared__ float zs[IC_][W_];
    __shared__ float wsm[C_ * IC_];
    __shared__ float bsm[C_];
    const int x = threadIdx.x;
    const int y = blockIdx.x, b = blockIdx.y;
    for (int i = x; i < C_ * IC_; i += 128) wsm[i] = Wmat[i];
    if (x < C_) bsm[x] = Wb[x];

    float v[IC_];
#pragma unroll
    for (int ic = 0; ic < IC_; ic++) v[ic] = 0.f;
    int cnt = 0;
#pragma unroll
    for (int i = 0; i < 3; i++) {
        const int tY = y + 1 - i;
        if (tY < 0 || (tY & 1) || (tY >> 1) >= HP_) continue;
        const int hp = tY >> 1;
#pragma unroll
        for (int j = 0; j < 3; j++) {
            const int tX = x + 1 - j;
            if (tX < 0 || (tX & 1) || (tX >> 1) >= HP_) continue;
            const int wp = tX >> 1;
            const float* zrow = &d_zi[b][hp * 64 + wp][0];
            cnt++;
#pragma unroll
            for (int ic = 0; ic < IC_; ic++) v[ic] += zrow[ic * 9 + i * 3 + j];
        }
    }
    const float invc = 1.0f / (float)cnt;
#pragma unroll
    for (int ic = 0; ic < IC_; ic++) zs[ic][x] = v[ic] * invc;
    __syncthreads();

    for (int o = 0; o < C_; o++) {
        float a = bsm[o];
#pragma unroll
        for (int ic = 0; ic < IC_; ic++) a += wsm[o * IC_ + ic] * zs[ic][x];
        d_yvec[b][o][y][x] = a;
    }
}

// ============================================================
// Kernel 5: out = s + yvec (broadcast over D), float4 streaming.
// 8.4M float4 over 32768 blocks x 256 threads.
// ============================================================
__global__ void k_out(const float4* __restrict__ s4, float4* __restrict__ out4) {
    const int idx = blockIdx.x * 256 + threadIdx.x;      // 0 .. 8388607
    const int pix4 = idx & 4095;                         // HW/4 = 4096
    const int bo = (idx >> 12) >> 3;                     // b*64 + o
    const float4 sv = s4[idx];
    const float4 yv = ((const float4*)&d_yvec[0][0][0][0])[bo * 4096 + pix4];
    out4[idx] = make_float4(sv.x + yv.x, sv.y + yv.y, sv.z + yv.z, sv.w + yv.w);
}

// ============================================================
extern "C" void kernel_launch(void* const* d_in, const int* /*in_sizes*/, int /*n_in*/,
                              void* d_out, int /*out_size*/) {
    const float* s   = (const float*)d_in[0];
    const float* g   = (const float*)d_in[1];
    const float* g_w = (const float*)d_in[2];
    const float* g_b = (const float*)d_in[3];
    const float* t_w = (const float*)d_in[4];
    const float* t_b = (const float*)d_in[5];
    const float* p_w = (const float*)d_in[6];
    const float* p_b = (const float*)d_in[7];
    const float* W_w = (const float*)d_in[8];
    const float* W_b = (const float*)d_in[9];
    float* out = (float*)d_out;

    cudaFuncSetAttribute(k_flash, cudaFuncAttributeMaxDynamicSharedMemorySize, FLASH_SMEM);

    k_conv<<<dim3(H_, B_), 128>>>(s, g, g_w, g_b, t_w, t_b, p_w, p_b);
    k_patch<<<dim3(HP_, B_), 128>>>();

    k_flash<<<dim3(32, B_), 512, FLASH_SMEM>>>();

    k_fold<<<dim3(H_, B_), 128>>>(W_w, W_b);

    const int total4 = (B_ * C_ * D_ * H_ * W_) / 4;     // 8388608
    k_out<<<total4 / 256, 256>>>((const float4*)s, (float4*)out);
}